// round 8
// baseline (speedup 1.0000x reference)
#include <cuda_runtime.h>
#include <cuda_fp16.h>
#include <mma.h>
#include <math.h>
#include <stdint.h>

using namespace nvcuda;

// ---------------- problem dims ----------------
#define Bb 8
#define Tt 64
#define Nn 16
#define DSs 128
#define Aa 32
#define Cc 1024
#define Hh 16
#define Ll 8
#define Ss 128            // 2*T
#define BNn 128           // B*N
#define Rr 16384          // BN*S
#define Dd 64             // head dim
#define QKVW (3 * Cc)     // fused qkv row width

// ---------------- scratch (device globals; no allocation allowed) ----------------
__device__ float   g_x[Rr * Cc];            // residual stream (fp32)
__device__ __half  g_h[Rr * Cc];            // LN output (fp16)
__device__ __half  g_qkv[Rr * 3 * Cc];      // fused q|k|v (fp16)
__device__ __half  g_y[Rr * Cc];
__device__ __half  g_mid[Rr * 4 * Cc];
__device__ __half  g_st[BNn * Tt * DSs];
__device__ __half  g_ac[BNn * Tt * Aa];
__device__ __half  g_wqkv[Ll * 3 * Cc * Cc];   // transposed [3C, C] per layer
__device__ float   g_bqkv[Ll * 3 * Cc];
__device__ __half  g_wp[Ll * Cc * Cc];         // transposed [N,K]
__device__ __half  g_w1[Ll * Cc * 4 * Cc];     // transposed [4C, C]
__device__ __half  g_w2[Ll * 4 * Cc * Cc];     // transposed [C, 4C]
__device__ __half  g_sew[DSs * Cc];            // K-major
__device__ __half  g_aew[Aa * Cc];

// ---------------- small helpers ----------------
__device__ __forceinline__ uint32_t smem_to_u32(const void* smem_ptr) {
    uint32_t addr;
    asm("{ .reg .u64 tmp; cvta.to.shared.u64 tmp, %1; cvt.u32.u64 %0, tmp; }"
        : "=r"(addr) : "l"(smem_ptr));
    return addr;
}
__device__ __forceinline__ void cp_async16(uint32_t saddr, const void* gptr) {
    asm volatile("cp.async.cg.shared.global [%0], [%1], 16;" :: "r"(saddr), "l"(gptr));
}
__device__ __forceinline__ void cp_commit() { asm volatile("cp.async.commit_group;" ::: "memory"); }
#define CP_WAIT_GROUP(n) asm volatile("cp.async.wait_group %0;" :: "n"(n) : "memory")

__device__ __forceinline__ uint32_t sw_off(uint32_t off) { return off ^ ((off >> 3) & 0x70u); }

__device__ __forceinline__ void ldmatrix_x4(uint32_t* d, uint32_t addr) {
    asm volatile("ldmatrix.sync.aligned.m8n8.x4.shared.b16 {%0,%1,%2,%3}, [%4];"
                 : "=r"(d[0]), "=r"(d[1]), "=r"(d[2]), "=r"(d[3]) : "r"(addr));
}
__device__ __forceinline__ void mma_16816(float* c, const uint32_t* a, const uint32_t* b) {
    asm volatile("mma.sync.aligned.m16n8k16.row.col.f32.f16.f16.f32 "
                 "{%0,%1,%2,%3}, {%4,%5,%6,%7}, {%8,%9}, {%0,%1,%2,%3};"
                 : "+f"(c[0]), "+f"(c[1]), "+f"(c[2]), "+f"(c[3])
                 : "r"(a[0]), "r"(a[1]), "r"(a[2]), "r"(a[3]), "r"(b[0]), "r"(b[1]));
}

__device__ __forceinline__ float gelu_f(float x) {
    float x3 = x * x * x;
    return 0.5f * x * (1.0f + tanhf(0.7978845608028654f * (x + 0.044715f * x3)));
}

// ---------------- prep + all weight transposes (ONE kernel) ----------------
// blocks 0..98303: transposes (qkv 24576 | wp 8192 | w1 32768 | w2 32768)
// blocks 98304..104159: elementwise prep (st | ac | sew | aew | bqkv), 256 elems/block
#define WCONV_BLOCKS 104160
__global__ void __launch_bounds__(256) wconv_all(const float* __restrict__ Wq,
                                                 const float* __restrict__ Wk,
                                                 const float* __restrict__ Wv,
                                                 const float* __restrict__ Wp,
                                                 const float* __restrict__ W1,
                                                 const float* __restrict__ W2,
                                                 const float* __restrict__ states,
                                                 const float* __restrict__ actions,
                                                 const float* __restrict__ seW,
                                                 const float* __restrict__ aeW,
                                                 const float* __restrict__ bq,
                                                 const float* __restrict__ bk,
                                                 const float* __restrict__ bv) {
    __shared__ float tile[32][33];
    int bid = blockIdx.x;
    if (bid >= 98304) {
        int i = (bid - 98304) * 256 + threadIdx.x;
        if (i < 1048576) {
            int ds = i % DSs;
            int row = i / DSs;
            int t = row % Tt;
            int bn = row / Tt;
            int b = bn / Nn, n = bn % Nn;
            g_st[i] = __float2half(states[(((size_t)b * Tt + t) * Nn + n) * DSs + ds]);
        } else if (i < 1310720) {
            int j = i - 1048576;
            int a = j % Aa;
            int row = j / Aa;
            int t = row % Tt;
            int bn = row / Tt;
            int b = bn / Nn, n = bn % Nn;
            g_ac[j] = __float2half(actions[(((size_t)b * Tt + t) * Nn + n) * Aa + a]);
        } else if (i < 1441792) {
            int j = i - 1310720;
            g_sew[j] = __float2half(seW[j]);
        } else if (i < 1474560) {
            int j = i - 1441792;
            g_aew[j] = __float2half(aeW[j]);
        } else {
            int j = i - 1474560;            // < Ll*3*Cc
            int l = j / (3 * Cc);
            int k = j - l * 3 * Cc;
            float v = (k < Cc) ? bq[l * Cc + k]
                    : (k < 2 * Cc) ? bk[l * Cc + k - Cc]
                                   : bv[l * Cc + k - 2 * Cc];
            g_bqkv[j] = v;
        }
        return;
    }
    const float* src;
    __half* dst;
    int K, N, bx, by;
    if (bid < 24576) {
        int which = bid >> 13;
        int r = bid & 8191;
        int layer = r >> 10;
        int rt = r & 1023;
        bx = rt & 31; by = rt >> 5; K = Cc; N = Cc;
        src = (which == 0 ? Wq : which == 1 ? Wk : Wv) + (size_t)layer * Cc * Cc;
        dst = g_wqkv + (size_t)layer * 3 * Cc * Cc + (size_t)which * Cc * Cc;
    } else if (bid < 32768) {
        int r = bid - 24576;
        int layer = r >> 10;
        int rt = r & 1023;
        bx = rt & 31; by = rt >> 5; K = Cc; N = Cc;
        src = Wp + (size_t)layer * Cc * Cc;
        dst = g_wp + (size_t)layer * Cc * Cc;
    } else if (bid < 65536) {
        int r = bid - 32768;
        int layer = r >> 12;
        int rt = r & 4095;
        bx = rt & 127; by = rt >> 7; K = Cc; N = 4 * Cc;
        src = W1 + (size_t)layer * Cc * 4 * Cc;
        dst = g_w1 + (size_t)layer * Cc * 4 * Cc;
    } else {
        int r = bid - 65536;
        int layer = r >> 12;
        int rt = r & 4095;
        bx = rt & 31; by = rt >> 5; K = 4 * Cc; N = Cc;
        src = W2 + (size_t)layer * 4 * Cc * Cc;
        dst = g_w2 + (size_t)layer * 4 * Cc * Cc;
    }
    int nb = bx * 32, kb = by * 32;
    int tx = threadIdx.x & 31, ty = threadIdx.x >> 5;  // 32 x 8
#pragma unroll
    for (int r = 0; r < 32; r += 8)
        tile[ty + r][tx] = src[(size_t)(kb + ty + r) * N + nb + tx];
    __syncthreads();
#pragma unroll
    for (int r = 0; r < 32; r += 8)
        dst[(size_t)(nb + ty + r) * K + kb + tx] = __float2half(tile[tx][ty + r]);
}

// ---------------- embed GEMM (wmma) with fused assemble epilogue; z=0 state, z=1 action ----------------
#define BM 128
#define BNt 128
#define BKt 32
#define APAD 8
#define BPAD 8
#define AS_BYTES (2 * BM * (BKt + APAD) * 2)
#define BS_BYTES (2 * BKt * (BNt + BPAD) * 2)

__global__ void __launch_bounds__(256) gemm_embed(const float* __restrict__ bias_s,
                                                  const float* __restrict__ bias_a,
                                                  const float* __restrict__ pe,
                                                  const float* __restrict__ gpe,
                                                  const int* __restrict__ ts,
                                                  float* __restrict__ xout) {
    __shared__ __align__(16) unsigned char sraw[AS_BYTES + BS_BYTES];
    typedef __half (*AsT)[BM][BKt + APAD];
    typedef __half (*BsT)[BKt][BNt + BPAD];
    AsT As = reinterpret_cast<AsT>(sraw);
    BsT Bs = reinterpret_cast<BsT>(sraw + AS_BYTES);

    int parity = blockIdx.z;
    const __half* A  = parity ? g_ac : g_st;
    const __half* Bm = parity ? g_aew : g_sew;
    const float* bias = parity ? bias_a : bias_s;
    int K = parity ? Aa : DSs;
    int N = Cc;

    int tid = threadIdx.x;
    int wid = tid >> 5;
    int wm = wid >> 2;
    int wn = wid & 3;
    int mBase = blockIdx.y * BM;
    int nBase = blockIdx.x * BNt;

    wmma::fragment<wmma::accumulator, 16, 16, 16, float> cf[4][2];
#pragma unroll
    for (int i = 0; i < 4; i++)
#pragma unroll
        for (int j = 0; j < 2; j++) wmma::fill_fragment(cf[i][j], 0.0f);

    int a_row[2], a_col[2], b_row[2], b_col[2];
#pragma unroll
    for (int u = 0; u < 2; u++) {
        int idx = tid + u * 256;
        a_row[u] = idx >> 2;
        a_col[u] = (idx & 3) * 8;
        b_row[u] = idx >> 4;
        b_col[u] = (idx & 15) * 8;
    }

    int ktiles = K / BKt;
    uint4 ra[2], rb[2];
#pragma unroll
    for (int u = 0; u < 2; u++) {
        ra[u] = (a_col[u] < K) ? *(const uint4*)(A + (size_t)(mBase + a_row[u]) * K + a_col[u])
                               : make_uint4(0, 0, 0, 0);
        rb[u] = *(const uint4*)(Bm + (size_t)b_row[u] * N + nBase + b_col[u]);
    }
#pragma unroll
    for (int u = 0; u < 2; u++) {
        if (a_col[u] < BKt) *(uint4*)&As[0][a_row[u]][a_col[u]] = ra[u];
        *(uint4*)&Bs[0][b_row[u]][b_col[u]] = rb[u];
    }
    __syncthreads();

    for (int kt = 0; kt < ktiles; kt++) {
        int cur = kt & 1, nxt = cur ^ 1;
        if (kt + 1 < ktiles) {
            int k0 = (kt + 1) * BKt;
#pragma unroll
            for (int u = 0; u < 2; u++) {
                ra[u] = *(const uint4*)(A + (size_t)(mBase + a_row[u]) * K + k0 + a_col[u]);
                rb[u] = *(const uint4*)(Bm + (size_t)(k0 + b_row[u]) * N + nBase + b_col[u]);
            }
        }
#pragma unroll
        for (int kk = 0; kk < BKt; kk += 16) {
            wmma::fragment<wmma::matrix_a, 16, 16, 16, __half, wmma::row_major> af[4];
            wmma::fragment<wmma::matrix_b, 16, 16, 16, __half, wmma::row_major> bf[2];
#pragma unroll
            for (int i = 0; i < 4; i++)
                wmma::load_matrix_sync(af[i], &As[cur][wm * 64 + i * 16][kk], BKt + APAD);
#pragma unroll
            for (int j = 0; j < 2; j++)
                wmma::load_matrix_sync(bf[j], &Bs[cur][kk][wn * 32 + j * 16], BNt + BPAD);
#pragma unroll
            for (int i = 0; i < 4; i++)
#pragma unroll
                for (int j = 0; j < 2; j++)
                    wmma::mma_sync(cf[i][j], af[i], bf[j], cf[i][j]);
        }
        if (kt + 1 < ktiles) {
            __syncthreads();
#pragma unroll
            for (int u = 0; u < 2; u++) {
                *(uint4*)&As[nxt][a_row[u]][a_col[u]] = ra[u];
                *(uint4*)&Bs[nxt][b_row[u]][b_col[u]] = rb[u];
            }
            __syncthreads();
        }
    }

    __syncthreads();
    float* Epi = reinterpret_cast<float*>(sraw);
#pragma unroll 1
    for (int p = 0; p < 2; p++) {
        if (wm == p) {
#pragma unroll
            for (int i = 0; i < 4; i++)
#pragma unroll
                for (int j = 0; j < 2; j++)
                    wmma::store_matrix_sync(&Epi[(i * 16) * 132 + wn * 32 + j * 16],
                                            cf[i][j], 132, wmma::mem_row_major);
        }
        __syncthreads();
#pragma unroll
        for (int it = 0; it < 8; it++) {
            int idx = tid + it * 256;
            int r = idx >> 5;
            int c4 = (idx & 31) * 4;
            int grow = mBase + p * 64 + r;
            int gcol = nBase + c4;
            float4 vv = *(float4*)&Epi[r * 132 + c4];
            int bn2 = grow >> 6, t = grow & 63, b = bn2 >> 4;
            int s2 = 2 * t + parity;
            int tsv = ts[b * Tt + t];
            const float4 pef = *(const float4*)(pe + (size_t)s2 * Cc + gcol);
            const float4 gf  = *(const float4*)(gpe + (size_t)tsv * Cc + gcol);
            float* Cp = xout + ((size_t)bn2 * Ss + s2) * Cc + gcol;
            *(float4*)Cp = make_float4(vv.x + bias[gcol + 0] + pef.x + gf.x,
                                       vv.y + bias[gcol + 1] + pef.y + gf.y,
                                       vv.z + bias[gcol + 2] + pef.z + gf.z,
                                       vv.w + bias[gcol + 3] + pef.w + gf.w);
        }
        __syncthreads();
    }
}

// ---------------- LayerNorm fp32 -> fp16 ----------------
__global__ void __launch_bounds__(256) ln_f2h(const float* __restrict__ x,
                                              const float* __restrict__ w,
                                              const float* __restrict__ bb,
                                              __half* __restrict__ out) {
    int row = blockIdx.x;
    const float* xr = x + (size_t)row * Cc;
    int c0 = threadIdx.x * 4;
    float4 f = *(const float4*)(xr + c0);
    float s = f.x + f.y + f.z + f.w;
    float ss = f.x * f.x + f.y * f.y + f.z * f.z + f.w * f.w;
#pragma unroll
    for (int o = 16; o > 0; o >>= 1) {
        s  += __shfl_xor_sync(0xffffffffu, s, o);
        ss += __shfl_xor_sync(0xffffffffu, ss, o);
    }
    __shared__ float rs[8], rss[8];
    int wrp = threadIdx.x >> 5, lane = threadIdx.x & 31;
    if (lane == 0) { rs[wrp] = s; rss[wrp] = ss; }
    __syncthreads();
    s = 0.f; ss = 0.f;
#pragma unroll
    for (int qq = 0; qq < 8; qq++) { s += rs[qq]; ss += rss[qq]; }
    float mean = s * (1.0f / Cc);
    float var = ss * (1.0f / Cc) - mean * mean;
    float rstd = rsqrtf(var + 1e-5f);
    float4 wf = *(const float4*)(w + c0);
    float4 bf = *(const float4*)(bb + c0);
    float o0 = (f.x - mean) * rstd * wf.x + bf.x;
    float o1 = (f.y - mean) * rstd * wf.y + bf.y;
    float o2 = (f.z - mean) * rstd * wf.z + bf.z;
    float o3 = (f.w - mean) * rstd * wf.w + bf.w;
    *(__half2*)(out + (size_t)row * Cc + c0)     = __floats2half2_rn(o0, o1);
    *(__half2*)(out + (size_t)row * Cc + c0 + 2) = __floats2half2_rn(o2, o3);
}

// ---------------- HMMA GEMM: 128x128 CTA, 4 warps 64x64, 3-stage cp.async, frag double-buffer ----------------
#define GBK 64
#define GSTG 3
#define GSTAGE_BYTES 32768          // A 16KB + B 16KB
#define GEMM_SMEM (GSTG * GSTAGE_BYTES)     // 96KB -> 2 CTAs/SM

template <int OUTHALF, int DOGELU, int DORES>
__global__ void __launch_bounds__(128, 2) gemm_mma(const __half* __restrict__ A,
                                                   const __half* __restrict__ Bt,
                                                   const float* __restrict__ bias,
                                                   const float* __restrict__ res,
                                                   void* __restrict__ Cout,
                                                   int M, int N, int K) {
    extern __shared__ unsigned char gsm[];
    uint32_t sbase = smem_to_u32(gsm);
    const int tid = threadIdx.x;
    const int wid = tid >> 5;
    const int lane = tid & 31;
    const int wm = wid & 1;
    const int wn = wid >> 1;
    const int mBase = blockIdx.y * 128;
    const int nBase = blockIdx.x * 128;

    float acc[4][8][4];
#pragma unroll
    for (int i = 0; i < 4; i++)
#pragma unroll
        for (int j = 0; j < 8; j++)
#pragma unroll
            for (int r = 0; r < 4; r++) acc[i][j][r] = 0.f;

    const int KT = K / GBK;

    auto load_stage = [&](int kt) {
        int k0 = kt * GBK;
        uint32_t ab = sbase + (uint32_t)(kt % GSTG) * GSTAGE_BYTES;
        uint32_t bb = ab + 16384;
#pragma unroll
        for (int j = 0; j < 8; j++) {
            int id = tid + j * 128;
            int row = id >> 3;
            int c16 = id & 7;
            uint32_t sw = sw_off((uint32_t)(row * 128 + c16 * 16));
            cp_async16(ab + sw, A + (size_t)(mBase + row) * K + k0 + c16 * 8);
            cp_async16(bb + sw, Bt + (size_t)(nBase + row) * K + k0 + c16 * 8);
        }
    };

    uint32_t aF[2][4][4], bF[2][8][2];
    auto loadfrags = [&](uint32_t ab, uint32_t bb, int ks, int buf) {
#pragma unroll
        for (int mi = 0; mi < 4; mi++) {
            int row = wm * 64 + mi * 16 + (lane & 15);
            int kc = ks * 2 + (lane >> 4);
            ldmatrix_x4(aF[buf][mi], ab + sw_off((uint32_t)(row * 128 + kc * 16)));
        }
#pragma unroll
        for (int bj = 0; bj < 4; bj++) {
            int nrow = wn * 64 + bj * 16 + (lane & 7) + ((lane >> 4) & 1) * 8;
            int kc = ks * 2 + ((lane >> 3) & 1);
            uint32_t r[4];
            ldmatrix_x4(r, bb + sw_off((uint32_t)(nrow * 128 + kc * 16)));
            bF[buf][bj * 2 + 0][0] = r[0]; bF[buf][bj * 2 + 0][1] = r[1];
            bF[buf][bj * 2 + 1][0] = r[2]; bF[buf][bj * 2 + 1][1] = r[3];
        }
    };

    load_stage(0); cp_commit();
    load_stage(1); cp_commit();

    for (int kt = 0; kt < KT; kt++) {
        CP_WAIT_GROUP(1);
        __syncthreads();
        uint32_t ab = sbase + (uint32_t)(kt % GSTG) * GSTAGE_BYTES;
        uint32_t bb = ab + 16384;
        loadfrags(ab, bb, 0, 0);               // ks=0 fragments first
        if (kt + 2 < KT) load_stage(kt + 2);   // then next-stage bulk loads
        cp_commit();

#pragma unroll
        for (int ks = 0; ks < 4; ks++) {
            int cur = ks & 1, nxt = cur ^ 1;
            if (ks < 3) loadfrags(ab, bb, ks + 1, nxt);
#pragma unroll
            for (int mi = 0; mi < 4; mi++)
#pragma unroll
                for (int ni = 0; ni < 8; ni++)
                    mma_16816(acc[mi][ni], aF[cur][mi], bF[cur][ni]);
        }
    }

#pragma unroll
    for (int mi = 0; mi < 4; mi++) {
#pragma unroll
        for (int ni = 0; ni < 8; ni++) {
            int r0 = mBase + wm * 64 + mi * 16 + (lane >> 2);
            int c0 = nBase + wn * 64 + ni * 8 + 2 * (lane & 3);
            float b0 = bias[c0], b1 = bias[c0 + 1];
#pragma unroll
            for (int half_ = 0; half_ < 2; half_++) {
                int row = r0 + half_ * 8;
                float o0 = acc[mi][ni][half_ * 2 + 0] + b0;
                float o1 = acc[mi][ni][half_ * 2 + 1] + b1;
                if (DOGELU) { o0 = gelu_f(o0); o1 = gelu_f(o1); }
                if (DORES) {
                    const float* rp = res + (size_t)row * N + c0;
                    o0 += rp[0]; o1 += rp[1];
                }
                if (OUTHALF) {
                    *(__half2*)((__half*)Cout + (size_t)row * N + c0) = __floats2half2_rn(o0, o1);
                } else {
                    *(float2*)((float*)Cout + (size_t)row * N + c0) = make_float2(o0, o1);
                }
            }
        }
    }
}

// ---------------- tensor-core attention: block per (bn, head), 4 warps ----------------
#define ATT_SMEM 81920

__global__ void __launch_bounds__(128) attn_tc(const __half* __restrict__ qkv,
                                               __half* __restrict__ y) {
    extern __shared__ unsigned char asm_[];
    uint32_t sb = smem_to_u32(asm_);
    uint32_t sK = sb, sQ = sb + 16384, sV0 = sb + 32768, sV1 = sb + 40960;
    int tid = threadIdx.x, wid = tid >> 5, lane = tid & 31;
    uint32_t sP0 = sb + 49152 + wid * 8192;
    uint32_t sP1 = sP0 + 4096;
    char* pch0 = (char*)asm_ + 49152 + wid * 8192;
    char* pch1 = pch0 + 4096;
    int bh = blockIdx.x, bn = bh >> 4, h = bh & 15;
    size_t baseq = (size_t)bn * Ss * QKVW + h * Dd;
    size_t basey = (size_t)bn * Ss * Cc + h * Dd;

    for (int idx = tid; idx < 1024; idx += 128) {
        int row = idx >> 3, c = idx & 7;
        uint32_t sw = sw_off((uint32_t)(row * 128 + c * 16));
        cp_async16(sQ + sw, qkv + baseq + (size_t)row * QKVW + c * 8);
        cp_async16(sK + sw, qkv + baseq + Cc + (size_t)row * QKVW + c * 8);
    }
    cp_commit();
    for (int idx = tid; idx < 4096; idx += 128) {
        int kv = idx >> 5, d2 = idx & 31;
        __half2 v2 = *(const __half2*)(qkv + baseq + 2 * Cc + (size_t)kv * QKVW + d2 * 2);
        char* vbp = (char*)asm_ + ((kv < 64) ? 32768 : 40960);
        int kc = kv & 63;
        *(__half*)(vbp + sw_off((uint32_t)((d2 * 2) * 128 + kc * 2)))     = __low2half(v2);
        *(__half*)(vbp + sw_off((uint32_t)((d2 * 2 + 1) * 128 + kc * 2))) = __high2half(v2);
    }
    CP_WAIT_GROUP(0);
    __syncthreads();

    int qb = wid * 32;
    float accS[2][16][4];
#pragma unroll
    for (int mi = 0; mi < 2; mi++)
#pragma unroll
        for (int ni = 0; ni < 16; ni++)
#pragma unroll
            for (int r = 0; r < 4; r++) accS[mi][ni][r] = 0.f;

#pragma unroll
    for (int ks = 0; ks < 4; ks++) {
        uint32_t a[2][4], b[16][2];
#pragma unroll
        for (int mi = 0; mi < 2; mi++) {
            int row = qb + mi * 16 + (lane & 15);
            int kc = ks * 2 + (lane >> 4);
            ldmatrix_x4(a[mi], sQ + sw_off((uint32_t)(row * 128 + kc * 16)));
        }
#pragma unroll
        for (int bj = 0; bj < 8; bj++) {
            int nrow = bj * 16 + (lane & 7) + ((lane >> 4) & 1) * 8;
            int kc = ks * 2 + ((lane >> 3) & 1);
            uint32_t r[4];
            ldmatrix_x4(r, sK + sw_off((uint32_t)(nrow * 128 + kc * 16)));
            b[bj * 2 + 0][0] = r[0]; b[bj * 2 + 0][1] = r[1];
            b[bj * 2 + 1][0] = r[2]; b[bj * 2 + 1][1] = r[3];
        }
#pragma unroll
        for (int mi = 0; mi < 2; mi++)
#pragma unroll
            for (int ni = 0; ni < 16; ni++)
                mma_16816(accS[mi][ni], a[mi], b[ni]);
    }

    float inv[2][2];
#pragma unroll
    for (int mi = 0; mi < 2; mi++) {
        float s0 = 0.f, s1 = 0.f;
        int rA = qb + mi * 16 + (lane >> 2);
        int rB = rA + 8;
        int rl = mi * 16 + (lane >> 2);
#pragma unroll
        for (int ni = 0; ni < 16; ni++) {
            int c0 = ni * 8 + 2 * (lane & 3);
            float p00 = (c0     <= rA) ? __expf(accS[mi][ni][0] * 0.125f) : 0.f;
            float p01 = (c0 + 1 <= rA) ? __expf(accS[mi][ni][1] * 0.125f) : 0.f;
            float p10 = (c0     <= rB) ? __expf(accS[mi][ni][2] * 0.125f) : 0.f;
            float p11 = (c0 + 1 <= rB) ? __expf(accS[mi][ni][3] * 0.125f) : 0.f;
            s0 += p00 + p01; s1 += p10 + p11;
            char* pp = (c0 < 64) ? pch0 : pch1;
            int cl = c0 & 63;
            *(__half2*)(pp + sw_off((uint32_t)(rl * 128 + cl * 2)))       = __floats2half2_rn(p00, p01);
            *(__half2*)(pp + sw_off((uint32_t)((rl + 8) * 128 + cl * 2))) = __floats2half2_rn(p10, p11);
        }
        s0 += __shfl_xor_sync(0xffffffffu, s0, 1);
        s0 += __shfl_xor_sync(0xffffffffu, s0, 2);
        s1 += __shfl_xor_sync(0xffffffffu, s1, 1);
        s1 += __shfl_xor_sync(0xffffffffu, s1, 2);
        inv[mi][0] = 1.0f / s0;
        inv[mi][1] = 1.0f / s1;
    }
    __syncwarp();

    float accO[2][8][4];
#pragma unroll
    for (int mi = 0; mi < 2; mi++)
#pragma unroll
        for (int ni = 0; ni < 8; ni++)
#pragma unroll
            for (int r = 0; r < 4; r++) accO[mi][ni][r] = 0.f;

#pragma unroll
    for (int ks = 0; ks < 8; ks++) {
        uint32_t pbase = (ks < 4) ? sP0 : sP1;
        uint32_t vbase = (ks < 4) ? sV0 : sV1;
        int kss = ks & 3;
        uint32_t a[2][4], b[8][2];
#pragma unroll
        for (int mi = 0; mi < 2; mi++) {
            int row = mi * 16 + (lane & 15);
            int kc = kss * 2 + (lane >> 4);
            ldmatrix_x4(a[mi], pbase + sw_off((uint32_t)(row * 128 + kc * 16)));
        }
#pragma unroll
        for (int bj = 0; bj < 4; bj++) {
            int nrow = bj * 16 + (lane & 7) + ((lane >> 4) & 1) * 8;
            int kc = kss * 2 + ((lane >> 3) & 1);
            uint32_t r[4];
            ldmatrix_x4(r, vbase + sw_off((uint32_t)(nrow * 128 + kc * 16)));
            b[bj * 2 + 0][0] = r[0]; b[bj * 2 + 0][1] = r[1];
            b[bj * 2 + 1][0] = r[2]; b[bj * 2 + 1][1] = r[3];
        }
#pragma unroll
        for (int mi = 0; mi < 2; mi++)
#pragma unroll
            for (int ni = 0; ni < 8; ni++)
                mma_16816(accO[mi][ni], a[mi], b[ni]);
    }

#pragma unroll
    for (int mi = 0; mi < 2; mi++) {
#pragma unroll
        for (int ni = 0; ni < 8; ni++) {
            int rA = qb + mi * 16 + (lane >> 2);
            int c0 = ni * 8 + 2 * (lane & 3);
            *(__half2*)(y + basey + (size_t)rA * Cc + c0) =
                __floats2half2_rn(accO[mi][ni][0] * inv[mi][0], accO[mi][ni][1] * inv[mi][0]);
            *(__half2*)(y + basey + (size_t)(rA + 8) * Cc + c0) =
                __floats2half2_rn(accO[mi][ni][2] * inv[mi][1], accO[mi][ni][3] * inv[mi][1]);
        }
    }
}

// ---------------- final LN + head ----------------
__global__ void __launch_bounds__(256) head_kernel(const float* __restrict__ x,
                                                   const float* __restrict__ lnw,
                                                   const float* __restrict__ lnb,
                                                   const float* __restrict__ headW,
                                                   float* __restrict__ out) {
    int bn = blockIdx.x;
    const float* xr = x + ((size_t)bn * Ss + (Ss - 2)) * Cc;
    __shared__ float hsm[Cc];
    int c0 = threadIdx.x * 4;
    float4 f = *(const float4*)(xr + c0);
    float s = f.x + f.y + f.z + f.w;
    float ss = f.x * f.x + f.y * f.y + f.z * f.z + f.w * f.w;
#pragma unroll
    for (int o = 16; o > 0; o >>= 1) {
        s  += __shfl_xor_sync(0xffffffffu, s, o);
        ss += __shfl_xor_sync(0xffffffffu, ss, o);
    }
    __shared__ float rs[8], rss[8];
    int wrp = threadIdx.x >> 5, lane = threadIdx.x & 31;
    if (lane == 0) { rs[wrp] = s; rss[wrp] = ss; }
    __syncthreads();
    s = 0.f; ss = 0.f;
#pragma unroll
    for (int qq = 0; qq < 8; qq++) { s += rs[qq]; ss += rss[qq]; }
    float mean = s * (1.0f / Cc);
    float var = ss * (1.0f / Cc) - mean * mean;
    float rstd = rsqrtf(var + 1e-5f);
    float4 wf = *(const float4*)(lnw + c0);
    float4 bf = *(const float4*)(lnb + c0);
    hsm[c0 + 0] = (f.x - mean) * rstd * wf.x + bf.x;
    hsm[c0 + 1] = (f.y - mean) * rstd * wf.y + bf.y;
    hsm[c0 + 2] = (f.z - mean) * rstd * wf.z + bf.z;
    hsm[c0 + 3] = (f.w - mean) * rstd * wf.w + bf.w;
    __syncthreads();
    if (threadIdx.x < Aa) {
        int a = threadIdx.x;
        float acc = 0.f;
        for (int c = 0; c < Cc; c++) acc += hsm[c] * headW[c * Aa + a];
        out[bn * Aa + a] = acc;
    }
}

// ---------------- host launch ----------------
extern "C" void kernel_launch(void* const* d_in, const int* in_sizes, int n_in,
                              void* d_out, int out_size) {
    const float* states     = (const float*)d_in[0];
    const float* actions    = (const float*)d_in[1];
    const int*   timesteps  = (const int*)d_in[2];
    const float* pos_emb    = (const float*)d_in[3];
    const float* gpe        = (const float*)d_in[4];
    const float* seW        = (const float*)d_in[5];
    const float* seb        = (const float*)d_in[6];
    const float* aeW        = (const float*)d_in[7];
    const float* aeb        = (const float*)d_in[8];
    const float* ln1w       = (const float*)d_in[9];
    const float* ln1b       = (const float*)d_in[10];
    const float* Wq         = (const float*)d_in[11];
    const float* bq         = (const float*)d_in[12];
    const float* Wk         = (const float*)d_in[13];
    const float* bk         = (const float*)d_in[14];
    const float* Wv         = (const float*)d_in[15];
    const float* bv         = (const float*)d_in[16];
    const float* Wp         = (const float*)d_in[17];
    const float* bp         = (const float*)d_in[18];
    const float* ln2w       = (const float*)d_in[19];
    const float* ln2b       = (const float*)d_in[20];
    const float* W1         = (const float*)d_in[21];
    const float* b1         = (const float*)d_in[22];
    const float* W2         = (const float*)d_in[23];
    const float* b2         = (const float*)d_in[24];
    const float* lnfw       = (const float*)d_in[25];
    const float* lnfb       = (const float*)d_in[26];
    const float* headW      = (const float*)d_in[27];

    void *p_x, *p_h, *p_qkv, *p_y, *p_mid;
    void *p_wqkv, *p_bqkv, *p_wp, *p_w1, *p_w2;
    cudaGetSymbolAddress(&p_x, g_x);       cudaGetSymbolAddress(&p_h, g_h);
    cudaGetSymbolAddress(&p_qkv, g_qkv);   cudaGetSymbolAddress(&p_y, g_y);
    cudaGetSymbolAddress(&p_mid, g_mid);   cudaGetSymbolAddress(&p_wqkv, g_wqkv);
    cudaGetSymbolAddress(&p_bqkv, g_bqkv); cudaGetSymbolAddress(&p_wp, g_wp);
    cudaGetSymbolAddress(&p_w1, g_w1);     cudaGetSymbolAddress(&p_w2, g_w2);

    float*  xbuf = (float*)p_x;
    __half* hbuf = (__half*)p_h;
    __half* qkvb = (__half*)p_qkv;
    __half* ybuf = (__half*)p_y;
    __half* midb = (__half*)p_mid;

    cudaFuncSetAttribute(gemm_mma<1, 0, 0>, cudaFuncAttributeMaxDynamicSharedMemorySize, GEMM_SMEM);
    cudaFuncSetAttribute(gemm_mma<0, 0, 1>, cudaFuncAttributeMaxDynamicSharedMemorySize, GEMM_SMEM);
    cudaFuncSetAttribute(gemm_mma<1, 1, 0>, cudaFuncAttributeMaxDynamicSharedMemorySize, GEMM_SMEM);
    cudaFuncSetAttribute(attn_tc, cudaFuncAttributeMaxDynamicSharedMemorySize, ATT_SMEM);

    // ours#1: all weight transposes + gathers + embed weights + bias concat
    wconv_all<<<WCONV_BLOCKS, 256>>>(Wq, Wk, Wv, Wp, W1, W2,
                                     states, actions, seW, aeW, bq, bk, bv);
    // ours#2: both embed GEMMs (z = parity) with fused assemble
    gemm_embed<<<dim3(Cc / BNt, 8192 / BM, 2), 256>>>(seb, aeb, pos_emb, gpe, timesteps, xbuf);

    for (int l = 0; l < Ll; l++) {
        size_t wo  = (size_t)l * Cc * Cc;
        size_t wq3 = (size_t)l * 3 * Cc * Cc;
        size_t w1o = (size_t)l * Cc * 4 * Cc;
        size_t bo  = (size_t)l * Cc;
        size_t b1o = (size_t)l * 4 * Cc;

        // ours#3 (l=0): LN ; ours#4 (l=0): fused QKV gemm  <- ncu capture (2 hidden + 4 = skip 5)
        ln_f2h<<<Rr, 256>>>(xbuf, ln1w + bo, ln1b + bo, hbuf);
        gemm_mma<1, 0, 0><<<dim3(3 * Cc / 128, Rr / 128), 128, GEMM_SMEM>>>(
            hbuf, (__half*)p_wqkv + wq3, (float*)p_bqkv + (size_t)l * 3 * Cc,
            nullptr, p_qkv, Rr, 3 * Cc, Cc);

        attn_tc<<<BNn * Hh, 128, ATT_SMEM>>>(qkvb, ybuf);

        gemm_mma<0, 0, 1><<<dim3(Cc / 128, Rr / 128), 128, GEMM_SMEM>>>(
            ybuf, (__half*)p_wp + wo, bp + bo, xbuf, p_x, Rr, Cc, Cc);

        ln_f2h<<<Rr, 256>>>(xbuf, ln2w + bo, ln2b + bo, hbuf);

        gemm_mma<1, 1, 0><<<dim3(4 * Cc / 128, Rr / 128), 128, GEMM_SMEM>>>(
            hbuf, (__half*)p_w1 + w1o, b1 + b1o, nullptr, p_mid, Rr, 4 * Cc, Cc);
        gemm_mma<0, 0, 1><<<dim3(Cc / 128, Rr / 128), 128, GEMM_SMEM>>>(
            midb, (__half*)p_w2 + w1o, b2 + bo, xbuf, p_x, Rr, Cc, 4 * Cc);
    }

    head_kernel<<<BNn, 256>>>(xbuf, lnfw, lnfb, headW, (float*)d_out);
}

// round 9
// speedup vs baseline: 1.0218x; 1.0218x over previous
#include <cuda_runtime.h>
#include <cuda_fp16.h>
#include <mma.h>
#include <math.h>
#include <stdint.h>

using namespace nvcuda;

// ---------------- problem dims ----------------
#define Bb 8
#define Tt 64
#define Nn 16
#define DSs 128
#define Aa 32
#define Cc 1024
#define Hh 16
#define Ll 8
#define Ss 128            // 2*T
#define BNn 128           // B*N
#define Rr 16384          // BN*S
#define Dd 64             // head dim
#define QKVW (3 * Cc)     // fused qkv row width

// ---------------- scratch (device globals; no allocation allowed) ----------------
__device__ float   g_x[Rr * Cc];            // residual stream (fp32)
__device__ __half  g_h[Rr * Cc];            // LN output (fp16)
__device__ __half  g_qkv[Rr * 3 * Cc];      // fused q|k|v (fp16)
__device__ __half  g_y[Rr * Cc];
__device__ __half  g_mid[Rr * 4 * Cc];
__device__ __half  g_st[BNn * Tt * DSs];
__device__ __half  g_ac[BNn * Tt * Aa];
__device__ __half  g_wqkv[Ll * 3 * Cc * Cc];   // transposed [3C, C] per layer
__device__ float   g_bqkv[Ll * 3 * Cc];
__device__ __half  g_wp[Ll * Cc * Cc];         // transposed [N,K]
__device__ __half  g_w1[Ll * Cc * 4 * Cc];     // transposed [4C, C]
__device__ __half  g_w2[Ll * 4 * Cc * Cc];     // transposed [C, 4C]
__device__ __half  g_sew[DSs * Cc];            // K-major
__device__ __half  g_aew[Aa * Cc];

// ---------------- small helpers ----------------
__device__ __forceinline__ uint32_t smem_to_u32(const void* smem_ptr) {
    uint32_t addr;
    asm("{ .reg .u64 tmp; cvta.to.shared.u64 tmp, %1; cvt.u32.u64 %0, tmp; }"
        : "=r"(addr) : "l"(smem_ptr));
    return addr;
}
__device__ __forceinline__ void cp_async16(uint32_t saddr, const void* gptr) {
    asm volatile("cp.async.cg.shared.global [%0], [%1], 16;" :: "r"(saddr), "l"(gptr));
}
__device__ __forceinline__ void cp_commit() { asm volatile("cp.async.commit_group;" ::: "memory"); }
#define CP_WAIT_GROUP(n) asm volatile("cp.async.wait_group %0;" :: "n"(n) : "memory")

__device__ __forceinline__ uint32_t sw_off(uint32_t off) { return off ^ ((off >> 3) & 0x70u); }

__device__ __forceinline__ void ldmatrix_x4(uint32_t* d, uint32_t addr) {
    asm volatile("ldmatrix.sync.aligned.m8n8.x4.shared.b16 {%0,%1,%2,%3}, [%4];"
                 : "=r"(d[0]), "=r"(d[1]), "=r"(d[2]), "=r"(d[3]) : "r"(addr));
}
__device__ __forceinline__ void mma_16816(float* c, const uint32_t* a, const uint32_t* b) {
    asm volatile("mma.sync.aligned.m16n8k16.row.col.f32.f16.f16.f32 "
                 "{%0,%1,%2,%3}, {%4,%5,%6,%7}, {%8,%9}, {%0,%1,%2,%3};"
                 : "+f"(c[0]), "+f"(c[1]), "+f"(c[2]), "+f"(c[3])
                 : "r"(a[0]), "r"(a[1]), "r"(a[2]), "r"(a[3]), "r"(b[0]), "r"(b[1]));
}

// gelu(x) = 0.5x(1+tanh(z)) with z = 0.79788456(x + 0.044715 x^3)
//         = x / (1 + exp(-2z))   (exact algebraic identity)
__device__ __forceinline__ float gelu_f(float x) {
    float x3 = x * x * x;
    float u = __expf(-1.5957691216057308f * (x + 0.044715f * x3));
    return __fdividef(x, 1.0f + u);
}

// ---------------- prep + all weight transposes (ONE kernel) ----------------
#define WCONV_BLOCKS 104160
__global__ void __launch_bounds__(256) wconv_all(const float* __restrict__ Wq,
                                                 const float* __restrict__ Wk,
                                                 const float* __restrict__ Wv,
                                                 const float* __restrict__ Wp,
                                                 const float* __restrict__ W1,
                                                 const float* __restrict__ W2,
                                                 const float* __restrict__ states,
                                                 const float* __restrict__ actions,
                                                 const float* __restrict__ seW,
                                                 const float* __restrict__ aeW,
                                                 const float* __restrict__ bq,
                                                 const float* __restrict__ bk,
                                                 const float* __restrict__ bv) {
    __shared__ float tile[32][33];
    int bid = blockIdx.x;
    if (bid >= 98304) {
        int i = (bid - 98304) * 256 + threadIdx.x;
        if (i < 1048576) {
            int ds = i % DSs;
            int row = i / DSs;
            int t = row % Tt;
            int bn = row / Tt;
            int b = bn / Nn, n = bn % Nn;
            g_st[i] = __float2half(states[(((size_t)b * Tt + t) * Nn + n) * DSs + ds]);
        } else if (i < 1310720) {
            int j = i - 1048576;
            int a = j % Aa;
            int row = j / Aa;
            int t = row % Tt;
            int bn = row / Tt;
            int b = bn / Nn, n = bn % Nn;
            g_ac[j] = __float2half(actions[(((size_t)b * Tt + t) * Nn + n) * Aa + a]);
        } else if (i < 1441792) {
            int j = i - 1310720;
            g_sew[j] = __float2half(seW[j]);
        } else if (i < 1474560) {
            int j = i - 1441792;
            g_aew[j] = __float2half(aeW[j]);
        } else {
            int j = i - 1474560;            // < Ll*3*Cc
            int l = j / (3 * Cc);
            int k = j - l * 3 * Cc;
            float v = (k < Cc) ? bq[l * Cc + k]
                    : (k < 2 * Cc) ? bk[l * Cc + k - Cc]
                                   : bv[l * Cc + k - 2 * Cc];
            g_bqkv[j] = v;
        }
        return;
    }
    const float* src;
    __half* dst;
    int K, N, bx, by;
    if (bid < 24576) {
        int which = bid >> 13;
        int r = bid & 8191;
        int layer = r >> 10;
        int rt = r & 1023;
        bx = rt & 31; by = rt >> 5; K = Cc; N = Cc;
        src = (which == 0 ? Wq : which == 1 ? Wk : Wv) + (size_t)layer * Cc * Cc;
        dst = g_wqkv + (size_t)layer * 3 * Cc * Cc + (size_t)which * Cc * Cc;
    } else if (bid < 32768) {
        int r = bid - 24576;
        int layer = r >> 10;
        int rt = r & 1023;
        bx = rt & 31; by = rt >> 5; K = Cc; N = Cc;
        src = Wp + (size_t)layer * Cc * Cc;
        dst = g_wp + (size_t)layer * Cc * Cc;
    } else if (bid < 65536) {
        int r = bid - 32768;
        int layer = r >> 12;
        int rt = r & 4095;
        bx = rt & 127; by = rt >> 7; K = Cc; N = 4 * Cc;
        src = W1 + (size_t)layer * Cc * 4 * Cc;
        dst = g_w1 + (size_t)layer * Cc * 4 * Cc;
    } else {
        int r = bid - 65536;
        int layer = r >> 12;
        int rt = r & 4095;
        bx = rt & 31; by = rt >> 5; K = 4 * Cc; N = Cc;
        src = W2 + (size_t)layer * 4 * Cc * Cc;
        dst = g_w2 + (size_t)layer * 4 * Cc * Cc;
    }
    int nb = bx * 32, kb = by * 32;
    int tx = threadIdx.x & 31, ty = threadIdx.x >> 5;  // 32 x 8
#pragma unroll
    for (int r = 0; r < 32; r += 8)
        tile[ty + r][tx] = src[(size_t)(kb + ty + r) * N + nb + tx];
    __syncthreads();
#pragma unroll
    for (int r = 0; r < 32; r += 8)
        dst[(size_t)(nb + ty + r) * K + kb + tx] = __float2half(tile[tx][ty + r]);
}

// ---------------- embed GEMM (wmma) with fused assemble epilogue; z=0 state, z=1 action ----------------
#define BM 128
#define BNt 128
#define BKt 32
#define APAD 8
#define BPAD 8
#define AS_BYTES (2 * BM * (BKt + APAD) * 2)
#define BS_BYTES (2 * BKt * (BNt + BPAD) * 2)

__global__ void __launch_bounds__(256) gemm_embed(const float* __restrict__ bias_s,
                                                  const float* __restrict__ bias_a,
                                                  const float* __restrict__ pe,
                                                  const float* __restrict__ gpe,
                                                  const int* __restrict__ ts,
                                                  float* __restrict__ xout) {
    __shared__ __align__(16) unsigned char sraw[AS_BYTES + BS_BYTES];
    typedef __half (*AsT)[BM][BKt + APAD];
    typedef __half (*BsT)[BKt][BNt + BPAD];
    AsT As = reinterpret_cast<AsT>(sraw);
    BsT Bs = reinterpret_cast<BsT>(sraw + AS_BYTES);

    int parity = blockIdx.z;
    const __half* A  = parity ? g_ac : g_st;
    const __half* Bm = parity ? g_aew : g_sew;
    const float* bias = parity ? bias_a : bias_s;
    int K = parity ? Aa : DSs;
    int N = Cc;

    int tid = threadIdx.x;
    int wid = tid >> 5;
    int wm = wid >> 2;
    int wn = wid & 3;
    int mBase = blockIdx.y * BM;
    int nBase = blockIdx.x * BNt;

    wmma::fragment<wmma::accumulator, 16, 16, 16, float> cf[4][2];
#pragma unroll
    for (int i = 0; i < 4; i++)
#pragma unroll
        for (int j = 0; j < 2; j++) wmma::fill_fragment(cf[i][j], 0.0f);

    int a_row[2], a_col[2], b_row[2], b_col[2];
#pragma unroll
    for (int u = 0; u < 2; u++) {
        int idx = tid + u * 256;
        a_row[u] = idx >> 2;
        a_col[u] = (idx & 3) * 8;
        b_row[u] = idx >> 4;
        b_col[u] = (idx & 15) * 8;
    }

    int ktiles = K / BKt;
    uint4 ra[2], rb[2];
#pragma unroll
    for (int u = 0; u < 2; u++) {
        ra[u] = (a_col[u] < K) ? *(const uint4*)(A + (size_t)(mBase + a_row[u]) * K + a_col[u])
                               : make_uint4(0, 0, 0, 0);
        rb[u] = *(const uint4*)(Bm + (size_t)b_row[u] * N + nBase + b_col[u]);
    }
#pragma unroll
    for (int u = 0; u < 2; u++) {
        if (a_col[u] < BKt) *(uint4*)&As[0][a_row[u]][a_col[u]] = ra[u];
        *(uint4*)&Bs[0][b_row[u]][b_col[u]] = rb[u];
    }
    __syncthreads();

    for (int kt = 0; kt < ktiles; kt++) {
        int cur = kt & 1, nxt = cur ^ 1;
        if (kt + 1 < ktiles) {
            int k0 = (kt + 1) * BKt;
#pragma unroll
            for (int u = 0; u < 2; u++) {
                ra[u] = *(const uint4*)(A + (size_t)(mBase + a_row[u]) * K + k0 + a_col[u]);
                rb[u] = *(const uint4*)(Bm + (size_t)(k0 + b_row[u]) * N + nBase + b_col[u]);
            }
        }
#pragma unroll
        for (int kk = 0; kk < BKt; kk += 16) {
            wmma::fragment<wmma::matrix_a, 16, 16, 16, __half, wmma::row_major> af[4];
            wmma::fragment<wmma::matrix_b, 16, 16, 16, __half, wmma::row_major> bf[2];
#pragma unroll
            for (int i = 0; i < 4; i++)
                wmma::load_matrix_sync(af[i], &As[cur][wm * 64 + i * 16][kk], BKt + APAD);
#pragma unroll
            for (int j = 0; j < 2; j++)
                wmma::load_matrix_sync(bf[j], &Bs[cur][kk][wn * 32 + j * 16], BNt + BPAD);
#pragma unroll
            for (int i = 0; i < 4; i++)
#pragma unroll
                for (int j = 0; j < 2; j++)
                    wmma::mma_sync(cf[i][j], af[i], bf[j], cf[i][j]);
        }
        if (kt + 1 < ktiles) {
            __syncthreads();
#pragma unroll
            for (int u = 0; u < 2; u++) {
                *(uint4*)&As[nxt][a_row[u]][a_col[u]] = ra[u];
                *(uint4*)&Bs[nxt][b_row[u]][b_col[u]] = rb[u];
            }
            __syncthreads();
        }
    }

    __syncthreads();
    float* Epi = reinterpret_cast<float*>(sraw);
#pragma unroll 1
    for (int p = 0; p < 2; p++) {
        if (wm == p) {
#pragma unroll
            for (int i = 0; i < 4; i++)
#pragma unroll
                for (int j = 0; j < 2; j++)
                    wmma::store_matrix_sync(&Epi[(i * 16) * 132 + wn * 32 + j * 16],
                                            cf[i][j], 132, wmma::mem_row_major);
        }
        __syncthreads();
#pragma unroll
        for (int it = 0; it < 8; it++) {
            int idx = tid + it * 256;
            int r = idx >> 5;
            int c4 = (idx & 31) * 4;
            int grow = mBase + p * 64 + r;
            int gcol = nBase + c4;
            float4 vv = *(float4*)&Epi[r * 132 + c4];
            int bn2 = grow >> 6, t = grow & 63, b = bn2 >> 4;
            int s2 = 2 * t + parity;
            int tsv = ts[b * Tt + t];
            const float4 pef = *(const float4*)(pe + (size_t)s2 * Cc + gcol);
            const float4 gf  = *(const float4*)(gpe + (size_t)tsv * Cc + gcol);
            float* Cp = xout + ((size_t)bn2 * Ss + s2) * Cc + gcol;
            *(float4*)Cp = make_float4(vv.x + bias[gcol + 0] + pef.x + gf.x,
                                       vv.y + bias[gcol + 1] + pef.y + gf.y,
                                       vv.z + bias[gcol + 2] + pef.z + gf.z,
                                       vv.w + bias[gcol + 3] + pef.w + gf.w);
        }
        __syncthreads();
    }
}

// ---------------- LayerNorm fp32 -> fp16 ----------------
__global__ void __launch_bounds__(256) ln_f2h(const float* __restrict__ x,
                                              const float* __restrict__ w,
                                              const float* __restrict__ bb,
                                              __half* __restrict__ out) {
    int row = blockIdx.x;
    const float* xr = x + (size_t)row * Cc;
    int c0 = threadIdx.x * 4;
    float4 f = *(const float4*)(xr + c0);
    float s = f.x + f.y + f.z + f.w;
    float ss = f.x * f.x + f.y * f.y + f.z * f.z + f.w * f.w;
#pragma unroll
    for (int o = 16; o > 0; o >>= 1) {
        s  += __shfl_xor_sync(0xffffffffu, s, o);
        ss += __shfl_xor_sync(0xffffffffu, ss, o);
    }
    __shared__ float rs[8], rss[8];
    int wrp = threadIdx.x >> 5, lane = threadIdx.x & 31;
    if (lane == 0) { rs[wrp] = s; rss[wrp] = ss; }
    __syncthreads();
    s = 0.f; ss = 0.f;
#pragma unroll
    for (int qq = 0; qq < 8; qq++) { s += rs[qq]; ss += rss[qq]; }
    float mean = s * (1.0f / Cc);
    float var = ss * (1.0f / Cc) - mean * mean;
    float rstd = rsqrtf(var + 1e-5f);
    float4 wf = *(const float4*)(w + c0);
    float4 bf = *(const float4*)(bb + c0);
    float o0 = (f.x - mean) * rstd * wf.x + bf.x;
    float o1 = (f.y - mean) * rstd * wf.y + bf.y;
    float o2 = (f.z - mean) * rstd * wf.z + bf.z;
    float o3 = (f.w - mean) * rstd * wf.w + bf.w;
    *(__half2*)(out + (size_t)row * Cc + c0)     = __floats2half2_rn(o0, o1);
    *(__half2*)(out + (size_t)row * Cc + c0 + 2) = __floats2half2_rn(o2, o3);
}

// ---------------- HMMA GEMM: 128x128 CTA, 4 warps 64x64, 3-stage cp.async ----------------
#define GBK 64
#define GSTG 3
#define GSTAGE_BYTES 32768          // A 16KB + B 16KB
#define GEMM_SMEM (GSTG * GSTAGE_BYTES)     // 96KB -> 2 CTAs/SM

template <int OUTHALF, int DOGELU, int DORES>
__global__ void __launch_bounds__(128, 2) gemm_mma(const __half* __restrict__ A,
                                                   const __half* __restrict__ Bt,
                                                   const float* __restrict__ bias,
                                                   const float* __restrict__ res,
                                                   void* __restrict__ Cout,
                                                   int M, int N, int K) {
    extern __shared__ unsigned char gsm[];
    uint32_t sbase = smem_to_u32(gsm);
    const int tid = threadIdx.x;
    const int wid = tid >> 5;
    const int lane = tid & 31;
    const int wm = wid & 1;
    const int wn = wid >> 1;
    const int mBase = blockIdx.y * 128;
    const int nBase = blockIdx.x * 128;

    float acc[4][8][4];
#pragma unroll
    for (int i = 0; i < 4; i++)
#pragma unroll
        for (int j = 0; j < 8; j++)
#pragma unroll
            for (int r = 0; r < 4; r++) acc[i][j][r] = 0.f;

    const int KT = K / GBK;

    auto load_stage = [&](int kt) {
        int k0 = kt * GBK;
        uint32_t ab = sbase + (uint32_t)(kt % GSTG) * GSTAGE_BYTES;
        uint32_t bb = ab + 16384;
#pragma unroll
        for (int j = 0; j < 8; j++) {
            int id = tid + j * 128;
            int row = id >> 3;
            int c16 = id & 7;
            uint32_t sw = sw_off((uint32_t)(row * 128 + c16 * 16));
            cp_async16(ab + sw, A + (size_t)(mBase + row) * K + k0 + c16 * 8);
            cp_async16(bb + sw, Bt + (size_t)(nBase + row) * K + k0 + c16 * 8);
        }
    };

    load_stage(0); cp_commit();
    load_stage(1); cp_commit();

    for (int kt = 0; kt < KT; kt++) {
        CP_WAIT_GROUP(1);
        __syncthreads();
        if (kt + 2 < KT) load_stage(kt + 2);
        cp_commit();

        uint32_t ab = sbase + (uint32_t)(kt % GSTG) * GSTAGE_BYTES;
        uint32_t bb = ab + 16384;
#pragma unroll
        for (int ks = 0; ks < 4; ks++) {
            uint32_t a_r[4][4];
            uint32_t b_r[8][2];
#pragma unroll
            for (int mi = 0; mi < 4; mi++) {
                int row = wm * 64 + mi * 16 + (lane & 15);
                int kc = ks * 2 + (lane >> 4);
                ldmatrix_x4(a_r[mi], ab + sw_off((uint32_t)(row * 128 + kc * 16)));
            }
#pragma unroll
            for (int bj = 0; bj < 4; bj++) {
                int nrow = wn * 64 + bj * 16 + (lane & 7) + ((lane >> 4) & 1) * 8;
                int kc = ks * 2 + ((lane >> 3) & 1);
                uint32_t r[4];
                ldmatrix_x4(r, bb + sw_off((uint32_t)(nrow * 128 + kc * 16)));
                b_r[bj * 2 + 0][0] = r[0]; b_r[bj * 2 + 0][1] = r[1];
                b_r[bj * 2 + 1][0] = r[2]; b_r[bj * 2 + 1][1] = r[3];
            }
#pragma unroll
            for (int mi = 0; mi < 4; mi++)
#pragma unroll
                for (int ni = 0; ni < 8; ni++)
                    mma_16816(acc[mi][ni], a_r[mi], b_r[ni]);
        }
    }

#pragma unroll
    for (int mi = 0; mi < 4; mi++) {
#pragma unroll
        for (int ni = 0; ni < 8; ni++) {
            int r0 = mBase + wm * 64 + mi * 16 + (lane >> 2);
            int c0 = nBase + wn * 64 + ni * 8 + 2 * (lane & 3);
            float b0 = bias[c0], b1 = bias[c0 + 1];
#pragma unroll
            for (int half_ = 0; half_ < 2; half_++) {
                int row = r0 + half_ * 8;
                float o0 = acc[mi][ni][half_ * 2 + 0] + b0;
                float o1 = acc[mi][ni][half_ * 2 + 1] + b1;
                if (DOGELU) { o0 = gelu_f(o0); o1 = gelu_f(o1); }
                if (DORES) {
                    const float* rp = res + (size_t)row * N + c0;
                    o0 += rp[0]; o1 += rp[1];
                }
                if (OUTHALF) {
                    *(__half2*)((__half*)Cout + (size_t)row * N + c0) = __floats2half2_rn(o0, o1);
                } else {
                    *(float2*)((float*)Cout + (size_t)row * N + c0) = make_float2(o0, o1);
                }
            }
        }
    }
}

// ---------------- tensor-core attention: block per (bn, head), 4 warps ----------------
#define ATT_SMEM 81920

__global__ void __launch_bounds__(128) attn_tc(const __half* __restrict__ qkv,
                                               __half* __restrict__ y) {
    extern __shared__ unsigned char asm_[];
    uint32_t sb = smem_to_u32(asm_);
    uint32_t sK = sb, sQ = sb + 16384, sV0 = sb + 32768, sV1 = sb + 40960;
    int tid = threadIdx.x, wid = tid >> 5, lane = tid & 31;
    uint32_t sP0 = sb + 49152 + wid * 8192;
    uint32_t sP1 = sP0 + 4096;
    char* pch0 = (char*)asm_ + 49152 + wid * 8192;
    char* pch1 = pch0 + 4096;
    int bh = blockIdx.x, bn = bh >> 4, h = bh & 15;
    size_t baseq = (size_t)bn * Ss * QKVW + h * Dd;
    size_t basey = (size_t)bn * Ss * Cc + h * Dd;

    for (int idx = tid; idx < 1024; idx += 128) {
        int row = idx >> 3, c = idx & 7;
        uint32_t sw = sw_off((uint32_t)(row * 128 + c * 16));
        cp_async16(sQ + sw, qkv + baseq + (size_t)row * QKVW + c * 8);
        cp_async16(sK + sw, qkv + baseq + Cc + (size_t)row * QKVW + c * 8);
    }
    cp_commit();
    for (int idx = tid; idx < 4096; idx += 128) {
        int kv = idx >> 5, d2 = idx & 31;
        __half2 v2 = *(const __half2*)(qkv + baseq + 2 * Cc + (size_t)kv * QKVW + d2 * 2);
        char* vbp = (char*)asm_ + ((kv < 64) ? 32768 : 40960);
        int kc = kv & 63;
        *(__half*)(vbp + sw_off((uint32_t)((d2 * 2) * 128 + kc * 2)))     = __low2half(v2);
        *(__half*)(vbp + sw_off((uint32_t)((d2 * 2 + 1) * 128 + kc * 2))) = __high2half(v2);
    }
    CP_WAIT_GROUP(0);
    __syncthreads();

    int qb = wid * 32;
    float accS[2][16][4];
#pragma unroll
    for (int mi = 0; mi < 2; mi++)
#pragma unroll
        for (int ni = 0; ni < 16; ni++)
#pragma unroll
            for (int r = 0; r < 4; r++) accS[mi][ni][r] = 0.f;

#pragma unroll
    for (int ks = 0; ks < 4; ks++) {
        uint32_t a[2][4], b[16][2];
#pragma unroll
        for (int mi = 0; mi < 2; mi++) {
            int row = qb + mi * 16 + (lane & 15);
            int kc = ks * 2 + (lane >> 4);
            ldmatrix_x4(a[mi], sQ + sw_off((uint32_t)(row * 128 + kc * 16)));
        }
#pragma unroll
        for (int bj = 0; bj < 8; bj++) {
            int nrow = bj * 16 + (lane & 7) + ((lane >> 4) & 1) * 8;
            int kc = ks * 2 + ((lane >> 3) & 1);
            uint32_t r[4];
            ldmatrix_x4(r, sK + sw_off((uint32_t)(nrow * 128 + kc * 16)));
            b[bj * 2 + 0][0] = r[0]; b[bj * 2 + 0][1] = r[1];
            b[bj * 2 + 1][0] = r[2]; b[bj * 2 + 1][1] = r[3];
        }
#pragma unroll
        for (int mi = 0; mi < 2; mi++)
#pragma unroll
            for (int ni = 0; ni < 16; ni++)
                mma_16816(accS[mi][ni], a[mi], b[ni]);
    }

    float inv[2][2];
#pragma unroll
    for (int mi = 0; mi < 2; mi++) {
        float s0 = 0.f, s1 = 0.f;
        int rA = qb + mi * 16 + (lane >> 2);
        int rB = rA + 8;
        int rl = mi * 16 + (lane >> 2);
#pragma unroll
        for (int ni = 0; ni < 16; ni++) {
            int c0 = ni * 8 + 2 * (lane & 3);
            float p00 = (c0     <= rA) ? __expf(accS[mi][ni][0] * 0.125f) : 0.f;
            float p01 = (c0 + 1 <= rA) ? __expf(accS[mi][ni][1] * 0.125f) : 0.f;
            float p10 = (c0     <= rB) ? __expf(accS[mi][ni][2] * 0.125f) : 0.f;
            float p11 = (c0 + 1 <= rB) ? __expf(accS[mi][ni][3] * 0.125f) : 0.f;
            s0 += p00 + p01; s1 += p10 + p11;
            char* pp = (c0 < 64) ? pch0 : pch1;
            int cl = c0 & 63;
            *(__half2*)(pp + sw_off((uint32_t)(rl * 128 + cl * 2)))       = __floats2half2_rn(p00, p01);
            *(__half2*)(pp + sw_off((uint32_t)((rl + 8) * 128 + cl * 2))) = __floats2half2_rn(p10, p11);
        }
        s0 += __shfl_xor_sync(0xffffffffu, s0, 1);
        s0 += __shfl_xor_sync(0xffffffffu, s0, 2);
        s1 += __shfl_xor_sync(0xffffffffu, s1, 1);
        s1 += __shfl_xor_sync(0xffffffffu, s1, 2);
        inv[mi][0] = 1.0f / s0;
        inv[mi][1] = 1.0f / s1;
    }
    __syncwarp();

    float accO[2][8][4];
#pragma unroll
    for (int mi = 0; mi < 2; mi++)
#pragma unroll
        for (int ni = 0; ni < 8; ni++)
#pragma unroll
            for (int r = 0; r < 4; r++) accO[mi][ni][r] = 0.f;

#pragma unroll
    for (int ks = 0; ks < 8; ks++) {
        uint32_t pbase = (ks < 4) ? sP0 : sP1;
        uint32_t vbase = (ks < 4) ? sV0 : sV1;
        int kss = ks & 3;
        uint32_t a[2][4], b[8][2];
#pragma unroll
        for (int mi = 0; mi < 2; mi++) {
            int row = mi * 16 + (lane & 15);
            int kc = kss * 2 + (lane >> 4);
            ldmatrix_x4(a[mi], pbase + sw_off((uint32_t)(row * 128 + kc * 16)));
        }
#pragma unroll
        for (int bj = 0; bj < 4; bj++) {
            int nrow = bj * 16 + (lane & 7) + ((lane >> 4) & 1) * 8;
            int kc = kss * 2 + ((lane >> 3) & 1);
            uint32_t r[4];
            ldmatrix_x4(r, vbase + sw_off((uint32_t)(nrow * 128 + kc * 16)));
            b[bj * 2 + 0][0] = r[0]; b[bj * 2 + 0][1] = r[1];
            b[bj * 2 + 1][0] = r[2]; b[bj * 2 + 1][1] = r[3];
        }
#pragma unroll
        for (int mi = 0; mi < 2; mi++)
#pragma unroll
            for (int ni = 0; ni < 8; ni++)
                mma_16816(accO[mi][ni], a[mi], b[ni]);
    }

#pragma unroll
    for (int mi = 0; mi < 2; mi++) {
#pragma unroll
        for (int ni = 0; ni < 8; ni++) {
            int rA = qb + mi * 16 + (lane >> 2);
            int c0 = ni * 8 + 2 * (lane & 3);
            *(__half2*)(y + basey + (size_t)rA * Cc + c0) =
                __floats2half2_rn(accO[mi][ni][0] * inv[mi][0], accO[mi][ni][1] * inv[mi][0]);
            *(__half2*)(y + basey + (size_t)(rA + 8) * Cc + c0) =
                __floats2half2_rn(accO[mi][ni][2] * inv[mi][1], accO[mi][ni][3] * inv[mi][1]);
        }
    }
}

// ---------------- final LN + head ----------------
__global__ void __launch_bounds__(256) head_kernel(const float* __restrict__ x,
                                                   const float* __restrict__ lnw,
                                                   const float* __restrict__ lnb,
                                                   const float* __restrict__ headW,
                                                   float* __restrict__ out) {
    int bn = blockIdx.x;
    const float* xr = x + ((size_t)bn * Ss + (Ss - 2)) * Cc;
    __shared__ float hsm[Cc];
    int c0 = threadIdx.x * 4;
    float4 f = *(const float4*)(xr + c0);
    float s = f.x + f.y + f.z + f.w;
    float ss = f.x * f.x + f.y * f.y + f.z * f.z + f.w * f.w;
#pragma unroll
    for (int o = 16; o > 0; o >>= 1) {
        s  += __shfl_xor_sync(0xffffffffu, s, o);
        ss += __shfl_xor_sync(0xffffffffu, ss, o);
    }
    __shared__ float rs[8], rss[8];
    int wrp = threadIdx.x >> 5, lane = threadIdx.x & 31;
    if (lane == 0) { rs[wrp] = s; rss[wrp] = ss; }
    __syncthreads();
    s = 0.f; ss = 0.f;
#pragma unroll
    for (int qq = 0; qq < 8; qq++) { s += rs[qq]; ss += rss[qq]; }
    float mean = s * (1.0f / Cc);
    float var = ss * (1.0f / Cc) - mean * mean;
    float rstd = rsqrtf(var + 1e-5f);
    float4 wf = *(const float4*)(lnw + c0);
    float4 bf = *(const float4*)(lnb + c0);
    hsm[c0 + 0] = (f.x - mean) * rstd * wf.x + bf.x;
    hsm[c0 + 1] = (f.y - mean) * rstd * wf.y + bf.y;
    hsm[c0 + 2] = (f.z - mean) * rstd * wf.z + bf.z;
    hsm[c0 + 3] = (f.w - mean) * rstd * wf.w + bf.w;
    __syncthreads();
    if (threadIdx.x < Aa) {
        int a = threadIdx.x;
        float acc = 0.f;
        for (int c = 0; c < Cc; c++) acc += hsm[c] * headW[c * Aa + a];
        out[bn * Aa + a] = acc;
    }
}

// ---------------- host launch ----------------
extern "C" void kernel_launch(void* const* d_in, const int* in_sizes, int n_in,
                              void* d_out, int out_size) {
    const float* states     = (const float*)d_in[0];
    const float* actions    = (const float*)d_in[1];
    const int*   timesteps  = (const int*)d_in[2];
    const float* pos_emb    = (const float*)d_in[3];
    const float* gpe        = (const float*)d_in[4];
    const float* seW        = (const float*)d_in[5];
    const float* seb        = (const float*)d_in[6];
    const float* aeW        = (const float*)d_in[7];
    const float* aeb        = (const float*)d_in[8];
    const float* ln1w       = (const float*)d_in[9];
    const float* ln1b       = (const float*)d_in[10];
    const float* Wq         = (const float*)d_in[11];
    const float* bq         = (const float*)d_in[12];
    const float* Wk         = (const float*)d_in[13];
    const float* bk         = (const float*)d_in[14];
    const float* Wv         = (const float*)d_in[15];
    const float* bv         = (const float*)d_in[16];
    const float* Wp         = (const float*)d_in[17];
    const float* bp         = (const float*)d_in[18];
    const float* ln2w       = (const float*)d_in[19];
    const float* ln2b       = (const float*)d_in[20];
    const float* W1         = (const float*)d_in[21];
    const float* b1         = (const float*)d_in[22];
    const float* W2         = (const float*)d_in[23];
    const float* b2         = (const float*)d_in[24];
    const float* lnfw       = (const float*)d_in[25];
    const float* lnfb       = (const float*)d_in[26];
    const float* headW      = (const float*)d_in[27];

    void *p_x, *p_h, *p_qkv, *p_y, *p_mid;
    void *p_wqkv, *p_bqkv, *p_wp, *p_w1, *p_w2;
    cudaGetSymbolAddress(&p_x, g_x);       cudaGetSymbolAddress(&p_h, g_h);
    cudaGetSymbolAddress(&p_qkv, g_qkv);   cudaGetSymbolAddress(&p_y, g_y);
    cudaGetSymbolAddress(&p_mid, g_mid);   cudaGetSymbolAddress(&p_wqkv, g_wqkv);
    cudaGetSymbolAddress(&p_bqkv, g_bqkv); cudaGetSymbolAddress(&p_wp, g_wp);
    cudaGetSymbolAddress(&p_w1, g_w1);     cudaGetSymbolAddress(&p_w2, g_w2);

    float*  xbuf = (float*)p_x;
    __half* hbuf = (__half*)p_h;
    __half* qkvb = (__half*)p_qkv;
    __half* ybuf = (__half*)p_y;
    __half* midb = (__half*)p_mid;

    cudaFuncSetAttribute(gemm_mma<1, 0, 0>, cudaFuncAttributeMaxDynamicSharedMemorySize, GEMM_SMEM);
    cudaFuncSetAttribute(gemm_mma<0, 0, 1>, cudaFuncAttributeMaxDynamicSharedMemorySize, GEMM_SMEM);
    cudaFuncSetAttribute(gemm_mma<1, 1, 0>, cudaFuncAttributeMaxDynamicSharedMemorySize, GEMM_SMEM);
    cudaFuncSetAttribute(attn_tc, cudaFuncAttributeMaxDynamicSharedMemorySize, ATT_SMEM);

    // ours#1: all weight transposes + gathers + embed weights + bias concat
    wconv_all<<<WCONV_BLOCKS, 256>>>(Wq, Wk, Wv, Wp, W1, W2,
                                     states, actions, seW, aeW, bq, bk, bv);
    // ours#2: both embed GEMMs (z = parity) with fused assemble
    gemm_embed<<<dim3(Cc / BNt, 8192 / BM, 2), 256>>>(seb, aeb, pos_emb, gpe, timesteps, xbuf);

    for (int l = 0; l < Ll; l++) {
        size_t wo  = (size_t)l * Cc * Cc;
        size_t wq3 = (size_t)l * 3 * Cc * Cc;
        size_t w1o = (size_t)l * Cc * 4 * Cc;
        size_t bo  = (size_t)l * Cc;
        size_t b1o = (size_t)l * 4 * Cc;

        // ours#3 (l=0): LN ; ours#4 (l=0): fused QKV gemm  <- ncu capture
        ln_f2h<<<Rr, 256>>>(xbuf, ln1w + bo, ln1b + bo, hbuf);
        gemm_mma<1, 0, 0><<<dim3(3 * Cc / 128, Rr / 128), 128, GEMM_SMEM>>>(
            hbuf, (__half*)p_wqkv + wq3, (float*)p_bqkv + (size_t)l * 3 * Cc,
            nullptr, p_qkv, Rr, 3 * Cc, Cc);

        attn_tc<<<BNn * Hh, 128, ATT_SMEM>>>(qkvb, ybuf);

        gemm_mma<0, 0, 1><<<dim3(Cc / 128, Rr / 128), 128, GEMM_SMEM>>>(
            ybuf, (__half*)p_wp + wo, bp + bo, xbuf, p_x, Rr, Cc, Cc);

        ln_f2h<<<Rr, 256>>>(xbuf, ln2w + bo, ln2b + bo, hbuf);

        gemm_mma<1, 1, 0><<<dim3(4 * Cc / 128, Rr / 128), 128, GEMM_SMEM>>>(
            hbuf, (__half*)p_w1 + w1o, b1 + b1o, nullptr, p_mid, Rr, 4 * Cc, Cc);
        gemm_mma<0, 0, 1><<<dim3(Cc / 128, Rr / 128), 128, GEMM_SMEM>>>(
            midb, (__half*)p_w2 + w1o, b2 + bo, xbuf, p_x, Rr, Cc, 4 * Cc);
    }

    head_kernel<<<BNn, 256>>>(xbuf, lnfw, lnfb, headW, (float*)d_out);
}

// round 10
// speedup vs baseline: 1.1097x; 1.0860x over previous
#include <cuda_runtime.h>
#include <cuda_fp16.h>
#include <mma.h>
#include <math.h>
#include <stdint.h>

using namespace nvcuda;

// ---------------- problem dims ----------------
#define Bb 8
#define Tt 64
#define Nn 16
#define DSs 128
#define Aa 32
#define Cc 1024
#define Hh 16
#define Ll 8
#define Ss 128            // 2*T
#define BNn 128           // B*N
#define Rr 16384          // BN*S
#define Dd 64             // head dim
#define QKVW (3 * Cc)     // fused qkv row width

// ---------------- scratch (device globals; no allocation allowed) ----------------
__device__ float   g_x[Rr * Cc];            // residual stream (fp32)
__device__ __half  g_h[Rr * Cc];            // LN output (fp16)
__device__ __half  g_qkv[Rr * 3 * Cc];      // fused q|k|v (fp16)
__device__ __half  g_y[Rr * Cc];
__device__ __half  g_mid[Rr * 4 * Cc];
__device__ __half  g_st[BNn * Tt * DSs];
__device__ __half  g_ac[BNn * Tt * Aa];
__device__ __half  g_wqkv[Ll * 3 * Cc * Cc];   // transposed [3C, C] per layer
__device__ float   g_bqkv[Ll * 3 * Cc];
__device__ __half  g_wp[Ll * Cc * Cc];         // transposed [N,K]
__device__ __half  g_w1[Ll * Cc * 4 * Cc];     // transposed [4C, C]
__device__ __half  g_w2[Ll * 4 * Cc * Cc];     // transposed [C, 4C]
__device__ __half  g_sew[DSs * Cc];            // K-major
__device__ __half  g_aew[Aa * Cc];
// last-layer compact buffers (row 126 of each bn)
__device__ __half  g_hq126[BNn * Cc];
__device__ float   g_x126[BNn * Cc];
__device__ __half  g_q126[BNn * Cc];
__device__ __half  g_y126[BNn * Cc];
__device__ __half  g_h126[BNn * Cc];
__device__ __half  g_mid126[BNn * 4 * Cc];

// ---------------- small helpers ----------------
__device__ __forceinline__ uint32_t smem_to_u32(const void* smem_ptr) {
    uint32_t addr;
    asm("{ .reg .u64 tmp; cvta.to.shared.u64 tmp, %1; cvt.u32.u64 %0, tmp; }"
        : "=r"(addr) : "l"(smem_ptr));
    return addr;
}
__device__ __forceinline__ void cp_async16(uint32_t saddr, const void* gptr) {
    asm volatile("cp.async.cg.shared.global [%0], [%1], 16;" :: "r"(saddr), "l"(gptr));
}
__device__ __forceinline__ void cp_commit() { asm volatile("cp.async.commit_group;" ::: "memory"); }
#define CP_WAIT_GROUP(n) asm volatile("cp.async.wait_group %0;" :: "n"(n) : "memory")

__device__ __forceinline__ uint32_t sw_off(uint32_t off) { return off ^ ((off >> 3) & 0x70u); }

__device__ __forceinline__ void ldmatrix_x4(uint32_t* d, uint32_t addr) {
    asm volatile("ldmatrix.sync.aligned.m8n8.x4.shared.b16 {%0,%1,%2,%3}, [%4];"
                 : "=r"(d[0]), "=r"(d[1]), "=r"(d[2]), "=r"(d[3]) : "r"(addr));
}
__device__ __forceinline__ void mma_16816(float* c, const uint32_t* a, const uint32_t* b) {
    asm volatile("mma.sync.aligned.m16n8k16.row.col.f32.f16.f16.f32 "
                 "{%0,%1,%2,%3}, {%4,%5,%6,%7}, {%8,%9}, {%0,%1,%2,%3};"
                 : "+f"(c[0]), "+f"(c[1]), "+f"(c[2]), "+f"(c[3])
                 : "r"(a[0]), "r"(a[1]), "r"(a[2]), "r"(a[3]), "r"(b[0]), "r"(b[1]));
}

// gelu(x) = 0.5x(1+tanh(z)) = x / (1 + exp(-2z)), exact identity
__device__ __forceinline__ float gelu_f(float x) {
    float x3 = x * x * x;
    float u = __expf(-1.5957691216057308f * (x + 0.044715f * x3));
    return __fdividef(x, 1.0f + u);
}

// ---------------- prep + all weight transposes (ONE kernel) ----------------
#define WCONV_BLOCKS 104160
__global__ void __launch_bounds__(256) wconv_all(const float* __restrict__ Wq,
                                                 const float* __restrict__ Wk,
                                                 const float* __restrict__ Wv,
                                                 const float* __restrict__ Wp,
                                                 const float* __restrict__ W1,
                                                 const float* __restrict__ W2,
                                                 const float* __restrict__ states,
                                                 const float* __restrict__ actions,
                                                 const float* __restrict__ seW,
                                                 const float* __restrict__ aeW,
                                                 const float* __restrict__ bq,
                                                 const float* __restrict__ bk,
                                                 const float* __restrict__ bv) {
    __shared__ float tile[32][33];
    int bid = blockIdx.x;
    if (bid >= 98304) {
        int i = (bid - 98304) * 256 + threadIdx.x;
        if (i < 1048576) {
            int ds = i % DSs;
            int row = i / DSs;
            int t = row % Tt;
            int bn = row / Tt;
            int b = bn / Nn, n = bn % Nn;
            g_st[i] = __float2half(states[(((size_t)b * Tt + t) * Nn + n) * DSs + ds]);
        } else if (i < 1310720) {
            int j = i - 1048576;
            int a = j % Aa;
            int row = j / Aa;
            int t = row % Tt;
            int bn = row / Tt;
            int b = bn / Nn, n = bn % Nn;
            g_ac[j] = __float2half(actions[(((size_t)b * Tt + t) * Nn + n) * Aa + a]);
        } else if (i < 1441792) {
            int j = i - 1310720;
            g_sew[j] = __float2half(seW[j]);
        } else if (i < 1474560) {
            int j = i - 1441792;
            g_aew[j] = __float2half(aeW[j]);
        } else {
            int j = i - 1474560;            // < Ll*3*Cc
            int l = j / (3 * Cc);
            int k = j - l * 3 * Cc;
            float v = (k < Cc) ? bq[l * Cc + k]
                    : (k < 2 * Cc) ? bk[l * Cc + k - Cc]
                                   : bv[l * Cc + k - 2 * Cc];
            g_bqkv[j] = v;
        }
        return;
    }
    const float* src;
    __half* dst;
    int K, N, bx, by;
    if (bid < 24576) {
        int which = bid >> 13;
        int r = bid & 8191;
        int layer = r >> 10;
        int rt = r & 1023;
        bx = rt & 31; by = rt >> 5; K = Cc; N = Cc;
        src = (which == 0 ? Wq : which == 1 ? Wk : Wv) + (size_t)layer * Cc * Cc;
        dst = g_wqkv + (size_t)layer * 3 * Cc * Cc + (size_t)which * Cc * Cc;
    } else if (bid < 32768) {
        int r = bid - 24576;
        int layer = r >> 10;
        int rt = r & 1023;
        bx = rt & 31; by = rt >> 5; K = Cc; N = Cc;
        src = Wp + (size_t)layer * Cc * Cc;
        dst = g_wp + (size_t)layer * Cc * Cc;
    } else if (bid < 65536) {
        int r = bid - 32768;
        int layer = r >> 12;
        int rt = r & 4095;
        bx = rt & 127; by = rt >> 7; K = Cc; N = 4 * Cc;
        src = W1 + (size_t)layer * Cc * 4 * Cc;
        dst = g_w1 + (size_t)layer * Cc * 4 * Cc;
    } else {
        int r = bid - 65536;
        int layer = r >> 12;
        int rt = r & 4095;
        bx = rt & 31; by = rt >> 5; K = 4 * Cc; N = Cc;
        src = W2 + (size_t)layer * 4 * Cc * Cc;
        dst = g_w2 + (size_t)layer * 4 * Cc * Cc;
    }
    int nb = bx * 32, kb = by * 32;
    int tx = threadIdx.x & 31, ty = threadIdx.x >> 5;  // 32 x 8
#pragma unroll
    for (int r = 0; r < 32; r += 8)
        tile[ty + r][tx] = src[(size_t)(kb + ty + r) * N + nb + tx];
    __syncthreads();
#pragma unroll
    for (int r = 0; r < 32; r += 8)
        dst[(size_t)(nb + ty + r) * K + kb + tx] = __float2half(tile[tx][ty + r]);
}

// ---------------- embed GEMM (wmma) with fused assemble epilogue; z=0 state, z=1 action ----------------
#define BM 128
#define BNt 128
#define BKt 32
#define APAD 8
#define BPAD 8
#define AS_BYTES (2 * BM * (BKt + APAD) * 2)
#define BS_BYTES (2 * BKt * (BNt + BPAD) * 2)

__global__ void __launch_bounds__(256) gemm_embed(const float* __restrict__ bias_s,
                                                  const float* __restrict__ bias_a,
                                                  const float* __restrict__ pe,
                                                  const float* __restrict__ gpe,
                                                  const int* __restrict__ ts,
                                                  float* __restrict__ xout) {
    __shared__ __align__(16) unsigned char sraw[AS_BYTES + BS_BYTES];
    typedef __half (*AsT)[BM][BKt + APAD];
    typedef __half (*BsT)[BKt][BNt + BPAD];
    AsT As = reinterpret_cast<AsT>(sraw);
    BsT Bs = reinterpret_cast<BsT>(sraw + AS_BYTES);

    int parity = blockIdx.z;
    const __half* A  = parity ? g_ac : g_st;
    const __half* Bm = parity ? g_aew : g_sew;
    const float* bias = parity ? bias_a : bias_s;
    int K = parity ? Aa : DSs;
    int N = Cc;

    int tid = threadIdx.x;
    int wid = tid >> 5;
    int wm = wid >> 2;
    int wn = wid & 3;
    int mBase = blockIdx.y * BM;
    int nBase = blockIdx.x * BNt;

    wmma::fragment<wmma::accumulator, 16, 16, 16, float> cf[4][2];
#pragma unroll
    for (int i = 0; i < 4; i++)
#pragma unroll
        for (int j = 0; j < 2; j++) wmma::fill_fragment(cf[i][j], 0.0f);

    int a_row[2], a_col[2], b_row[2], b_col[2];
#pragma unroll
    for (int u = 0; u < 2; u++) {
        int idx = tid + u * 256;
        a_row[u] = idx >> 2;
        a_col[u] = (idx & 3) * 8;
        b_row[u] = idx >> 4;
        b_col[u] = (idx & 15) * 8;
    }

    int ktiles = K / BKt;
    uint4 ra[2], rb[2];
#pragma unroll
    for (int u = 0; u < 2; u++) {
        ra[u] = (a_col[u] < K) ? *(const uint4*)(A + (size_t)(mBase + a_row[u]) * K + a_col[u])
                               : make_uint4(0, 0, 0, 0);
        rb[u] = *(const uint4*)(Bm + (size_t)b_row[u] * N + nBase + b_col[u]);
    }
#pragma unroll
    for (int u = 0; u < 2; u++) {
        if (a_col[u] < BKt) *(uint4*)&As[0][a_row[u]][a_col[u]] = ra[u];
        *(uint4*)&Bs[0][b_row[u]][b_col[u]] = rb[u];
    }
    __syncthreads();

    for (int kt = 0; kt < ktiles; kt++) {
        int cur = kt & 1, nxt = cur ^ 1;
        if (kt + 1 < ktiles) {
            int k0 = (kt + 1) * BKt;
#pragma unroll
            for (int u = 0; u < 2; u++) {
                ra[u] = *(const uint4*)(A + (size_t)(mBase + a_row[u]) * K + k0 + a_col[u]);
                rb[u] = *(const uint4*)(Bm + (size_t)(k0 + b_row[u]) * N + nBase + b_col[u]);
            }
        }
#pragma unroll
        for (int kk = 0; kk < BKt; kk += 16) {
            wmma::fragment<wmma::matrix_a, 16, 16, 16, __half, wmma::row_major> af[4];
            wmma::fragment<wmma::matrix_b, 16, 16, 16, __half, wmma::row_major> bf[2];
#pragma unroll
            for (int i = 0; i < 4; i++)
                wmma::load_matrix_sync(af[i], &As[cur][wm * 64 + i * 16][kk], BKt + APAD);
#pragma unroll
            for (int j = 0; j < 2; j++)
                wmma::load_matrix_sync(bf[j], &Bs[cur][kk][wn * 32 + j * 16], BNt + BPAD);
#pragma unroll
            for (int i = 0; i < 4; i++)
#pragma unroll
                for (int j = 0; j < 2; j++)
                    wmma::mma_sync(cf[i][j], af[i], bf[j], cf[i][j]);
        }
        if (kt + 1 < ktiles) {
            __syncthreads();
#pragma unroll
            for (int u = 0; u < 2; u++) {
                *(uint4*)&As[nxt][a_row[u]][a_col[u]] = ra[u];
                *(uint4*)&Bs[nxt][b_row[u]][b_col[u]] = rb[u];
            }
            __syncthreads();
        }
    }

    __syncthreads();
    float* Epi = reinterpret_cast<float*>(sraw);
#pragma unroll 1
    for (int p = 0; p < 2; p++) {
        if (wm == p) {
#pragma unroll
            for (int i = 0; i < 4; i++)
#pragma unroll
                for (int j = 0; j < 2; j++)
                    wmma::store_matrix_sync(&Epi[(i * 16) * 132 + wn * 32 + j * 16],
                                            cf[i][j], 132, wmma::mem_row_major);
        }
        __syncthreads();
#pragma unroll
        for (int it = 0; it < 8; it++) {
            int idx = tid + it * 256;
            int r = idx >> 5;
            int c4 = (idx & 31) * 4;
            int grow = mBase + p * 64 + r;
            int gcol = nBase + c4;
            float4 vv = *(float4*)&Epi[r * 132 + c4];
            int bn2 = grow >> 6, t = grow & 63, b = bn2 >> 4;
            int s2 = 2 * t + parity;
            int tsv = ts[b * Tt + t];
            const float4 pef = *(const float4*)(pe + (size_t)s2 * Cc + gcol);
            const float4 gf  = *(const float4*)(gpe + (size_t)tsv * Cc + gcol);
            float* Cp = xout + ((size_t)bn2 * Ss + s2) * Cc + gcol;
            *(float4*)Cp = make_float4(vv.x + bias[gcol + 0] + pef.x + gf.x,
                                       vv.y + bias[gcol + 1] + pef.y + gf.y,
                                       vv.z + bias[gcol + 2] + pef.z + gf.z,
                                       vv.w + bias[gcol + 3] + pef.w + gf.w);
        }
        __syncthreads();
    }
}

// ---------------- LayerNorm fp32 -> fp16 ----------------
__global__ void __launch_bounds__(256) ln_f2h(const float* __restrict__ x,
                                              const float* __restrict__ w,
                                              const float* __restrict__ bb,
                                              __half* __restrict__ out) {
    int row = blockIdx.x;
    const float* xr = x + (size_t)row * Cc;
    int c0 = threadIdx.x * 4;
    float4 f = *(const float4*)(xr + c0);
    float s = f.x + f.y + f.z + f.w;
    float ss = f.x * f.x + f.y * f.y + f.z * f.z + f.w * f.w;
#pragma unroll
    for (int o = 16; o > 0; o >>= 1) {
        s  += __shfl_xor_sync(0xffffffffu, s, o);
        ss += __shfl_xor_sync(0xffffffffu, ss, o);
    }
    __shared__ float rs[8], rss[8];
    int wrp = threadIdx.x >> 5, lane = threadIdx.x & 31;
    if (lane == 0) { rs[wrp] = s; rss[wrp] = ss; }
    __syncthreads();
    s = 0.f; ss = 0.f;
#pragma unroll
    for (int qq = 0; qq < 8; qq++) { s += rs[qq]; ss += rss[qq]; }
    float mean = s * (1.0f / Cc);
    float var = ss * (1.0f / Cc) - mean * mean;
    float rstd = rsqrtf(var + 1e-5f);
    float4 wf = *(const float4*)(w + c0);
    float4 bf = *(const float4*)(bb + c0);
    float o0 = (f.x - mean) * rstd * wf.x + bf.x;
    float o1 = (f.y - mean) * rstd * wf.y + bf.y;
    float o2 = (f.z - mean) * rstd * wf.z + bf.z;
    float o3 = (f.w - mean) * rstd * wf.w + bf.w;
    *(__half2*)(out + (size_t)row * Cc + c0)     = __floats2half2_rn(o0, o1);
    *(__half2*)(out + (size_t)row * Cc + c0 + 2) = __floats2half2_rn(o2, o3);
}

// ---------------- gather row 126 of each bn: h (fp16) and x (fp32) ----------------
__global__ void gather126(const __half* __restrict__ h, const float* __restrict__ x) {
    int i = blockIdx.x * 256 + threadIdx.x;       // < 2*131072
    if (i < BNn * Cc) {
        int bn = i >> 10, c = i & (Cc - 1);
        g_hq126[i] = h[((size_t)bn * Ss + (Ss - 2)) * Cc + c];
    } else {
        int j = i - BNn * Cc;
        int bn = j >> 10, c = j & (Cc - 1);
        g_x126[j] = x[((size_t)bn * Ss + (Ss - 2)) * Cc + c];
    }
}

// ---------------- HMMA GEMM: 128x128 CTA, 4 warps 64x64, 3-stage cp.async ----------------
#define GBK 64
#define GSTG 3
#define GSTAGE_BYTES 32768          // A 16KB + B 16KB
#define GEMM_SMEM (GSTG * GSTAGE_BYTES)     // 96KB -> 2 CTAs/SM

template <int OUTHALF, int DOGELU, int DORES>
__global__ void __launch_bounds__(128, 2) gemm_mma(const __half* __restrict__ A,
                                                   const __half* __restrict__ Bt,
                                                   const float* __restrict__ bias,
                                                   const float* __restrict__ res,
                                                   void* __restrict__ Cout,
                                                   int M, int N, int K) {
    extern __shared__ unsigned char gsm[];
    uint32_t sbase = smem_to_u32(gsm);
    const int tid = threadIdx.x;
    const int wid = tid >> 5;
    const int lane = tid & 31;
    const int wm = wid & 1;
    const int wn = wid >> 1;
    const int mBase = blockIdx.y * 128;
    const int nBase = blockIdx.x * 128;

    float acc[4][8][4];
#pragma unroll
    for (int i = 0; i < 4; i++)
#pragma unroll
        for (int j = 0; j < 8; j++)
#pragma unroll
            for (int r = 0; r < 4; r++) acc[i][j][r] = 0.f;

    const int KT = K / GBK;

    auto load_stage = [&](int kt) {
        int k0 = kt * GBK;
        uint32_t ab = sbase + (uint32_t)(kt % GSTG) * GSTAGE_BYTES;
        uint32_t bb = ab + 16384;
#pragma unroll
        for (int j = 0; j < 8; j++) {
            int id = tid + j * 128;
            int row = id >> 3;
            int c16 = id & 7;
            uint32_t sw = sw_off((uint32_t)(row * 128 + c16 * 16));
            cp_async16(ab + sw, A + (size_t)(mBase + row) * K + k0 + c16 * 8);
            cp_async16(bb + sw, Bt + (size_t)(nBase + row) * K + k0 + c16 * 8);
        }
    };

    load_stage(0); cp_commit();
    load_stage(1); cp_commit();

    for (int kt = 0; kt < KT; kt++) {
        CP_WAIT_GROUP(1);
        __syncthreads();
        if (kt + 2 < KT) load_stage(kt + 2);
        cp_commit();

        uint32_t ab = sbase + (uint32_t)(kt % GSTG) * GSTAGE_BYTES;
        uint32_t bb = ab + 16384;
#pragma unroll
        for (int ks = 0; ks < 4; ks++) {
            uint32_t a_r[4][4];
            uint32_t b_r[8][2];
#pragma unroll
            for (int mi = 0; mi < 4; mi++) {
                int row = wm * 64 + mi * 16 + (lane & 15);
                int kc = ks * 2 + (lane >> 4);
                ldmatrix_x4(a_r[mi], ab + sw_off((uint32_t)(row * 128 + kc * 16)));
            }
#pragma unroll
            for (int bj = 0; bj < 4; bj++) {
                int nrow = wn * 64 + bj * 16 + (lane & 7) + ((lane >> 4) & 1) * 8;
                int kc = ks * 2 + ((lane >> 3) & 1);
                uint32_t r[4];
                ldmatrix_x4(r, bb + sw_off((uint32_t)(nrow * 128 + kc * 16)));
                b_r[bj * 2 + 0][0] = r[0]; b_r[bj * 2 + 0][1] = r[1];
                b_r[bj * 2 + 1][0] = r[2]; b_r[bj * 2 + 1][1] = r[3];
            }
#pragma unroll
            for (int mi = 0; mi < 4; mi++)
#pragma unroll
                for (int ni = 0; ni < 8; ni++)
                    mma_16816(acc[mi][ni], a_r[mi], b_r[ni]);
        }
    }

#pragma unroll
    for (int mi = 0; mi < 4; mi++) {
#pragma unroll
        for (int ni = 0; ni < 8; ni++) {
            int r0 = mBase + wm * 64 + mi * 16 + (lane >> 2);
            int c0 = nBase + wn * 64 + ni * 8 + 2 * (lane & 3);
            float b0 = bias[c0], b1 = bias[c0 + 1];
#pragma unroll
            for (int half_ = 0; half_ < 2; half_++) {
                int row = r0 + half_ * 8;
                float o0 = acc[mi][ni][half_ * 2 + 0] + b0;
                float o1 = acc[mi][ni][half_ * 2 + 1] + b1;
                if (DOGELU) { o0 = gelu_f(o0); o1 = gelu_f(o1); }
                if (DORES) {
                    const float* rp = res + (size_t)row * N + c0;
                    o0 += rp[0]; o1 += rp[1];
                }
                if (OUTHALF) {
                    *(__half2*)((__half*)Cout + (size_t)row * N + c0) = __floats2half2_rn(o0, o1);
                } else {
                    *(float2*)((float*)Cout + (size_t)row * N + c0) = make_float2(o0, o1);
                }
            }
        }
    }
}

// ---------------- tensor-core attention: block per (bn, head), 4 warps ----------------
#define ATT_SMEM 81920

__global__ void __launch_bounds__(128) attn_tc(const __half* __restrict__ qkv,
                                               __half* __restrict__ y) {
    extern __shared__ unsigned char asm_[];
    uint32_t sb = smem_to_u32(asm_);
    uint32_t sK = sb, sQ = sb + 16384, sV0 = sb + 32768, sV1 = sb + 40960;
    int tid = threadIdx.x, wid = tid >> 5, lane = tid & 31;
    uint32_t sP0 = sb + 49152 + wid * 8192;
    uint32_t sP1 = sP0 + 4096;
    char* pch0 = (char*)asm_ + 49152 + wid * 8192;
    char* pch1 = pch0 + 4096;
    int bh = blockIdx.x, bn = bh >> 4, h = bh & 15;
    size_t baseq = (size_t)bn * Ss * QKVW + h * Dd;
    size_t basey = (size_t)bn * Ss * Cc + h * Dd;

    for (int idx = tid; idx < 1024; idx += 128) {
        int row = idx >> 3, c = idx & 7;
        uint32_t sw = sw_off((uint32_t)(row * 128 + c * 16));
        cp_async16(sQ + sw, qkv + baseq + (size_t)row * QKVW + c * 8);
        cp_async16(sK + sw, qkv + baseq + Cc + (size_t)row * QKVW + c * 8);
    }
    cp_commit();
    for (int idx = tid; idx < 4096; idx += 128) {
        int kv = idx >> 5, d2 = idx & 31;
        __half2 v2 = *(const __half2*)(qkv + baseq + 2 * Cc + (size_t)kv * QKVW + d2 * 2);
        char* vbp = (char*)asm_ + ((kv < 64) ? 32768 : 40960);
        int kc = kv & 63;
        *(__half*)(vbp + sw_off((uint32_t)((d2 * 2) * 128 + kc * 2)))     = __low2half(v2);
        *(__half*)(vbp + sw_off((uint32_t)((d2 * 2 + 1) * 128 + kc * 2))) = __high2half(v2);
    }
    CP_WAIT_GROUP(0);
    __syncthreads();

    int qb = wid * 32;
    float accS[2][16][4];
#pragma unroll
    for (int mi = 0; mi < 2; mi++)
#pragma unroll
        for (int ni = 0; ni < 16; ni++)
#pragma unroll
            for (int r = 0; r < 4; r++) accS[mi][ni][r] = 0.f;

#pragma unroll
    for (int ks = 0; ks < 4; ks++) {
        uint32_t a[2][4], b[16][2];
#pragma unroll
        for (int mi = 0; mi < 2; mi++) {
            int row = qb + mi * 16 + (lane & 15);
            int kc = ks * 2 + (lane >> 4);
            ldmatrix_x4(a[mi], sQ + sw_off((uint32_t)(row * 128 + kc * 16)));
        }
#pragma unroll
        for (int bj = 0; bj < 8; bj++) {
            int nrow = bj * 16 + (lane & 7) + ((lane >> 4) & 1) * 8;
            int kc = ks * 2 + ((lane >> 3) & 1);
            uint32_t r[4];
            ldmatrix_x4(r, sK + sw_off((uint32_t)(nrow * 128 + kc * 16)));
            b[bj * 2 + 0][0] = r[0]; b[bj * 2 + 0][1] = r[1];
            b[bj * 2 + 1][0] = r[2]; b[bj * 2 + 1][1] = r[3];
        }
#pragma unroll
        for (int mi = 0; mi < 2; mi++)
#pragma unroll
            for (int ni = 0; ni < 16; ni++)
                mma_16816(accS[mi][ni], a[mi], b[ni]);
    }

    float inv[2][2];
#pragma unroll
    for (int mi = 0; mi < 2; mi++) {
        float s0 = 0.f, s1 = 0.f;
        int rA = qb + mi * 16 + (lane >> 2);
        int rB = rA + 8;
        int rl = mi * 16 + (lane >> 2);
#pragma unroll
        for (int ni = 0; ni < 16; ni++) {
            int c0 = ni * 8 + 2 * (lane & 3);
            float p00 = (c0     <= rA) ? __expf(accS[mi][ni][0] * 0.125f) : 0.f;
            float p01 = (c0 + 1 <= rA) ? __expf(accS[mi][ni][1] * 0.125f) : 0.f;
            float p10 = (c0     <= rB) ? __expf(accS[mi][ni][2] * 0.125f) : 0.f;
            float p11 = (c0 + 1 <= rB) ? __expf(accS[mi][ni][3] * 0.125f) : 0.f;
            s0 += p00 + p01; s1 += p10 + p11;
            char* pp = (c0 < 64) ? pch0 : pch1;
            int cl = c0 & 63;
            *(__half2*)(pp + sw_off((uint32_t)(rl * 128 + cl * 2)))       = __floats2half2_rn(p00, p01);
            *(__half2*)(pp + sw_off((uint32_t)((rl + 8) * 128 + cl * 2))) = __floats2half2_rn(p10, p11);
        }
        s0 += __shfl_xor_sync(0xffffffffu, s0, 1);
        s0 += __shfl_xor_sync(0xffffffffu, s0, 2);
        s1 += __shfl_xor_sync(0xffffffffu, s1, 1);
        s1 += __shfl_xor_sync(0xffffffffu, s1, 2);
        inv[mi][0] = 1.0f / s0;
        inv[mi][1] = 1.0f / s1;
    }
    __syncwarp();

    float accO[2][8][4];
#pragma unroll
    for (int mi = 0; mi < 2; mi++)
#pragma unroll
        for (int ni = 0; ni < 8; ni++)
#pragma unroll
            for (int r = 0; r < 4; r++) accO[mi][ni][r] = 0.f;

#pragma unroll
    for (int ks = 0; ks < 8; ks++) {
        uint32_t pbase = (ks < 4) ? sP0 : sP1;
        uint32_t vbase = (ks < 4) ? sV0 : sV1;
        int kss = ks & 3;
        uint32_t a[2][4], b[8][2];
#pragma unroll
        for (int mi = 0; mi < 2; mi++) {
            int row = mi * 16 + (lane & 15);
            int kc = kss * 2 + (lane >> 4);
            ldmatrix_x4(a[mi], pbase + sw_off((uint32_t)(row * 128 + kc * 16)));
        }
#pragma unroll
        for (int bj = 0; bj < 4; bj++) {
            int nrow = bj * 16 + (lane & 7) + ((lane >> 4) & 1) * 8;
            int kc = kss * 2 + ((lane >> 3) & 1);
            uint32_t r[4];
            ldmatrix_x4(r, vbase + sw_off((uint32_t)(nrow * 128 + kc * 16)));
            b[bj * 2 + 0][0] = r[0]; b[bj * 2 + 0][1] = r[1];
            b[bj * 2 + 1][0] = r[2]; b[bj * 2 + 1][1] = r[3];
        }
#pragma unroll
        for (int mi = 0; mi < 2; mi++)
#pragma unroll
            for (int ni = 0; ni < 8; ni++)
                mma_16816(accO[mi][ni], a[mi], b[ni]);
    }

#pragma unroll
    for (int mi = 0; mi < 2; mi++) {
#pragma unroll
        for (int ni = 0; ni < 8; ni++) {
            int rA = qb + mi * 16 + (lane >> 2);
            int c0 = ni * 8 + 2 * (lane & 3);
            *(__half2*)(y + basey + (size_t)rA * Cc + c0) =
                __floats2half2_rn(accO[mi][ni][0] * inv[mi][0], accO[mi][ni][1] * inv[mi][0]);
            *(__half2*)(y + basey + (size_t)(rA + 8) * Cc + c0) =
                __floats2half2_rn(accO[mi][ni][2] * inv[mi][1], accO[mi][ni][3] * inv[mi][1]);
        }
    }
}

// ---------------- last-layer single-query attention: block per (bn,h) ----------------
__global__ void __launch_bounds__(128) attn_last(const __half* __restrict__ qkv,
                                                 const __half* __restrict__ q126,
                                                 __half* __restrict__ y126) {
    __shared__ float qs[Dd];
    __shared__ float e[Ss];
    __shared__ float ws[4];
    int tid = threadIdx.x, wid = tid >> 5, lane = tid & 31;
    int bh = blockIdx.x, bn = bh >> 4, h = bh & 15;
    size_t base = (size_t)bn * Ss * QKVW + h * Dd;

    if (tid < 32) {
        float2 f = __half22float2(*(const __half2*)(q126 + (size_t)bn * Cc + h * Dd + tid * 2));
        qs[tid * 2] = f.x; qs[tid * 2 + 1] = f.y;
    }
    __syncthreads();

    int j = tid;
    float ej = 0.f;
    if (j <= Ss - 2) {
        const __half* kr = qkv + base + Cc + (size_t)j * QKVW;
        float s = 0.f;
#pragma unroll
        for (int i = 0; i < Dd; i++) s += qs[i] * __half2float(kr[i]);
        ej = __expf(s * 0.125f);
    }
    e[j] = ej;
    float s = ej;
#pragma unroll
    for (int o = 16; o > 0; o >>= 1) s += __shfl_xor_sync(0xffffffffu, s, o);
    if (lane == 0) ws[wid] = s;
    __syncthreads();
    float sum = ws[0] + ws[1] + ws[2] + ws[3];

    if (tid < Dd) {
        float acc = 0.f;
        for (int k = 0; k <= Ss - 2; k++)
            acc += e[k] * __half2float(qkv[base + 2 * Cc + (size_t)k * QKVW + tid]);
        y126[(size_t)bn * Cc + h * Dd + tid] = __float2half(acc / sum);
    }
}

// ---------------- final LN + head (compact x126 input) ----------------
__global__ void __launch_bounds__(256) head_kernel(const float* __restrict__ x,
                                                   const float* __restrict__ lnw,
                                                   const float* __restrict__ lnb,
                                                   const float* __restrict__ headW,
                                                   float* __restrict__ out) {
    int bn = blockIdx.x;
    const float* xr = x + (size_t)bn * Cc;
    __shared__ float hsm[Cc];
    int c0 = threadIdx.x * 4;
    float4 f = *(const float4*)(xr + c0);
    float s = f.x + f.y + f.z + f.w;
    float ss = f.x * f.x + f.y * f.y + f.z * f.z + f.w * f.w;
#pragma unroll
    for (int o = 16; o > 0; o >>= 1) {
        s  += __shfl_xor_sync(0xffffffffu, s, o);
        ss += __shfl_xor_sync(0xffffffffu, ss, o);
    }
    __shared__ float rs[8], rss[8];
    int wrp = threadIdx.x >> 5, lane = threadIdx.x & 31;
    if (lane == 0) { rs[wrp] = s; rss[wrp] = ss; }
    __syncthreads();
    s = 0.f; ss = 0.f;
#pragma unroll
    for (int qq = 0; qq < 8; qq++) { s += rs[qq]; ss += rss[qq]; }
    float mean = s * (1.0f / Cc);
    float var = ss * (1.0f / Cc) - mean * mean;
    float rstd = rsqrtf(var + 1e-5f);
    float4 wf = *(const float4*)(lnw + c0);
    float4 bf = *(const float4*)(lnb + c0);
    hsm[c0 + 0] = (f.x - mean) * rstd * wf.x + bf.x;
    hsm[c0 + 1] = (f.y - mean) * rstd * wf.y + bf.y;
    hsm[c0 + 2] = (f.z - mean) * rstd * wf.z + bf.z;
    hsm[c0 + 3] = (f.w - mean) * rstd * wf.w + bf.w;
    __syncthreads();
    if (threadIdx.x < Aa) {
        int a = threadIdx.x;
        float acc = 0.f;
        for (int c = 0; c < Cc; c++) acc += hsm[c] * headW[c * Aa + a];
        out[bn * Aa + a] = acc;
    }
}

// ---------------- host launch ----------------
extern "C" void kernel_launch(void* const* d_in, const int* in_sizes, int n_in,
                              void* d_out, int out_size) {
    const float* states     = (const float*)d_in[0];
    const float* actions    = (const float*)d_in[1];
    const int*   timesteps  = (const int*)d_in[2];
    const float* pos_emb    = (const float*)d_in[3];
    const float* gpe        = (const float*)d_in[4];
    const float* seW        = (const float*)d_in[5];
    const float* seb        = (const float*)d_in[6];
    const float* aeW        = (const float*)d_in[7];
    const float* aeb        = (const float*)d_in[8];
    const float* ln1w       = (const float*)d_in[9];
    const float* ln1b       = (const float*)d_in[10];
    const float* Wq         = (const float*)d_in[11];
    const float* bq         = (const float*)d_in[12];
    const float* Wk         = (const float*)d_in[13];
    const float* bk         = (const float*)d_in[14];
    const float* Wv         = (const float*)d_in[15];
    const float* bv         = (const float*)d_in[16];
    const float* Wp         = (const float*)d_in[17];
    const float* bp         = (const float*)d_in[18];
    const float* ln2w       = (const float*)d_in[19];
    const float* ln2b       = (const float*)d_in[20];
    const float* W1         = (const float*)d_in[21];
    const float* b1         = (const float*)d_in[22];
    const float* W2         = (const float*)d_in[23];
    const float* b2         = (const float*)d_in[24];
    const float* lnfw       = (const float*)d_in[25];
    const float* lnfb       = (const float*)d_in[26];
    const float* headW      = (const float*)d_in[27];

    void *p_x, *p_h, *p_qkv, *p_y, *p_mid;
    void *p_wqkv, *p_bqkv, *p_wp, *p_w1, *p_w2;
    void *p_hq126, *p_x126, *p_q126, *p_y126, *p_h126, *p_mid126;
    cudaGetSymbolAddress(&p_x, g_x);       cudaGetSymbolAddress(&p_h, g_h);
    cudaGetSymbolAddress(&p_qkv, g_qkv);   cudaGetSymbolAddress(&p_y, g_y);
    cudaGetSymbolAddress(&p_mid, g_mid);   cudaGetSymbolAddress(&p_wqkv, g_wqkv);
    cudaGetSymbolAddress(&p_bqkv, g_bqkv); cudaGetSymbolAddress(&p_wp, g_wp);
    cudaGetSymbolAddress(&p_w1, g_w1);     cudaGetSymbolAddress(&p_w2, g_w2);
    cudaGetSymbolAddress(&p_hq126, g_hq126); cudaGetSymbolAddress(&p_x126, g_x126);
    cudaGetSymbolAddress(&p_q126, g_q126);   cudaGetSymbolAddress(&p_y126, g_y126);
    cudaGetSymbolAddress(&p_h126, g_h126);   cudaGetSymbolAddress(&p_mid126, g_mid126);

    float*  xbuf = (float*)p_x;
    __half* hbuf = (__half*)p_h;
    __half* qkvb = (__half*)p_qkv;
    __half* ybuf = (__half*)p_y;
    __half* midb = (__half*)p_mid;

    cudaFuncSetAttribute(gemm_mma<1, 0, 0>, cudaFuncAttributeMaxDynamicSharedMemorySize, GEMM_SMEM);
    cudaFuncSetAttribute(gemm_mma<0, 0, 1>, cudaFuncAttributeMaxDynamicSharedMemorySize, GEMM_SMEM);
    cudaFuncSetAttribute(gemm_mma<1, 1, 0>, cudaFuncAttributeMaxDynamicSharedMemorySize, GEMM_SMEM);
    cudaFuncSetAttribute(attn_tc, cudaFuncAttributeMaxDynamicSharedMemorySize, ATT_SMEM);

    // ours#1: all weight transposes + gathers + embed weights + bias concat
    wconv_all<<<WCONV_BLOCKS, 256>>>(Wq, Wk, Wv, Wp, W1, W2,
                                     states, actions, seW, aeW, bq, bk, bv);
    // ours#2: both embed GEMMs (z = parity) with fused assemble
    gemm_embed<<<dim3(Cc / BNt, 8192 / BM, 2), 256>>>(seb, aeb, pos_emb, gpe, timesteps, xbuf);

    for (int l = 0; l < Ll; l++) {
        size_t wo  = (size_t)l * Cc * Cc;
        size_t wq3 = (size_t)l * 3 * Cc * Cc;
        size_t w1o = (size_t)l * Cc * 4 * Cc;
        size_t bo  = (size_t)l * Cc;
        size_t b1o = (size_t)l * 4 * Cc;

        ln_f2h<<<Rr, 256>>>(xbuf, ln1w + bo, ln1b + bo, hbuf);

        if (l < Ll - 1) {
            // full QKV
            gemm_mma<1, 0, 0><<<dim3(3 * Cc / 128, Rr / 128), 128, GEMM_SMEM>>>(
                hbuf, (__half*)p_wqkv + wq3, (float*)p_bqkv + (size_t)l * 3 * Cc,
                nullptr, p_qkv, Rr, 3 * Cc, Cc);

            attn_tc<<<BNn * Hh, 128, ATT_SMEM>>>(qkvb, ybuf);

            gemm_mma<0, 0, 1><<<dim3(Cc / 128, Rr / 128), 128, GEMM_SMEM>>>(
                ybuf, (__half*)p_wp + wo, bp + bo, xbuf, p_x, Rr, Cc, Cc);

            ln_f2h<<<Rr, 256>>>(xbuf, ln2w + bo, ln2b + bo, hbuf);

            gemm_mma<1, 1, 0><<<dim3(4 * Cc / 128, Rr / 128), 128, GEMM_SMEM>>>(
                hbuf, (__half*)p_w1 + w1o, b1 + b1o, nullptr, p_mid, Rr, 4 * Cc, Cc);
            gemm_mma<0, 0, 1><<<dim3(Cc / 128, Rr / 128), 128, GEMM_SMEM>>>(
                midb, (__half*)p_w2 + w1o, b2 + bo, xbuf, p_x, Rr, Cc, 4 * Cc);
        } else {
            // last layer: only row S-2 of each bn feeds the output
            gather126<<<(2 * BNn * Cc) / 256, 256>>>(hbuf, xbuf);

            // k,v for all rows (columns [C, 3C) of qkv)
            gemm_mma<1, 0, 0><<<dim3(2 * Cc / 128, Rr / 128), 128, GEMM_SMEM>>>(
                hbuf, (__half*)p_wqkv + wq3 + (size_t)Cc * Cc,
                (float*)p_bqkv + (size_t)l * 3 * Cc + Cc,
                nullptr, (void*)((__half*)p_qkv + Cc), Rr, 3 * Cc, Cc);
            // q only for the 128 gathered rows
            gemm_mma<1, 0, 0><<<dim3(Cc / 128, 1), 128, GEMM_SMEM>>>(
                (__half*)p_hq126, (__half*)p_wqkv + wq3,
                (float*)p_bqkv + (size_t)l * 3 * Cc,
                nullptr, p_q126, BNn, Cc, Cc);

            attn_last<<<BNn * Hh, 128>>>(qkvb, (__half*)p_q126, (__half*)p_y126);

            // proj + residual (compact, in-place on x126)
            gemm_mma<0, 0, 1><<<dim3(Cc / 128, 1), 128, GEMM_SMEM>>>(
                (__half*)p_y126, (__half*)p_wp + wo, bp + bo,
                (float*)p_x126, p_x126, BNn, Cc, Cc);

            ln_f2h<<<BNn, 256>>>((float*)p_x126, ln2w + bo, ln2b + bo, (__half*)p_h126);

            gemm_mma<1, 1, 0><<<dim3(4 * Cc / 128, 1), 128, GEMM_SMEM>>>(
                (__half*)p_h126, (__half*)p_w1 + w1o, b1 + b1o,
                nullptr, p_mid126, BNn, 4 * Cc, Cc);
            gemm_mma<0, 0, 1><<<dim3(Cc / 128, 1), 128, GEMM_SMEM>>>(
                (__half*)p_mid126, (__half*)p_w2 + w1o, b2 + bo,
                (float*)p_x126, p_x126, BNn, Cc, 4 * Cc);
        }
    }

    head_kernel<<<BNn, 256>>>((float*)p_x126, lnfw, lnfb, headW, (float*)d_out);
}

// round 11
// speedup vs baseline: 1.1579x; 1.0435x over previous
#include <cuda_runtime.h>
#include <cuda_fp16.h>
#include <mma.h>
#include <math.h>
#include <stdint.h>

using namespace nvcuda;

// ---------------- problem dims ----------------
#define Bb 8
#define Tt 64
#define Nn 16
#define DSs 128
#define Aa 32
#define Cc 1024
#define Hh 16
#define Ll 8
#define Ss 128            // 2*T
#define BNn 128           // B*N
#define Rr 16384          // BN*S
#define Dd 64             // head dim
#define QKVW (3 * Cc)     // fused qkv row width

// ---------------- scratch (device globals; no allocation allowed) ----------------
__device__ float   g_x[Rr * Cc];            // residual stream (fp32)
__device__ __half  g_h[Rr * Cc];            // LN output (fp16)
__device__ __half  g_qkv[Rr * 3 * Cc];      // fused q|k|v (fp16)
__device__ __half  g_y[Rr * Cc];
__device__ __half  g_mid[Rr * 4 * Cc];
__device__ __half  g_st[BNn * Tt * DSs];
__device__ __half  g_ac[BNn * Tt * Aa];
__device__ __half  g_wqkv[Ll * 3 * Cc * Cc];   // transposed [3C, C] per layer
__device__ float   g_bqkv[Ll * 3 * Cc];
__device__ __half  g_wp[Ll * Cc * Cc];         // transposed [N,K]
__device__ __half  g_w1[Ll * Cc * 4 * Cc];     // transposed [4C, C]
__device__ __half  g_w2[Ll * 4 * Cc * Cc];     // transposed [C, 4C]
__device__ __half  g_sew[DSs * Cc];            // K-major
__device__ __half  g_aew[Aa * Cc];
// last-layer compact buffers (row 126 of each bn)
__device__ __half  g_hq126[BNn * Cc];
__device__ float   g_x126[BNn * Cc];
__device__ __half  g_q126[BNn * Cc];
__device__ __half  g_y126[BNn * Cc];
__device__ __half  g_h126[BNn * Cc];
__device__ __half  g_mid126[BNn * 4 * Cc];

// ---------------- small helpers ----------------
__device__ __forceinline__ uint32_t smem_to_u32(const void* smem_ptr) {
    uint32_t addr;
    asm("{ .reg .u64 tmp; cvta.to.shared.u64 tmp, %1; cvt.u32.u64 %0, tmp; }"
        : "=r"(addr) : "l"(smem_ptr));
    return addr;
}
__device__ __forceinline__ void cp_async16(uint32_t saddr, const void* gptr) {
    asm volatile("cp.async.cg.shared.global [%0], [%1], 16;" :: "r"(saddr), "l"(gptr));
}
__device__ __forceinline__ void cp_commit() { asm volatile("cp.async.commit_group;" ::: "memory"); }
#define CP_WAIT_GROUP(n) asm volatile("cp.async.wait_group %0;" :: "n"(n) : "memory")

__device__ __forceinline__ uint32_t sw_off(uint32_t off) { return off ^ ((off >> 3) & 0x70u); }

__device__ __forceinline__ void ldmatrix_x4(uint32_t* d, uint32_t addr) {
    asm volatile("ldmatrix.sync.aligned.m8n8.x4.shared.b16 {%0,%1,%2,%3}, [%4];"
                 : "=r"(d[0]), "=r"(d[1]), "=r"(d[2]), "=r"(d[3]) : "r"(addr));
}
__device__ __forceinline__ void mma_16816(float* c, const uint32_t* a, const uint32_t* b) {
    asm volatile("mma.sync.aligned.m16n8k16.row.col.f32.f16.f16.f32 "
                 "{%0,%1,%2,%3}, {%4,%5,%6,%7}, {%8,%9}, {%0,%1,%2,%3};"
                 : "+f"(c[0]), "+f"(c[1]), "+f"(c[2]), "+f"(c[3])
                 : "r"(a[0]), "r"(a[1]), "r"(a[2]), "r"(a[3]), "r"(b[0]), "r"(b[1]));
}

// gelu(x) = 0.5x(1+tanh(z)) = x / (1 + exp(-2z)), exact identity
__device__ __forceinline__ float gelu_f(float x) {
    float x3 = x * x * x;
    float u = __expf(-1.5957691216057308f * (x + 0.044715f * x3));
    return __fdividef(x, 1.0f + u);
}

// ---------------- prep + all weight transposes (ONE kernel) ----------------
#define WCONV_BLOCKS 104160
__global__ void __launch_bounds__(256) wconv_all(const float* __restrict__ Wq,
                                                 const float* __restrict__ Wk,
                                                 const float* __restrict__ Wv,
                                                 const float* __restrict__ Wp,
                                                 const float* __restrict__ W1,
                                                 const float* __restrict__ W2,
                                                 const float* __restrict__ states,
                                                 const float* __restrict__ actions,
                                                 const float* __restrict__ seW,
                                                 const float* __restrict__ aeW,
                                                 const float* __restrict__ bq,
                                                 const float* __restrict__ bk,
                                                 const float* __restrict__ bv) {
    __shared__ float tile[32][33];
    int bid = blockIdx.x;
    if (bid >= 98304) {
        int i = (bid - 98304) * 256 + threadIdx.x;
        if (i < 1048576) {
            int ds = i % DSs;
            int row = i / DSs;
            int t = row % Tt;
            int bn = row / Tt;
            int b = bn / Nn, n = bn % Nn;
            g_st[i] = __float2half(states[(((size_t)b * Tt + t) * Nn + n) * DSs + ds]);
        } else if (i < 1310720) {
            int j = i - 1048576;
            int a = j % Aa;
            int row = j / Aa;
            int t = row % Tt;
            int bn = row / Tt;
            int b = bn / Nn, n = bn % Nn;
            g_ac[j] = __float2half(actions[(((size_t)b * Tt + t) * Nn + n) * Aa + a]);
        } else if (i < 1441792) {
            int j = i - 1310720;
            g_sew[j] = __float2half(seW[j]);
        } else if (i < 1474560) {
            int j = i - 1441792;
            g_aew[j] = __float2half(aeW[j]);
        } else {
            int j = i - 1474560;            // < Ll*3*Cc
            int l = j / (3 * Cc);
            int k = j - l * 3 * Cc;
            float v = (k < Cc) ? bq[l * Cc + k]
                    : (k < 2 * Cc) ? bk[l * Cc + k - Cc]
                                   : bv[l * Cc + k - 2 * Cc];
            g_bqkv[j] = v;
        }
        return;
    }
    const float* src;
    __half* dst;
    int K, N, bx, by;
    if (bid < 24576) {
        int which = bid >> 13;
        int r = bid & 8191;
        int layer = r >> 10;
        int rt = r & 1023;
        bx = rt & 31; by = rt >> 5; K = Cc; N = Cc;
        src = (which == 0 ? Wq : which == 1 ? Wk : Wv) + (size_t)layer * Cc * Cc;
        dst = g_wqkv + (size_t)layer * 3 * Cc * Cc + (size_t)which * Cc * Cc;
    } else if (bid < 32768) {
        int r = bid - 24576;
        int layer = r >> 10;
        int rt = r & 1023;
        bx = rt & 31; by = rt >> 5; K = Cc; N = Cc;
        src = Wp + (size_t)layer * Cc * Cc;
        dst = g_wp + (size_t)layer * Cc * Cc;
    } else if (bid < 65536) {
        int r = bid - 32768;
        int layer = r >> 12;
        int rt = r & 4095;
        bx = rt & 127; by = rt >> 7; K = Cc; N = 4 * Cc;
        src = W1 + (size_t)layer * Cc * 4 * Cc;
        dst = g_w1 + (size_t)layer * Cc * 4 * Cc;
    } else {
        int r = bid - 65536;
        int layer = r >> 12;
        int rt = r & 4095;
        bx = rt & 31; by = rt >> 5; K = 4 * Cc; N = Cc;
        src = W2 + (size_t)layer * 4 * Cc * Cc;
        dst = g_w2 + (size_t)layer * 4 * Cc * Cc;
    }
    int nb = bx * 32, kb = by * 32;
    int tx = threadIdx.x & 31, ty = threadIdx.x >> 5;  // 32 x 8
#pragma unroll
    for (int r = 0; r < 32; r += 8)
        tile[ty + r][tx] = src[(size_t)(kb + ty + r) * N + nb + tx];
    __syncthreads();
#pragma unroll
    for (int r = 0; r < 32; r += 8)
        dst[(size_t)(nb + ty + r) * K + kb + tx] = __float2half(tile[tx][ty + r]);
}

// ---------------- embed GEMM (wmma) with fused assemble epilogue; z=0 state, z=1 action ----------------
#define BM 128
#define BNt 128
#define BKt 32
#define APAD 8
#define BPAD 8
#define AS_BYTES (2 * BM * (BKt + APAD) * 2)
#define BS_BYTES (2 * BKt * (BNt + BPAD) * 2)

__global__ void __launch_bounds__(256) gemm_embed(const float* __restrict__ bias_s,
                                                  const float* __restrict__ bias_a,
                                                  const float* __restrict__ pe,
                                                  const float* __restrict__ gpe,
                                                  const int* __restrict__ ts,
                                                  float* __restrict__ xout) {
    __shared__ __align__(16) unsigned char sraw[AS_BYTES + BS_BYTES];
    typedef __half (*AsT)[BM][BKt + APAD];
    typedef __half (*BsT)[BKt][BNt + BPAD];
    AsT As = reinterpret_cast<AsT>(sraw);
    BsT Bs = reinterpret_cast<BsT>(sraw + AS_BYTES);

    int parity = blockIdx.z;
    const __half* A  = parity ? g_ac : g_st;
    const __half* Bm = parity ? g_aew : g_sew;
    const float* bias = parity ? bias_a : bias_s;
    int K = parity ? Aa : DSs;
    int N = Cc;

    int tid = threadIdx.x;
    int wid = tid >> 5;
    int wm = wid >> 2;
    int wn = wid & 3;
    int mBase = blockIdx.y * BM;
    int nBase = blockIdx.x * BNt;

    wmma::fragment<wmma::accumulator, 16, 16, 16, float> cf[4][2];
#pragma unroll
    for (int i = 0; i < 4; i++)
#pragma unroll
        for (int j = 0; j < 2; j++) wmma::fill_fragment(cf[i][j], 0.0f);

    int a_row[2], a_col[2], b_row[2], b_col[2];
#pragma unroll
    for (int u = 0; u < 2; u++) {
        int idx = tid + u * 256;
        a_row[u] = idx >> 2;
        a_col[u] = (idx & 3) * 8;
        b_row[u] = idx >> 4;
        b_col[u] = (idx & 15) * 8;
    }

    int ktiles = K / BKt;
    uint4 ra[2], rb[2];
#pragma unroll
    for (int u = 0; u < 2; u++) {
        ra[u] = (a_col[u] < K) ? *(const uint4*)(A + (size_t)(mBase + a_row[u]) * K + a_col[u])
                               : make_uint4(0, 0, 0, 0);
        rb[u] = *(const uint4*)(Bm + (size_t)b_row[u] * N + nBase + b_col[u]);
    }
#pragma unroll
    for (int u = 0; u < 2; u++) {
        if (a_col[u] < BKt) *(uint4*)&As[0][a_row[u]][a_col[u]] = ra[u];
        *(uint4*)&Bs[0][b_row[u]][b_col[u]] = rb[u];
    }
    __syncthreads();

    for (int kt = 0; kt < ktiles; kt++) {
        int cur = kt & 1, nxt = cur ^ 1;
        if (kt + 1 < ktiles) {
            int k0 = (kt + 1) * BKt;
#pragma unroll
            for (int u = 0; u < 2; u++) {
                ra[u] = *(const uint4*)(A + (size_t)(mBase + a_row[u]) * K + k0 + a_col[u]);
                rb[u] = *(const uint4*)(Bm + (size_t)(k0 + b_row[u]) * N + nBase + b_col[u]);
            }
        }
#pragma unroll
        for (int kk = 0; kk < BKt; kk += 16) {
            wmma::fragment<wmma::matrix_a, 16, 16, 16, __half, wmma::row_major> af[4];
            wmma::fragment<wmma::matrix_b, 16, 16, 16, __half, wmma::row_major> bf[2];
#pragma unroll
            for (int i = 0; i < 4; i++)
                wmma::load_matrix_sync(af[i], &As[cur][wm * 64 + i * 16][kk], BKt + APAD);
#pragma unroll
            for (int j = 0; j < 2; j++)
                wmma::load_matrix_sync(bf[j], &Bs[cur][kk][wn * 32 + j * 16], BNt + BPAD);
#pragma unroll
            for (int i = 0; i < 4; i++)
#pragma unroll
                for (int j = 0; j < 2; j++)
                    wmma::mma_sync(cf[i][j], af[i], bf[j], cf[i][j]);
        }
        if (kt + 1 < ktiles) {
            __syncthreads();
#pragma unroll
            for (int u = 0; u < 2; u++) {
                *(uint4*)&As[nxt][a_row[u]][a_col[u]] = ra[u];
                *(uint4*)&Bs[nxt][b_row[u]][b_col[u]] = rb[u];
            }
            __syncthreads();
        }
    }

    __syncthreads();
    float* Epi = reinterpret_cast<float*>(sraw);
#pragma unroll 1
    for (int p = 0; p < 2; p++) {
        if (wm == p) {
#pragma unroll
            for (int i = 0; i < 4; i++)
#pragma unroll
                for (int j = 0; j < 2; j++)
                    wmma::store_matrix_sync(&Epi[(i * 16) * 132 + wn * 32 + j * 16],
                                            cf[i][j], 132, wmma::mem_row_major);
        }
        __syncthreads();
#pragma unroll
        for (int it = 0; it < 8; it++) {
            int idx = tid + it * 256;
            int r = idx >> 5;
            int c4 = (idx & 31) * 4;
            int grow = mBase + p * 64 + r;
            int gcol = nBase + c4;
            float4 vv = *(float4*)&Epi[r * 132 + c4];
            int bn2 = grow >> 6, t = grow & 63, b = bn2 >> 4;
            int s2 = 2 * t + parity;
            int tsv = ts[b * Tt + t];
            const float4 pef = *(const float4*)(pe + (size_t)s2 * Cc + gcol);
            const float4 gf  = *(const float4*)(gpe + (size_t)tsv * Cc + gcol);
            float* Cp = xout + ((size_t)bn2 * Ss + s2) * Cc + gcol;
            *(float4*)Cp = make_float4(vv.x + bias[gcol + 0] + pef.x + gf.x,
                                       vv.y + bias[gcol + 1] + pef.y + gf.y,
                                       vv.z + bias[gcol + 2] + pef.z + gf.z,
                                       vv.w + bias[gcol + 3] + pef.w + gf.w);
        }
        __syncthreads();
    }
}

// ---------------- LayerNorm fp32 -> fp16 ----------------
__global__ void __launch_bounds__(256) ln_f2h(const float* __restrict__ x,
                                              const float* __restrict__ w,
                                              const float* __restrict__ bb,
                                              __half* __restrict__ out) {
    int row = blockIdx.x;
    const float* xr = x + (size_t)row * Cc;
    int c0 = threadIdx.x * 4;
    float4 f = *(const float4*)(xr + c0);
    float s = f.x + f.y + f.z + f.w;
    float ss = f.x * f.x + f.y * f.y + f.z * f.z + f.w * f.w;
#pragma unroll
    for (int o = 16; o > 0; o >>= 1) {
        s  += __shfl_xor_sync(0xffffffffu, s, o);
        ss += __shfl_xor_sync(0xffffffffu, ss, o);
    }
    __shared__ float rs[8], rss[8];
    int wrp = threadIdx.x >> 5, lane = threadIdx.x & 31;
    if (lane == 0) { rs[wrp] = s; rss[wrp] = ss; }
    __syncthreads();
    s = 0.f; ss = 0.f;
#pragma unroll
    for (int qq = 0; qq < 8; qq++) { s += rs[qq]; ss += rss[qq]; }
    float mean = s * (1.0f / Cc);
    float var = ss * (1.0f / Cc) - mean * mean;
    float rstd = rsqrtf(var + 1e-5f);
    float4 wf = *(const float4*)(w + c0);
    float4 bf = *(const float4*)(bb + c0);
    float o0 = (f.x - mean) * rstd * wf.x + bf.x;
    float o1 = (f.y - mean) * rstd * wf.y + bf.y;
    float o2 = (f.z - mean) * rstd * wf.z + bf.z;
    float o3 = (f.w - mean) * rstd * wf.w + bf.w;
    *(__half2*)(out + (size_t)row * Cc + c0)     = __floats2half2_rn(o0, o1);
    *(__half2*)(out + (size_t)row * Cc + c0 + 2) = __floats2half2_rn(o2, o3);
}

// ---------------- gather row 126 of each bn: h (fp16) and x (fp32) ----------------
__global__ void gather126(const __half* __restrict__ h, const float* __restrict__ x) {
    int i = blockIdx.x * 256 + threadIdx.x;       // < 2*131072
    if (i < BNn * Cc) {
        int bn = i >> 10, c = i & (Cc - 1);
        g_hq126[i] = h[((size_t)bn * Ss + (Ss - 2)) * Cc + c];
    } else {
        int j = i - BNn * Cc;
        int bn = j >> 10, c = j & (Cc - 1);
        g_x126[j] = x[((size_t)bn * Ss + (Ss - 2)) * Cc + c];
    }
}

// ---------------- HMMA GEMM: MT x 128 CTA tile, 4 warps (MT/2 x 64 each), 3-stage cp.async ----------------
// Templated on M-tile (128 or 64) and K (compile-time unroll).
#define GBK 64
#define GSTG 3

template <int OUTHALF, int DOGELU, int DORES, int MT, int KDIM>
__global__ void __launch_bounds__(128, 2) gemm_mma(const __half* __restrict__ A,
                                                   const __half* __restrict__ Bt,
                                                   const float* __restrict__ bias,
                                                   const float* __restrict__ res,
                                                   void* __restrict__ Cout,
                                                   int N) {
    constexpr int MI = MT / 32;                    // 4 or 2
    constexpr int STAGE_B = (MT + 128) * 128;      // bytes per stage
    constexpr int ACH = MT * 8;                    // A chunks per stage
    constexpr int TOTCH = ACH + 1024;              // total 16B chunks
    constexpr int JN = TOTCH / 128;
    constexpr int KT = KDIM / GBK;

    extern __shared__ unsigned char gsm[];
    uint32_t sbase = smem_to_u32(gsm);
    const int tid = threadIdx.x;
    const int wid = tid >> 5;
    const int lane = tid & 31;
    const int wm = wid & 1;
    const int wn = wid >> 1;
    const int mBase = blockIdx.y * MT;
    const int nBase = blockIdx.x * 128;

    float acc[MI][8][4];
#pragma unroll
    for (int i = 0; i < MI; i++)
#pragma unroll
        for (int j = 0; j < 8; j++)
#pragma unroll
            for (int r = 0; r < 4; r++) acc[i][j][r] = 0.f;

    auto load_stage = [&](int kt) {
        int k0 = kt * GBK;
        uint32_t ab = sbase + (uint32_t)(kt % GSTG) * STAGE_B;
        uint32_t bb = ab + (uint32_t)(MT * 128);
#pragma unroll
        for (int j = 0; j < JN; j++) {
            int id = tid + j * 128;
            if (id < ACH) {
                int row = id >> 3;
                int c16 = id & 7;
                uint32_t sw = sw_off((uint32_t)(row * 128 + c16 * 16));
                cp_async16(ab + sw, A + (size_t)(mBase + row) * KDIM + k0 + c16 * 8);
            } else {
                int idx = id - ACH;
                int row = idx >> 3;
                int c16 = idx & 7;
                uint32_t sw = sw_off((uint32_t)(row * 128 + c16 * 16));
                cp_async16(bb + sw, Bt + (size_t)(nBase + row) * KDIM + k0 + c16 * 8);
            }
        }
    };

    load_stage(0); cp_commit();
    load_stage(1); cp_commit();

#pragma unroll 2
    for (int kt = 0; kt < KT; kt++) {
        CP_WAIT_GROUP(1);
        __syncthreads();
        if (kt + 2 < KT) load_stage(kt + 2);
        cp_commit();

        uint32_t ab = sbase + (uint32_t)(kt % GSTG) * STAGE_B;
        uint32_t bb = ab + (uint32_t)(MT * 128);
#pragma unroll
        for (int ks = 0; ks < 4; ks++) {
            uint32_t a_r[MI][4];
            uint32_t b_r[8][2];
#pragma unroll
            for (int mi = 0; mi < MI; mi++) {
                int row = wm * (MT / 2) + mi * 16 + (lane & 15);
                int kc = ks * 2 + (lane >> 4);
                ldmatrix_x4(a_r[mi], ab + sw_off((uint32_t)(row * 128 + kc * 16)));
            }
#pragma unroll
            for (int bj = 0; bj < 4; bj++) {
                int nrow = wn * 64 + bj * 16 + (lane & 7) + ((lane >> 4) & 1) * 8;
                int kc = ks * 2 + ((lane >> 3) & 1);
                uint32_t r[4];
                ldmatrix_x4(r, bb + sw_off((uint32_t)(nrow * 128 + kc * 16)));
                b_r[bj * 2 + 0][0] = r[0]; b_r[bj * 2 + 0][1] = r[1];
                b_r[bj * 2 + 1][0] = r[2]; b_r[bj * 2 + 1][1] = r[3];
            }
#pragma unroll
            for (int mi = 0; mi < MI; mi++)
#pragma unroll
                for (int ni = 0; ni < 8; ni++)
                    mma_16816(acc[mi][ni], a_r[mi], b_r[ni]);
        }
    }

#pragma unroll
    for (int mi = 0; mi < MI; mi++) {
#pragma unroll
        for (int ni = 0; ni < 8; ni++) {
            int r0 = mBase + wm * (MT / 2) + mi * 16 + (lane >> 2);
            int c0 = nBase + wn * 64 + ni * 8 + 2 * (lane & 3);
            float b0 = bias[c0], b1 = bias[c0 + 1];
#pragma unroll
            for (int half_ = 0; half_ < 2; half_++) {
                int row = r0 + half_ * 8;
                float o0 = acc[mi][ni][half_ * 2 + 0] + b0;
                float o1 = acc[mi][ni][half_ * 2 + 1] + b1;
                if (DOGELU) { o0 = gelu_f(o0); o1 = gelu_f(o1); }
                if (DORES) {
                    const float* rp = res + (size_t)row * N + c0;
                    o0 += rp[0]; o1 += rp[1];
                }
                if (OUTHALF) {
                    *(__half2*)((__half*)Cout + (size_t)row * N + c0) = __floats2half2_rn(o0, o1);
                } else {
                    *(float2*)((float*)Cout + (size_t)row * N + c0) = make_float2(o0, o1);
                }
            }
        }
    }
}

#define SMEM_MT128 (GSTG * (128 + 128) * 128)   // 98304
#define SMEM_MT64  (GSTG * (64 + 128) * 128)    // 73728

// ---------------- tensor-core attention: block per (bn, head), 4 warps ----------------
#define ATT_SMEM 81920

__global__ void __launch_bounds__(128) attn_tc(const __half* __restrict__ qkv,
                                               __half* __restrict__ y) {
    extern __shared__ unsigned char asm_[];
    uint32_t sb = smem_to_u32(asm_);
    uint32_t sK = sb, sQ = sb + 16384, sV0 = sb + 32768, sV1 = sb + 40960;
    int tid = threadIdx.x, wid = tid >> 5, lane = tid & 31;
    uint32_t sP0 = sb + 49152 + wid * 8192;
    uint32_t sP1 = sP0 + 4096;
    char* pch0 = (char*)asm_ + 49152 + wid * 8192;
    char* pch1 = pch0 + 4096;
    int bh = blockIdx.x, bn = bh >> 4, h = bh & 15;
    size_t baseq = (size_t)bn * Ss * QKVW + h * Dd;
    size_t basey = (size_t)bn * Ss * Cc + h * Dd;

    for (int idx = tid; idx < 1024; idx += 128) {
        int row = idx >> 3, c = idx & 7;
        uint32_t sw = sw_off((uint32_t)(row * 128 + c * 16));
        cp_async16(sQ + sw, qkv + baseq + (size_t)row * QKVW + c * 8);
        cp_async16(sK + sw, qkv + baseq + Cc + (size_t)row * QKVW + c * 8);
    }
    cp_commit();
    for (int idx = tid; idx < 4096; idx += 128) {
        int kv = idx >> 5, d2 = idx & 31;
        __half2 v2 = *(const __half2*)(qkv + baseq + 2 * Cc + (size_t)kv * QKVW + d2 * 2);
        char* vbp = (char*)asm_ + ((kv < 64) ? 32768 : 40960);
        int kc = kv & 63;
        *(__half*)(vbp + sw_off((uint32_t)((d2 * 2) * 128 + kc * 2)))     = __low2half(v2);
        *(__half*)(vbp + sw_off((uint32_t)((d2 * 2 + 1) * 128 + kc * 2))) = __high2half(v2);
    }
    CP_WAIT_GROUP(0);
    __syncthreads();

    int qb = wid * 32;
    float accS[2][16][4];
#pragma unroll
    for (int mi = 0; mi < 2; mi++)
#pragma unroll
        for (int ni = 0; ni < 16; ni++)
#pragma unroll
            for (int r = 0; r < 4; r++) accS[mi][ni][r] = 0.f;

#pragma unroll
    for (int ks = 0; ks < 4; ks++) {
        uint32_t a[2][4], b[16][2];
#pragma unroll
        for (int mi = 0; mi < 2; mi++) {
            int row = qb + mi * 16 + (lane & 15);
            int kc = ks * 2 + (lane >> 4);
            ldmatrix_x4(a[mi], sQ + sw_off((uint32_t)(row * 128 + kc * 16)));
        }
#pragma unroll
        for (int bj = 0; bj < 8; bj++) {
            int nrow = bj * 16 + (lane & 7) + ((lane >> 4) & 1) * 8;
            int kc = ks * 2 + ((lane >> 3) & 1);
            uint32_t r[4];
            ldmatrix_x4(r, sK + sw_off((uint32_t)(nrow * 128 + kc * 16)));
            b[bj * 2 + 0][0] = r[0]; b[bj * 2 + 0][1] = r[1];
            b[bj * 2 + 1][0] = r[2]; b[bj * 2 + 1][1] = r[3];
        }
#pragma unroll
        for (int mi = 0; mi < 2; mi++)
#pragma unroll
            for (int ni = 0; ni < 16; ni++)
                mma_16816(accS[mi][ni], a[mi], b[ni]);
    }

    float inv[2][2];
#pragma unroll
    for (int mi = 0; mi < 2; mi++) {
        float s0 = 0.f, s1 = 0.f;
        int rA = qb + mi * 16 + (lane >> 2);
        int rB = rA + 8;
        int rl = mi * 16 + (lane >> 2);
#pragma unroll
        for (int ni = 0; ni < 16; ni++) {
            int c0 = ni * 8 + 2 * (lane & 3);
            float p00 = (c0     <= rA) ? __expf(accS[mi][ni][0] * 0.125f) : 0.f;
            float p01 = (c0 + 1 <= rA) ? __expf(accS[mi][ni][1] * 0.125f) : 0.f;
            float p10 = (c0     <= rB) ? __expf(accS[mi][ni][2] * 0.125f) : 0.f;
            float p11 = (c0 + 1 <= rB) ? __expf(accS[mi][ni][3] * 0.125f) : 0.f;
            s0 += p00 + p01; s1 += p10 + p11;
            char* pp = (c0 < 64) ? pch0 : pch1;
            int cl = c0 & 63;
            *(__half2*)(pp + sw_off((uint32_t)(rl * 128 + cl * 2)))       = __floats2half2_rn(p00, p01);
            *(__half2*)(pp + sw_off((uint32_t)((rl + 8) * 128 + cl * 2))) = __floats2half2_rn(p10, p11);
        }
        s0 += __shfl_xor_sync(0xffffffffu, s0, 1);
        s0 += __shfl_xor_sync(0xffffffffu, s0, 2);
        s1 += __shfl_xor_sync(0xffffffffu, s1, 1);
        s1 += __shfl_xor_sync(0xffffffffu, s1, 2);
        inv[mi][0] = 1.0f / s0;
        inv[mi][1] = 1.0f / s1;
    }
    __syncwarp();

    float accO[2][8][4];
#pragma unroll
    for (int mi = 0; mi < 2; mi++)
#pragma unroll
        for (int ni = 0; ni < 8; ni++)
#pragma unroll
            for (int r = 0; r < 4; r++) accO[mi][ni][r] = 0.f;

#pragma unroll
    for (int ks = 0; ks < 8; ks++) {
        uint32_t pbase = (ks < 4) ? sP0 : sP1;
        uint32_t vbase = (ks < 4) ? sV0 : sV1;
        int kss = ks & 3;
        uint32_t a[2][4], b[8][2];
#pragma unroll
        for (int mi = 0; mi < 2; mi++) {
            int row = mi * 16 + (lane & 15);
            int kc = kss * 2 + (lane >> 4);
            ldmatrix_x4(a[mi], pbase + sw_off((uint32_t)(row * 128 + kc * 16)));
        }
#pragma unroll
        for (int bj = 0; bj < 4; bj++) {
            int nrow = bj * 16 + (lane & 7) + ((lane >> 4) & 1) * 8;
            int kc = kss * 2 + ((lane >> 3) & 1);
            uint32_t r[4];
            ldmatrix_x4(r, vbase + sw_off((uint32_t)(nrow * 128 + kc * 16)));
            b[bj * 2 + 0][0] = r[0]; b[bj * 2 + 0][1] = r[1];
            b[bj * 2 + 1][0] = r[2]; b[bj * 2 + 1][1] = r[3];
        }
#pragma unroll
        for (int mi = 0; mi < 2; mi++)
#pragma unroll
            for (int ni = 0; ni < 8; ni++)
                mma_16816(accO[mi][ni], a[mi], b[ni]);
    }

#pragma unroll
    for (int mi = 0; mi < 2; mi++) {
#pragma unroll
        for (int ni = 0; ni < 8; ni++) {
            int rA = qb + mi * 16 + (lane >> 2);
            int c0 = ni * 8 + 2 * (lane & 3);
            *(__half2*)(y + basey + (size_t)rA * Cc + c0) =
                __floats2half2_rn(accO[mi][ni][0] * inv[mi][0], accO[mi][ni][1] * inv[mi][0]);
            *(__half2*)(y + basey + (size_t)(rA + 8) * Cc + c0) =
                __floats2half2_rn(accO[mi][ni][2] * inv[mi][1], accO[mi][ni][3] * inv[mi][1]);
        }
    }
}

// ---------------- last-layer single-query attention: block per (bn,h) ----------------
__global__ void __launch_bounds__(128) attn_last(const __half* __restrict__ qkv,
                                                 const __half* __restrict__ q126,
                                                 __half* __restrict__ y126) {
    __shared__ float qs[Dd];
    __shared__ float e[Ss];
    __shared__ float ws[4];
    int tid = threadIdx.x, wid = tid >> 5, lane = tid & 31;
    int bh = blockIdx.x, bn = bh >> 4, h = bh & 15;
    size_t base = (size_t)bn * Ss * QKVW + h * Dd;

    if (tid < 32) {
        float2 f = __half22float2(*(const __half2*)(q126 + (size_t)bn * Cc + h * Dd + tid * 2));
        qs[tid * 2] = f.x; qs[tid * 2 + 1] = f.y;
    }
    __syncthreads();

    int j = tid;
    float ej = 0.f;
    if (j <= Ss - 2) {
        const __half* kr = qkv + base + Cc + (size_t)j * QKVW;
        float s = 0.f;
#pragma unroll
        for (int i = 0; i < Dd; i++) s += qs[i] * __half2float(kr[i]);
        ej = __expf(s * 0.125f);
    }
    e[j] = ej;
    float s = ej;
#pragma unroll
    for (int o = 16; o > 0; o >>= 1) s += __shfl_xor_sync(0xffffffffu, s, o);
    if (lane == 0) ws[wid] = s;
    __syncthreads();
    float sum = ws[0] + ws[1] + ws[2] + ws[3];

    if (tid < Dd) {
        float acc = 0.f;
        for (int k = 0; k <= Ss - 2; k++)
            acc += e[k] * __half2float(qkv[base + 2 * Cc + (size_t)k * QKVW + tid]);
        y126[(size_t)bn * Cc + h * Dd + tid] = __float2half(acc / sum);
    }
}

// ---------------- final LN + head (compact x126 input) ----------------
__global__ void __launch_bounds__(256) head_kernel(const float* __restrict__ x,
                                                   const float* __restrict__ lnw,
                                                   const float* __restrict__ lnb,
                                                   const float* __restrict__ headW,
                                                   float* __restrict__ out) {
    int bn = blockIdx.x;
    const float* xr = x + (size_t)bn * Cc;
    __shared__ float hsm[Cc];
    int c0 = threadIdx.x * 4;
    float4 f = *(const float4*)(xr + c0);
    float s = f.x + f.y + f.z + f.w;
    float ss = f.x * f.x + f.y * f.y + f.z * f.z + f.w * f.w;
#pragma unroll
    for (int o = 16; o > 0; o >>= 1) {
        s  += __shfl_xor_sync(0xffffffffu, s, o);
        ss += __shfl_xor_sync(0xffffffffu, ss, o);
    }
    __shared__ float rs[8], rss[8];
    int wrp = threadIdx.x >> 5, lane = threadIdx.x & 31;
    if (lane == 0) { rs[wrp] = s; rss[wrp] = ss; }
    __syncthreads();
    s = 0.f; ss = 0.f;
#pragma unroll
    for (int qq = 0; qq < 8; qq++) { s += rs[qq]; ss += rss[qq]; }
    float mean = s * (1.0f / Cc);
    float var = ss * (1.0f / Cc) - mean * mean;
    float rstd = rsqrtf(var + 1e-5f);
    float4 wf = *(const float4*)(lnw + c0);
    float4 bf = *(const float4*)(lnb + c0);
    hsm[c0 + 0] = (f.x - mean) * rstd * wf.x + bf.x;
    hsm[c0 + 1] = (f.y - mean) * rstd * wf.y + bf.y;
    hsm[c0 + 2] = (f.z - mean) * rstd * wf.z + bf.z;
    hsm[c0 + 3] = (f.w - mean) * rstd * wf.w + bf.w;
    __syncthreads();
    if (threadIdx.x < Aa) {
        int a = threadIdx.x;
        float acc = 0.f;
        for (int c = 0; c < Cc; c++) acc += hsm[c] * headW[c * Aa + a];
        out[bn * Aa + a] = acc;
    }
}

// ---------------- host launch ----------------
extern "C" void kernel_launch(void* const* d_in, const int* in_sizes, int n_in,
                              void* d_out, int out_size) {
    const float* states     = (const float*)d_in[0];
    const float* actions    = (const float*)d_in[1];
    const int*   timesteps  = (const int*)d_in[2];
    const float* pos_emb    = (const float*)d_in[3];
    const float* gpe        = (const float*)d_in[4];
    const float* seW        = (const float*)d_in[5];
    const float* seb        = (const float*)d_in[6];
    const float* aeW        = (const float*)d_in[7];
    const float* aeb        = (const float*)d_in[8];
    const float* ln1w       = (const float*)d_in[9];
    const float* ln1b       = (const float*)d_in[10];
    const float* Wq         = (const float*)d_in[11];
    const float* bq         = (const float*)d_in[12];
    const float* Wk         = (const float*)d_in[13];
    const float* bk         = (const float*)d_in[14];
    const float* Wv         = (const float*)d_in[15];
    const float* bv         = (const float*)d_in[16];
    const float* Wp         = (const float*)d_in[17];
    const float* bp         = (const float*)d_in[18];
    const float* ln2w       = (const float*)d_in[19];
    const float* ln2b       = (const float*)d_in[20];
    const float* W1         = (const float*)d_in[21];
    const float* b1         = (const float*)d_in[22];
    const float* W2         = (const float*)d_in[23];
    const float* b2         = (const float*)d_in[24];
    const float* lnfw       = (const float*)d_in[25];
    const float* lnfb       = (const float*)d_in[26];
    const float* headW      = (const float*)d_in[27];

    void *p_x, *p_h, *p_qkv, *p_y, *p_mid;
    void *p_wqkv, *p_bqkv, *p_wp, *p_w1, *p_w2;
    void *p_hq126, *p_x126, *p_q126, *p_y126, *p_h126, *p_mid126;
    cudaGetSymbolAddress(&p_x, g_x);       cudaGetSymbolAddress(&p_h, g_h);
    cudaGetSymbolAddress(&p_qkv, g_qkv);   cudaGetSymbolAddress(&p_y, g_y);
    cudaGetSymbolAddress(&p_mid, g_mid);   cudaGetSymbolAddress(&p_wqkv, g_wqkv);
    cudaGetSymbolAddress(&p_bqkv, g_bqkv); cudaGetSymbolAddress(&p_wp, g_wp);
    cudaGetSymbolAddress(&p_w1, g_w1);     cudaGetSymbolAddress(&p_w2, g_w2);
    cudaGetSymbolAddress(&p_hq126, g_hq126); cudaGetSymbolAddress(&p_x126, g_x126);
    cudaGetSymbolAddress(&p_q126, g_q126);   cudaGetSymbolAddress(&p_y126, g_y126);
    cudaGetSymbolAddress(&p_h126, g_h126);   cudaGetSymbolAddress(&p_mid126, g_mid126);

    float*  xbuf = (float*)p_x;
    __half* hbuf = (__half*)p_h;
    __half* qkvb = (__half*)p_qkv;
    __half* ybuf = (__half*)p_y;
    __half* midb = (__half*)p_mid;

    cudaFuncSetAttribute((gemm_mma<1, 0, 0, 128, Cc>), cudaFuncAttributeMaxDynamicSharedMemorySize, SMEM_MT128);
    cudaFuncSetAttribute((gemm_mma<1, 1, 0, 128, Cc>), cudaFuncAttributeMaxDynamicSharedMemorySize, SMEM_MT128);
    cudaFuncSetAttribute((gemm_mma<0, 0, 1, 64, Cc>),  cudaFuncAttributeMaxDynamicSharedMemorySize, SMEM_MT64);
    cudaFuncSetAttribute((gemm_mma<0, 0, 1, 64, 4 * Cc>), cudaFuncAttributeMaxDynamicSharedMemorySize, SMEM_MT64);
    cudaFuncSetAttribute(attn_tc, cudaFuncAttributeMaxDynamicSharedMemorySize, ATT_SMEM);

    // ours#1: all weight transposes + gathers + embed weights + bias concat
    wconv_all<<<WCONV_BLOCKS, 256>>>(Wq, Wk, Wv, Wp, W1, W2,
                                     states, actions, seW, aeW, bq, bk, bv);
    // ours#2: both embed GEMMs (z = parity) with fused assemble
    gemm_embed<<<dim3(Cc / BNt, 8192 / BM, 2), 256>>>(seb, aeb, pos_emb, gpe, timesteps, xbuf);

    for (int l = 0; l < Ll; l++) {
        size_t wo  = (size_t)l * Cc * Cc;
        size_t wq3 = (size_t)l * 3 * Cc * Cc;
        size_t w1o = (size_t)l * Cc * 4 * Cc;
        size_t bo  = (size_t)l * Cc;
        size_t b1o = (size_t)l * 4 * Cc;

        ln_f2h<<<Rr, 256>>>(xbuf, ln1w + bo, ln1b + bo, hbuf);

        if (l < Ll - 1) {
            // full QKV
            gemm_mma<1, 0, 0, 128, Cc><<<dim3(3 * Cc / 128, Rr / 128), 128, SMEM_MT128>>>(
                hbuf, (__half*)p_wqkv + wq3, (float*)p_bqkv + (size_t)l * 3 * Cc,
                nullptr, p_qkv, 3 * Cc);

            attn_tc<<<BNn * Hh, 128, ATT_SMEM>>>(qkvb, ybuf);

            gemm_mma<0, 0, 1, 64, Cc><<<dim3(Cc / 128, Rr / 64), 128, SMEM_MT64>>>(
                ybuf, (__half*)p_wp + wo, bp + bo, xbuf, p_x, Cc);

            ln_f2h<<<Rr, 256>>>(xbuf, ln2w + bo, ln2b + bo, hbuf);

            gemm_mma<1, 1, 0, 128, Cc><<<dim3(4 * Cc / 128, Rr / 128), 128, SMEM_MT128>>>(
                hbuf, (__half*)p_w1 + w1o, b1 + b1o, nullptr, p_mid, 4 * Cc);
            gemm_mma<0, 0, 1, 64, 4 * Cc><<<dim3(Cc / 128, Rr / 64), 128, SMEM_MT64>>>(
                midb, (__half*)p_w2 + w1o, b2 + bo, xbuf, p_x, Cc);
        } else {
            // last layer: only row S-2 of each bn feeds the output
            gather126<<<(2 * BNn * Cc) / 256, 256>>>(hbuf, xbuf);

            // k,v for all rows (columns [C, 3C) of qkv)
            gemm_mma<1, 0, 0, 128, Cc><<<dim3(2 * Cc / 128, Rr / 128), 128, SMEM_MT128>>>(
                hbuf, (__half*)p_wqkv + wq3 + (size_t)Cc * Cc,
                (float*)p_bqkv + (size_t)l * 3 * Cc + Cc,
                nullptr, (void*)((__half*)p_qkv + Cc), 3 * Cc);
            // q only for the 128 gathered rows
            gemm_mma<1, 0, 0, 128, Cc><<<dim3(Cc / 128, 1), 128, SMEM_MT128>>>(
                (__half*)p_hq126, (__half*)p_wqkv + wq3,
                (float*)p_bqkv + (size_t)l * 3 * Cc,
                nullptr, p_q126, Cc);

            attn_last<<<BNn * Hh, 128>>>(qkvb, (__half*)p_q126, (__half*)p_y126);

            // proj + residual (compact, in-place on x126)
            gemm_mma<0, 0, 1, 64, Cc><<<dim3(Cc / 128, BNn / 64), 128, SMEM_MT64>>>(
                (__half*)p_y126, (__half*)p_wp + wo, bp + bo,
                (float*)p_x126, p_x126, Cc);

            ln_f2h<<<BNn, 256>>>((float*)p_x126, ln2w + bo, ln2b + bo, (__half*)p_h126);

            gemm_mma<1, 1, 0, 128, Cc><<<dim3(4 * Cc / 128, 1), 128, SMEM_MT128>>>(
                (__half*)p_h126, (__half*)p_w1 + w1o, b1 + b1o,
                nullptr, p_mid126, 4 * Cc);
            gemm_mma<0, 0, 1, 64, 4 * Cc><<<dim3(Cc / 128, BNn / 64), 128, SMEM_MT64>>>(
                (__half*)p_mid126, (__half*)p_w2 + w1o, b2 + bo,
                (float*)p_x126, p_x126, Cc);
        }
    }

    head_kernel<<<BNn, 256>>>((float*)p_x126, lnfw, lnfb, headW, (float*)d_out);
}

// round 12
// speedup vs baseline: 1.1923x; 1.0296x over previous
#include <cuda_runtime.h>
#include <cuda_fp16.h>
#include <mma.h>
#include <math.h>
#include <stdint.h>

using namespace nvcuda;

// ---------------- problem dims ----------------
#define Bb 8
#define Tt 64
#define Nn 16
#define DSs 128
#define Aa 32
#define Cc 1024
#define Hh 16
#define Ll 8
#define Ss 128            // 2*T
#define BNn 128           // B*N
#define Rr 16384          // BN*S
#define Dd 64             // head dim
#define QKVW (3 * Cc)     // fused qkv row width

// ---------------- scratch (device globals; no allocation allowed) ----------------
__device__ float   g_x[Rr * Cc];            // residual stream (fp32)
__device__ __half  g_h[Rr * Cc];            // LN output (fp16)
__device__ __half  g_qkv[Rr * 3 * Cc];      // fused q|k|v (fp16)
__device__ __half  g_y[Rr * Cc];
__device__ __half  g_mid[Rr * 4 * Cc];
__device__ __half  g_st[BNn * Tt * DSs];
__device__ __half  g_ac[BNn * Tt * Aa];
__device__ __half  g_wqkv[Ll * 3 * Cc * Cc];   // transposed [3C, C] per layer
__device__ float   g_bqkv[Ll * 3 * Cc];
__device__ __half  g_wp[Ll * Cc * Cc];         // transposed [N,K]
__device__ __half  g_w1[Ll * Cc * 4 * Cc];     // transposed [4C, C]
__device__ __half  g_w2[Ll * 4 * Cc * Cc];     // transposed [C, 4C]
__device__ __half  g_sew[DSs * Cc];            // K-major
__device__ __half  g_aew[Aa * Cc];
// last-layer compact buffers (row 126 of each bn)
__device__ __half  g_hq126[BNn * Cc];
__device__ float   g_x126[BNn * Cc];
__device__ __half  g_q126[BNn * Cc];
__device__ __half  g_y126[BNn * Cc];
__device__ __half  g_h126[BNn * Cc];
__device__ __half  g_mid126[BNn * 4 * Cc];

// ---------------- small helpers ----------------
__device__ __forceinline__ uint32_t smem_to_u32(const void* smem_ptr) {
    uint32_t addr;
    asm("{ .reg .u64 tmp; cvta.to.shared.u64 tmp, %1; cvt.u32.u64 %0, tmp; }"
        : "=r"(addr) : "l"(smem_ptr));
    return addr;
}
__device__ __forceinline__ void cp_async16(uint32_t saddr, const void* gptr) {
    asm volatile("cp.async.cg.shared.global [%0], [%1], 16;" :: "r"(saddr), "l"(gptr));
}
__device__ __forceinline__ void cp_commit() { asm volatile("cp.async.commit_group;" ::: "memory"); }
#define CP_WAIT_GROUP(n) asm volatile("cp.async.wait_group %0;" :: "n"(n) : "memory")

__device__ __forceinline__ uint32_t sw_off(uint32_t off) { return off ^ ((off >> 3) & 0x70u); }

__device__ __forceinline__ void ldmatrix_x4(uint32_t* d, uint32_t addr) {
    asm volatile("ldmatrix.sync.aligned.m8n8.x4.shared.b16 {%0,%1,%2,%3}, [%4];"
                 : "=r"(d[0]), "=r"(d[1]), "=r"(d[2]), "=r"(d[3]) : "r"(addr));
}
__device__ __forceinline__ void mma_16816(float* c, const uint32_t* a, const uint32_t* b) {
    asm volatile("mma.sync.aligned.m16n8k16.row.col.f32.f16.f16.f32 "
                 "{%0,%1,%2,%3}, {%4,%5,%6,%7}, {%8,%9}, {%0,%1,%2,%3};"
                 : "+f"(c[0]), "+f"(c[1]), "+f"(c[2]), "+f"(c[3])
                 : "r"(a[0]), "r"(a[1]), "r"(a[2]), "r"(a[3]), "r"(b[0]), "r"(b[1]));
}

// gelu(x) = 0.5x(1+tanh(z)) = x / (1 + exp(-2z)), exact identity
__device__ __forceinline__ float gelu_f(float x) {
    float x3 = x * x * x;
    float u = __expf(-1.5957691216057308f * (x + 0.044715f * x3));
    return __fdividef(x, 1.0f + u);
}

// ---------------- prep + all weight transposes (ONE kernel) ----------------
#define WCONV_BLOCKS 104160
__global__ void __launch_bounds__(256) wconv_all(const float* __restrict__ Wq,
                                                 const float* __restrict__ Wk,
                                                 const float* __restrict__ Wv,
                                                 const float* __restrict__ Wp,
                                                 const float* __restrict__ W1,
                                                 const float* __restrict__ W2,
                                                 const float* __restrict__ states,
                                                 const float* __restrict__ actions,
                                                 const float* __restrict__ seW,
                                                 const float* __restrict__ aeW,
                                                 const float* __restrict__ bq,
                                                 const float* __restrict__ bk,
                                                 const float* __restrict__ bv) {
    __shared__ float tile[32][33];
    int bid = blockIdx.x;
    if (bid >= 98304) {
        int i = (bid - 98304) * 256 + threadIdx.x;
        if (i < 1048576) {
            int ds = i % DSs;
            int row = i / DSs;
            int t = row % Tt;
            int bn = row / Tt;
            int b = bn / Nn, n = bn % Nn;
            g_st[i] = __float2half(states[(((size_t)b * Tt + t) * Nn + n) * DSs + ds]);
        } else if (i < 1310720) {
            int j = i - 1048576;
            int a = j % Aa;
            int row = j / Aa;
            int t = row % Tt;
            int bn = row / Tt;
            int b = bn / Nn, n = bn % Nn;
            g_ac[j] = __float2half(actions[(((size_t)b * Tt + t) * Nn + n) * Aa + a]);
        } else if (i < 1441792) {
            int j = i - 1310720;
            g_sew[j] = __float2half(seW[j]);
        } else if (i < 1474560) {
            int j = i - 1441792;
            g_aew[j] = __float2half(aeW[j]);
        } else {
            int j = i - 1474560;            // < Ll*3*Cc
            int l = j / (3 * Cc);
            int k = j - l * 3 * Cc;
            float v = (k < Cc) ? bq[l * Cc + k]
                    : (k < 2 * Cc) ? bk[l * Cc + k - Cc]
                                   : bv[l * Cc + k - 2 * Cc];
            g_bqkv[j] = v;
        }
        return;
    }
    const float* src;
    __half* dst;
    int K, N, bx, by;
    if (bid < 24576) {
        int which = bid >> 13;
        int r = bid & 8191;
        int layer = r >> 10;
        int rt = r & 1023;
        bx = rt & 31; by = rt >> 5; K = Cc; N = Cc;
        src = (which == 0 ? Wq : which == 1 ? Wk : Wv) + (size_t)layer * Cc * Cc;
        dst = g_wqkv + (size_t)layer * 3 * Cc * Cc + (size_t)which * Cc * Cc;
    } else if (bid < 32768) {
        int r = bid - 24576;
        int layer = r >> 10;
        int rt = r & 1023;
        bx = rt & 31; by = rt >> 5; K = Cc; N = Cc;
        src = Wp + (size_t)layer * Cc * Cc;
        dst = g_wp + (size_t)layer * Cc * Cc;
    } else if (bid < 65536) {
        int r = bid - 32768;
        int layer = r >> 12;
        int rt = r & 4095;
        bx = rt & 127; by = rt >> 7; K = Cc; N = 4 * Cc;
        src = W1 + (size_t)layer * Cc * 4 * Cc;
        dst = g_w1 + (size_t)layer * Cc * 4 * Cc;
    } else {
        int r = bid - 65536;
        int layer = r >> 12;
        int rt = r & 4095;
        bx = rt & 31; by = rt >> 5; K = 4 * Cc; N = Cc;
        src = W2 + (size_t)layer * 4 * Cc * Cc;
        dst = g_w2 + (size_t)layer * 4 * Cc * Cc;
    }
    int nb = bx * 32, kb = by * 32;
    int tx = threadIdx.x & 31, ty = threadIdx.x >> 5;  // 32 x 8
#pragma unroll
    for (int r = 0; r < 32; r += 8)
        tile[ty + r][tx] = src[(size_t)(kb + ty + r) * N + nb + tx];
    __syncthreads();
#pragma unroll
    for (int r = 0; r < 32; r += 8)
        dst[(size_t)(nb + ty + r) * K + kb + tx] = __float2half(tile[tx][ty + r]);
}

// ---------------- embed GEMM (wmma) with fused assemble epilogue; z=0 state, z=1 action ----------------
#define BM 128
#define BNt 128
#define BKt 32
#define APAD 8
#define BPAD 8
#define AS_BYTES (2 * BM * (BKt + APAD) * 2)
#define BS_BYTES (2 * BKt * (BNt + BPAD) * 2)

__global__ void __launch_bounds__(256) gemm_embed(const float* __restrict__ bias_s,
                                                  const float* __restrict__ bias_a,
                                                  const float* __restrict__ pe,
                                                  const float* __restrict__ gpe,
                                                  const int* __restrict__ ts,
                                                  float* __restrict__ xout) {
    __shared__ __align__(16) unsigned char sraw[AS_BYTES + BS_BYTES];
    typedef __half (*AsT)[BM][BKt + APAD];
    typedef __half (*BsT)[BKt][BNt + BPAD];
    AsT As = reinterpret_cast<AsT>(sraw);
    BsT Bs = reinterpret_cast<BsT>(sraw + AS_BYTES);

    int parity = blockIdx.z;
    const __half* A  = parity ? g_ac : g_st;
    const __half* Bm = parity ? g_aew : g_sew;
    const float* bias = parity ? bias_a : bias_s;
    int K = parity ? Aa : DSs;
    int N = Cc;

    int tid = threadIdx.x;
    int wid = tid >> 5;
    int wm = wid >> 2;
    int wn = wid & 3;
    int mBase = blockIdx.y * BM;
    int nBase = blockIdx.x * BNt;

    wmma::fragment<wmma::accumulator, 16, 16, 16, float> cf[4][2];
#pragma unroll
    for (int i = 0; i < 4; i++)
#pragma unroll
        for (int j = 0; j < 2; j++) wmma::fill_fragment(cf[i][j], 0.0f);

    int a_row[2], a_col[2], b_row[2], b_col[2];
#pragma unroll
    for (int u = 0; u < 2; u++) {
        int idx = tid + u * 256;
        a_row[u] = idx >> 2;
        a_col[u] = (idx & 3) * 8;
        b_row[u] = idx >> 4;
        b_col[u] = (idx & 15) * 8;
    }

    int ktiles = K / BKt;
    uint4 ra[2], rb[2];
#pragma unroll
    for (int u = 0; u < 2; u++) {
        ra[u] = (a_col[u] < K) ? *(const uint4*)(A + (size_t)(mBase + a_row[u]) * K + a_col[u])
                               : make_uint4(0, 0, 0, 0);
        rb[u] = *(const uint4*)(Bm + (size_t)b_row[u] * N + nBase + b_col[u]);
    }
#pragma unroll
    for (int u = 0; u < 2; u++) {
        if (a_col[u] < BKt) *(uint4*)&As[0][a_row[u]][a_col[u]] = ra[u];
        *(uint4*)&Bs[0][b_row[u]][b_col[u]] = rb[u];
    }
    __syncthreads();

    for (int kt = 0; kt < ktiles; kt++) {
        int cur = kt & 1, nxt = cur ^ 1;
        if (kt + 1 < ktiles) {
            int k0 = (kt + 1) * BKt;
#pragma unroll
            for (int u = 0; u < 2; u++) {
                ra[u] = *(const uint4*)(A + (size_t)(mBase + a_row[u]) * K + k0 + a_col[u]);
                rb[u] = *(const uint4*)(Bm + (size_t)(k0 + b_row[u]) * N + nBase + b_col[u]);
            }
        }
#pragma unroll
        for (int kk = 0; kk < BKt; kk += 16) {
            wmma::fragment<wmma::matrix_a, 16, 16, 16, __half, wmma::row_major> af[4];
            wmma::fragment<wmma::matrix_b, 16, 16, 16, __half, wmma::row_major> bf[2];
#pragma unroll
            for (int i = 0; i < 4; i++)
                wmma::load_matrix_sync(af[i], &As[cur][wm * 64 + i * 16][kk], BKt + APAD);
#pragma unroll
            for (int j = 0; j < 2; j++)
                wmma::load_matrix_sync(bf[j], &Bs[cur][kk][wn * 32 + j * 16], BNt + BPAD);
#pragma unroll
            for (int i = 0; i < 4; i++)
#pragma unroll
                for (int j = 0; j < 2; j++)
                    wmma::mma_sync(cf[i][j], af[i], bf[j], cf[i][j]);
        }
        if (kt + 1 < ktiles) {
            __syncthreads();
#pragma unroll
            for (int u = 0; u < 2; u++) {
                *(uint4*)&As[nxt][a_row[u]][a_col[u]] = ra[u];
                *(uint4*)&Bs[nxt][b_row[u]][b_col[u]] = rb[u];
            }
            __syncthreads();
        }
    }

    __syncthreads();
    float* Epi = reinterpret_cast<float*>(sraw);
#pragma unroll 1
    for (int p = 0; p < 2; p++) {
        if (wm == p) {
#pragma unroll
            for (int i = 0; i < 4; i++)
#pragma unroll
                for (int j = 0; j < 2; j++)
                    wmma::store_matrix_sync(&Epi[(i * 16) * 132 + wn * 32 + j * 16],
                                            cf[i][j], 132, wmma::mem_row_major);
        }
        __syncthreads();
#pragma unroll
        for (int it = 0; it < 8; it++) {
            int idx = tid + it * 256;
            int r = idx >> 5;
            int c4 = (idx & 31) * 4;
            int grow = mBase + p * 64 + r;
            int gcol = nBase + c4;
            float4 vv = *(float4*)&Epi[r * 132 + c4];
            int bn2 = grow >> 6, t = grow & 63, b = bn2 >> 4;
            int s2 = 2 * t + parity;
            int tsv = ts[b * Tt + t];
            const float4 pef = *(const float4*)(pe + (size_t)s2 * Cc + gcol);
            const float4 gf  = *(const float4*)(gpe + (size_t)tsv * Cc + gcol);
            float* Cp = xout + ((size_t)bn2 * Ss + s2) * Cc + gcol;
            *(float4*)Cp = make_float4(vv.x + bias[gcol + 0] + pef.x + gf.x,
                                       vv.y + bias[gcol + 1] + pef.y + gf.y,
                                       vv.z + bias[gcol + 2] + pef.z + gf.z,
                                       vv.w + bias[gcol + 3] + pef.w + gf.w);
        }
        __syncthreads();
    }
}

// ---------------- LayerNorm fp32 -> fp16, one warp per row (no smem, no block sync) ----------------
// grid = nrows/8 blocks of 256 threads.
__global__ void __launch_bounds__(256) ln_f2h(const float* __restrict__ x,
                                              const float* __restrict__ w,
                                              const float* __restrict__ bb,
                                              __half* __restrict__ out) {
    int wid = threadIdx.x >> 5, lane = threadIdx.x & 31;
    size_t row = (size_t)blockIdx.x * 8 + wid;
    const float* xr = x + row * Cc;
    float v[32];
    float s = 0.f, ss = 0.f;
#pragma unroll
    for (int j = 0; j < 8; j++) {
        float4 f = *(const float4*)(xr + j * 128 + lane * 4);
        v[j * 4 + 0] = f.x; v[j * 4 + 1] = f.y; v[j * 4 + 2] = f.z; v[j * 4 + 3] = f.w;
        s  += f.x + f.y + f.z + f.w;
        ss += f.x * f.x + f.y * f.y + f.z * f.z + f.w * f.w;
    }
#pragma unroll
    for (int o = 16; o > 0; o >>= 1) {
        s  += __shfl_xor_sync(0xffffffffu, s, o);
        ss += __shfl_xor_sync(0xffffffffu, ss, o);
    }
    float mean = s * (1.0f / Cc);
    float var = ss * (1.0f / Cc) - mean * mean;
    float rstd = rsqrtf(var + 1e-5f);
    __half* orow = out + row * Cc;
#pragma unroll
    for (int j = 0; j < 8; j++) {
        int c = j * 128 + lane * 4;
        float4 wf = *(const float4*)(w + c);
        float4 bf = *(const float4*)(bb + c);
        float o0 = (v[j * 4 + 0] - mean) * rstd * wf.x + bf.x;
        float o1 = (v[j * 4 + 1] - mean) * rstd * wf.y + bf.y;
        float o2 = (v[j * 4 + 2] - mean) * rstd * wf.z + bf.z;
        float o3 = (v[j * 4 + 3] - mean) * rstd * wf.w + bf.w;
        *(__half2*)(orow + c)     = __floats2half2_rn(o0, o1);
        *(__half2*)(orow + c + 2) = __floats2half2_rn(o2, o3);
    }
}

// ---------------- gather row 126 of each bn: h (fp16) and x (fp32) ----------------
__global__ void gather126(const __half* __restrict__ h, const float* __restrict__ x) {
    int i = blockIdx.x * 256 + threadIdx.x;       // < 2*131072
    if (i < BNn * Cc) {
        int bn = i >> 10, c = i & (Cc - 1);
        g_hq126[i] = h[((size_t)bn * Ss + (Ss - 2)) * Cc + c];
    } else {
        int j = i - BNn * Cc;
        int bn = j >> 10, c = j & (Cc - 1);
        g_x126[j] = x[((size_t)bn * Ss + (Ss - 2)) * Cc + c];
    }
}

// ---------------- HMMA GEMM: MT x 128 CTA tile, 4 warps (MT/2 x 64 each), 3-stage cp.async ----------------
#define GBK 64
#define GSTG 3

template <int OUTHALF, int DOGELU, int DORES, int MT, int KDIM>
__global__ void __launch_bounds__(128, MT == 64 ? 3 : 2)
gemm_mma(const __half* __restrict__ A,
         const __half* __restrict__ Bt,
         const float* __restrict__ bias,
         const float* __restrict__ res,
         void* __restrict__ Cout,
         int N) {
    constexpr int MI = MT / 32;                    // 4 or 2
    constexpr int STAGE_B = (MT + 128) * 128;      // bytes per stage
    constexpr int ACH = MT * 8;                    // A chunks per stage
    constexpr int TOTCH = ACH + 1024;              // total 16B chunks
    constexpr int JN = TOTCH / 128;
    constexpr int KT = KDIM / GBK;

    extern __shared__ unsigned char gsm[];
    uint32_t sbase = smem_to_u32(gsm);
    const int tid = threadIdx.x;
    const int wid = tid >> 5;
    const int lane = tid & 31;
    const int wm = wid & 1;
    const int wn = wid >> 1;
    const int mBase = blockIdx.y * MT;
    const int nBase = blockIdx.x * 128;

    float acc[MI][8][4];
#pragma unroll
    for (int i = 0; i < MI; i++)
#pragma unroll
        for (int j = 0; j < 8; j++)
#pragma unroll
            for (int r = 0; r < 4; r++) acc[i][j][r] = 0.f;

    auto load_stage = [&](int kt) {
        int k0 = kt * GBK;
        uint32_t ab = sbase + (uint32_t)(kt % GSTG) * STAGE_B;
        uint32_t bb = ab + (uint32_t)(MT * 128);
#pragma unroll
        for (int j = 0; j < JN; j++) {
            int id = tid + j * 128;
            if (id < ACH) {
                int row = id >> 3;
                int c16 = id & 7;
                uint32_t sw = sw_off((uint32_t)(row * 128 + c16 * 16));
                cp_async16(ab + sw, A + (size_t)(mBase + row) * KDIM + k0 + c16 * 8);
            } else {
                int idx = id - ACH;
                int row = idx >> 3;
                int c16 = idx & 7;
                uint32_t sw = sw_off((uint32_t)(row * 128 + c16 * 16));
                cp_async16(bb + sw, Bt + (size_t)(nBase + row) * KDIM + k0 + c16 * 8);
            }
        }
    };

    load_stage(0); cp_commit();
    load_stage(1); cp_commit();

#pragma unroll 2
    for (int kt = 0; kt < KT; kt++) {
        CP_WAIT_GROUP(1);
        __syncthreads();
        if (kt + 2 < KT) load_stage(kt + 2);
        cp_commit();

        uint32_t ab = sbase + (uint32_t)(kt % GSTG) * STAGE_B;
        uint32_t bb = ab + (uint32_t)(MT * 128);
#pragma unroll
        for (int ks = 0; ks < 4; ks++) {
            uint32_t a_r[MI][4];
            uint32_t b_r[8][2];
#pragma unroll
            for (int mi = 0; mi < MI; mi++) {
                int row = wm * (MT / 2) + mi * 16 + (lane & 15);
                int kc = ks * 2 + (lane >> 4);
                ldmatrix_x4(a_r[mi], ab + sw_off((uint32_t)(row * 128 + kc * 16)));
            }
#pragma unroll
            for (int bj = 0; bj < 4; bj++) {
                int nrow = wn * 64 + bj * 16 + (lane & 7) + ((lane >> 4) & 1) * 8;
                int kc = ks * 2 + ((lane >> 3) & 1);
                uint32_t r[4];
                ldmatrix_x4(r, bb + sw_off((uint32_t)(nrow * 128 + kc * 16)));
                b_r[bj * 2 + 0][0] = r[0]; b_r[bj * 2 + 0][1] = r[1];
                b_r[bj * 2 + 1][0] = r[2]; b_r[bj * 2 + 1][1] = r[3];
            }
#pragma unroll
            for (int mi = 0; mi < MI; mi++)
#pragma unroll
                for (int ni = 0; ni < 8; ni++)
                    mma_16816(acc[mi][ni], a_r[mi], b_r[ni]);
        }
    }

#pragma unroll
    for (int mi = 0; mi < MI; mi++) {
#pragma unroll
        for (int ni = 0; ni < 8; ni++) {
            int r0 = mBase + wm * (MT / 2) + mi * 16 + (lane >> 2);
            int c0 = nBase + wn * 64 + ni * 8 + 2 * (lane & 3);
            float b0 = bias[c0], b1 = bias[c0 + 1];
#pragma unroll
            for (int half_ = 0; half_ < 2; half_++) {
                int row = r0 + half_ * 8;
                float o0 = acc[mi][ni][half_ * 2 + 0] + b0;
                float o1 = acc[mi][ni][half_ * 2 + 1] + b1;
                if (DOGELU) { o0 = gelu_f(o0); o1 = gelu_f(o1); }
                if (DORES) {
                    const float* rp = res + (size_t)row * N + c0;
                    o0 += rp[0]; o1 += rp[1];
                }
                if (OUTHALF) {
                    *(__half2*)((__half*)Cout + (size_t)row * N + c0) = __floats2half2_rn(o0, o1);
                } else {
                    *(float2*)((float*)Cout + (size_t)row * N + c0) = make_float2(o0, o1);
                }
            }
        }
    }
}

#define SMEM_MT128 (GSTG * (128 + 128) * 128)   // 98304
#define SMEM_MT64  (GSTG * (64 + 128) * 128)    // 73728

// ---------------- tensor-core attention: block per (bn, head), 4 warps ----------------
#define ATT_SMEM 81920

__global__ void __launch_bounds__(128) attn_tc(const __half* __restrict__ qkv,
                                               __half* __restrict__ y) {
    extern __shared__ unsigned char asm_[];
    uint32_t sb = smem_to_u32(asm_);
    uint32_t sK = sb, sQ = sb + 16384, sV0 = sb + 32768, sV1 = sb + 40960;
    int tid = threadIdx.x, wid = tid >> 5, lane = tid & 31;
    uint32_t sP0 = sb + 49152 + wid * 8192;
    uint32_t sP1 = sP0 + 4096;
    char* pch0 = (char*)asm_ + 49152 + wid * 8192;
    char* pch1 = pch0 + 4096;
    int bh = blockIdx.x, bn = bh >> 4, h = bh & 15;
    size_t baseq = (size_t)bn * Ss * QKVW + h * Dd;
    size_t basey = (size_t)bn * Ss * Cc + h * Dd;

    for (int idx = tid; idx < 1024; idx += 128) {
        int row = idx >> 3, c = idx & 7;
        uint32_t sw = sw_off((uint32_t)(row * 128 + c * 16));
        cp_async16(sQ + sw, qkv + baseq + (size_t)row * QKVW + c * 8);
        cp_async16(sK + sw, qkv + baseq + Cc + (size_t)row * QKVW + c * 8);
    }
    cp_commit();
    for (int idx = tid; idx < 4096; idx += 128) {
        int kv = idx >> 5, d2 = idx & 31;
        __half2 v2 = *(const __half2*)(qkv + baseq + 2 * Cc + (size_t)kv * QKVW + d2 * 2);
        char* vbp = (char*)asm_ + ((kv < 64) ? 32768 : 40960);
        int kc = kv & 63;
        *(__half*)(vbp + sw_off((uint32_t)((d2 * 2) * 128 + kc * 2)))     = __low2half(v2);
        *(__half*)(vbp + sw_off((uint32_t)((d2 * 2 + 1) * 128 + kc * 2))) = __high2half(v2);
    }
    CP_WAIT_GROUP(0);
    __syncthreads();

    int qb = wid * 32;
    float accS[2][16][4];
#pragma unroll
    for (int mi = 0; mi < 2; mi++)
#pragma unroll
        for (int ni = 0; ni < 16; ni++)
#pragma unroll
            for (int r = 0; r < 4; r++) accS[mi][ni][r] = 0.f;

#pragma unroll
    for (int ks = 0; ks < 4; ks++) {
        uint32_t a[2][4], b[16][2];
#pragma unroll
        for (int mi = 0; mi < 2; mi++) {
            int row = qb + mi * 16 + (lane & 15);
            int kc = ks * 2 + (lane >> 4);
            ldmatrix_x4(a[mi], sQ + sw_off((uint32_t)(row * 128 + kc * 16)));
        }
#pragma unroll
        for (int bj = 0; bj < 8; bj++) {
            int nrow = bj * 16 + (lane & 7) + ((lane >> 4) & 1) * 8;
            int kc = ks * 2 + ((lane >> 3) & 1);
            uint32_t r[4];
            ldmatrix_x4(r, sK + sw_off((uint32_t)(nrow * 128 + kc * 16)));
            b[bj * 2 + 0][0] = r[0]; b[bj * 2 + 0][1] = r[1];
            b[bj * 2 + 1][0] = r[2]; b[bj * 2 + 1][1] = r[3];
        }
#pragma unroll
        for (int mi = 0; mi < 2; mi++)
#pragma unroll
            for (int ni = 0; ni < 16; ni++)
                mma_16816(accS[mi][ni], a[mi], b[ni]);
    }

    float inv[2][2];
#pragma unroll
    for (int mi = 0; mi < 2; mi++) {
        float s0 = 0.f, s1 = 0.f;
        int rA = qb + mi * 16 + (lane >> 2);
        int rB = rA + 8;
        int rl = mi * 16 + (lane >> 2);
#pragma unroll
        for (int ni = 0; ni < 16; ni++) {
            int c0 = ni * 8 + 2 * (lane & 3);
            float p00 = (c0     <= rA) ? __expf(accS[mi][ni][0] * 0.125f) : 0.f;
            float p01 = (c0 + 1 <= rA) ? __expf(accS[mi][ni][1] * 0.125f) : 0.f;
            float p10 = (c0     <= rB) ? __expf(accS[mi][ni][2] * 0.125f) : 0.f;
            float p11 = (c0 + 1 <= rB) ? __expf(accS[mi][ni][3] * 0.125f) : 0.f;
            s0 += p00 + p01; s1 += p10 + p11;
            char* pp = (c0 < 64) ? pch0 : pch1;
            int cl = c0 & 63;
            *(__half2*)(pp + sw_off((uint32_t)(rl * 128 + cl * 2)))       = __floats2half2_rn(p00, p01);
            *(__half2*)(pp + sw_off((uint32_t)((rl + 8) * 128 + cl * 2))) = __floats2half2_rn(p10, p11);
        }
        s0 += __shfl_xor_sync(0xffffffffu, s0, 1);
        s0 += __shfl_xor_sync(0xffffffffu, s0, 2);
        s1 += __shfl_xor_sync(0xffffffffu, s1, 1);
        s1 += __shfl_xor_sync(0xffffffffu, s1, 2);
        inv[mi][0] = 1.0f / s0;
        inv[mi][1] = 1.0f / s1;
    }
    __syncwarp();

    float accO[2][8][4];
#pragma unroll
    for (int mi = 0; mi < 2; mi++)
#pragma unroll
        for (int ni = 0; ni < 8; ni++)
#pragma unroll
            for (int r = 0; r < 4; r++) accO[mi][ni][r] = 0.f;

#pragma unroll
    for (int ks = 0; ks < 8; ks++) {
        uint32_t pbase = (ks < 4) ? sP0 : sP1;
        uint32_t vbase = (ks < 4) ? sV0 : sV1;
        int kss = ks & 3;
        uint32_t a[2][4], b[8][2];
#pragma unroll
        for (int mi = 0; mi < 2; mi++) {
            int row = mi * 16 + (lane & 15);
            int kc = kss * 2 + (lane >> 4);
            ldmatrix_x4(a[mi], pbase + sw_off((uint32_t)(row * 128 + kc * 16)));
        }
#pragma unroll
        for (int bj = 0; bj < 4; bj++) {
            int nrow = bj * 16 + (lane & 7) + ((lane >> 4) & 1) * 8;
            int kc = kss * 2 + ((lane >> 3) & 1);
            uint32_t r[4];
            ldmatrix_x4(r, vbase + sw_off((uint32_t)(nrow * 128 + kc * 16)));
            b[bj * 2 + 0][0] = r[0]; b[bj * 2 + 0][1] = r[1];
            b[bj * 2 + 1][0] = r[2]; b[bj * 2 + 1][1] = r[3];
        }
#pragma unroll
        for (int mi = 0; mi < 2; mi++)
#pragma unroll
            for (int ni = 0; ni < 8; ni++)
                mma_16816(accO[mi][ni], a[mi], b[ni]);
    }

#pragma unroll
    for (int mi = 0; mi < 2; mi++) {
#pragma unroll
        for (int ni = 0; ni < 8; ni++) {
            int rA = qb + mi * 16 + (lane >> 2);
            int c0 = ni * 8 + 2 * (lane & 3);
            *(__half2*)(y + basey + (size_t)rA * Cc + c0) =
                __floats2half2_rn(accO[mi][ni][0] * inv[mi][0], accO[mi][ni][1] * inv[mi][0]);
            *(__half2*)(y + basey + (size_t)(rA + 8) * Cc + c0) =
                __floats2half2_rn(accO[mi][ni][2] * inv[mi][1], accO[mi][ni][3] * inv[mi][1]);
        }
    }
}

// ---------------- last-layer single-query attention: block per (bn,h) ----------------
__global__ void __launch_bounds__(128) attn_last(const __half* __restrict__ qkv,
                                                 const __half* __restrict__ q126,
                                                 __half* __restrict__ y126) {
    __shared__ float qs[Dd];
    __shared__ float e[Ss];
    __shared__ float ws[4];
    int tid = threadIdx.x, wid = tid >> 5, lane = tid & 31;
    int bh = blockIdx.x, bn = bh >> 4, h = bh & 15;
    size_t base = (size_t)bn * Ss * QKVW + h * Dd;

    if (tid < 32) {
        float2 f = __half22float2(*(const __half2*)(q126 + (size_t)bn * Cc + h * Dd + tid * 2));
        qs[tid * 2] = f.x; qs[tid * 2 + 1] = f.y;
    }
    __syncthreads();

    int j = tid;
    float ej = 0.f;
    if (j <= Ss - 2) {
        const __half* kr = qkv + base + Cc + (size_t)j * QKVW;
        float s = 0.f;
#pragma unroll
        for (int i = 0; i < Dd; i++) s += qs[i] * __half2float(kr[i]);
        ej = __expf(s * 0.125f);
    }
    e[j] = ej;
    float s = ej;
#pragma unroll
    for (int o = 16; o > 0; o >>= 1) s += __shfl_xor_sync(0xffffffffu, s, o);
    if (lane == 0) ws[wid] = s;
    __syncthreads();
    float sum = ws[0] + ws[1] + ws[2] + ws[3];

    if (tid < Dd) {
        float acc = 0.f;
        for (int k = 0; k <= Ss - 2; k++)
            acc += e[k] * __half2float(qkv[base + 2 * Cc + (size_t)k * QKVW + tid]);
        y126[(size_t)bn * Cc + h * Dd + tid] = __float2half(acc / sum);
    }
}

// ---------------- final LN + head (compact x126 input) ----------------
__global__ void __launch_bounds__(256) head_kernel(const float* __restrict__ x,
                                                   const float* __restrict__ lnw,
                                                   const float* __restrict__ lnb,
                                                   const float* __restrict__ headW,
                                                   float* __restrict__ out) {
    int bn = blockIdx.x;
    const float* xr = x + (size_t)bn * Cc;
    __shared__ float hsm[Cc];
    int c0 = threadIdx.x * 4;
    float4 f = *(const float4*)(xr + c0);
    float s = f.x + f.y + f.z + f.w;
    float ss = f.x * f.x + f.y * f.y + f.z * f.z + f.w * f.w;
#pragma unroll
    for (int o = 16; o > 0; o >>= 1) {
        s  += __shfl_xor_sync(0xffffffffu, s, o);
        ss += __shfl_xor_sync(0xffffffffu, ss, o);
    }
    __shared__ float rs[8], rss[8];
    int wrp = threadIdx.x >> 5, lane = threadIdx.x & 31;
    if (lane == 0) { rs[wrp] = s; rss[wrp] = ss; }
    __syncthreads();
    s = 0.f; ss = 0.f;
#pragma unroll
    for (int qq = 0; qq < 8; qq++) { s += rs[qq]; ss += rss[qq]; }
    float mean = s * (1.0f / Cc);
    float var = ss * (1.0f / Cc) - mean * mean;
    float rstd = rsqrtf(var + 1e-5f);
    float4 wf = *(const float4*)(lnw + c0);
    float4 bf = *(const float4*)(lnb + c0);
    hsm[c0 + 0] = (f.x - mean) * rstd * wf.x + bf.x;
    hsm[c0 + 1] = (f.y - mean) * rstd * wf.y + bf.y;
    hsm[c0 + 2] = (f.z - mean) * rstd * wf.z + bf.z;
    hsm[c0 + 3] = (f.w - mean) * rstd * wf.w + bf.w;
    __syncthreads();
    if (threadIdx.x < Aa) {
        int a = threadIdx.x;
        float acc = 0.f;
        for (int c = 0; c < Cc; c++) acc += hsm[c] * headW[c * Aa + a];
        out[bn * Aa + a] = acc;
    }
}

// ---------------- host launch ----------------
extern "C" void kernel_launch(void* const* d_in, const int* in_sizes, int n_in,
                              void* d_out, int out_size) {
    const float* states     = (const float*)d_in[0];
    const float* actions    = (const float*)d_in[1];
    const int*   timesteps  = (const int*)d_in[2];
    const float* pos_emb    = (const float*)d_in[3];
    const float* gpe        = (const float*)d_in[4];
    const float* seW        = (const float*)d_in[5];
    const float* seb        = (const float*)d_in[6];
    const float* aeW        = (const float*)d_in[7];
    const float* aeb        = (const float*)d_in[8];
    const float* ln1w       = (const float*)d_in[9];
    const float* ln1b       = (const float*)d_in[10];
    const float* Wq         = (const float*)d_in[11];
    const float* bq         = (const float*)d_in[12];
    const float* Wk         = (const float*)d_in[13];
    const float* bk         = (const float*)d_in[14];
    const float* Wv         = (const float*)d_in[15];
    const float* bv         = (const float*)d_in[16];
    const float* Wp         = (const float*)d_in[17];
    const float* bp         = (const float*)d_in[18];
    const float* ln2w       = (const float*)d_in[19];
    const float* ln2b       = (const float*)d_in[20];
    const float* W1         = (const float*)d_in[21];
    const float* b1         = (const float*)d_in[22];
    const float* W2         = (const float*)d_in[23];
    const float* b2         = (const float*)d_in[24];
    const float* lnfw       = (const float*)d_in[25];
    const float* lnfb       = (const float*)d_in[26];
    const float* headW      = (const float*)d_in[27];

    void *p_x, *p_h, *p_qkv, *p_y, *p_mid;
    void *p_wqkv, *p_bqkv, *p_wp, *p_w1, *p_w2;
    void *p_hq126, *p_x126, *p_q126, *p_y126, *p_h126, *p_mid126;
    cudaGetSymbolAddress(&p_x, g_x);       cudaGetSymbolAddress(&p_h, g_h);
    cudaGetSymbolAddress(&p_qkv, g_qkv);   cudaGetSymbolAddress(&p_y, g_y);
    cudaGetSymbolAddress(&p_mid, g_mid);   cudaGetSymbolAddress(&p_wqkv, g_wqkv);
    cudaGetSymbolAddress(&p_bqkv, g_bqkv); cudaGetSymbolAddress(&p_wp, g_wp);
    cudaGetSymbolAddress(&p_w1, g_w1);     cudaGetSymbolAddress(&p_w2, g_w2);
    cudaGetSymbolAddress(&p_hq126, g_hq126); cudaGetSymbolAddress(&p_x126, g_x126);
    cudaGetSymbolAddress(&p_q126, g_q126);   cudaGetSymbolAddress(&p_y126, g_y126);
    cudaGetSymbolAddress(&p_h126, g_h126);   cudaGetSymbolAddress(&p_mid126, g_mid126);

    float*  xbuf = (float*)p_x;
    __half* hbuf = (__half*)p_h;
    __half* qkvb = (__half*)p_qkv;
    __half* ybuf = (__half*)p_y;
    __half* midb = (__half*)p_mid;

    cudaFuncSetAttribute((gemm_mma<1, 0, 0, 128, Cc>), cudaFuncAttributeMaxDynamicSharedMemorySize, SMEM_MT128);
    cudaFuncSetAttribute((gemm_mma<1, 1, 0, 128, Cc>), cudaFuncAttributeMaxDynamicSharedMemorySize, SMEM_MT128);
    cudaFuncSetAttribute((gemm_mma<0, 0, 1, 64, Cc>),  cudaFuncAttributeMaxDynamicSharedMemorySize, SMEM_MT64);
    cudaFuncSetAttribute((gemm_mma<0, 0, 1, 64, 4 * Cc>), cudaFuncAttributeMaxDynamicSharedMemorySize, SMEM_MT64);
    cudaFuncSetAttribute(attn_tc, cudaFuncAttributeMaxDynamicSharedMemorySize, ATT_SMEM);

    // ours#1: all weight transposes + gathers + embed weights + bias concat
    wconv_all<<<WCONV_BLOCKS, 256>>>(Wq, Wk, Wv, Wp, W1, W2,
                                     states, actions, seW, aeW, bq, bk, bv);
    // ours#2: both embed GEMMs (z = parity) with fused assemble
    gemm_embed<<<dim3(Cc / BNt, 8192 / BM, 2), 256>>>(seb, aeb, pos_emb, gpe, timesteps, xbuf);

    for (int l = 0; l < Ll; l++) {
        size_t wo  = (size_t)l * Cc * Cc;
        size_t wq3 = (size_t)l * 3 * Cc * Cc;
        size_t w1o = (size_t)l * Cc * 4 * Cc;
        size_t bo  = (size_t)l * Cc;
        size_t b1o = (size_t)l * 4 * Cc;

        ln_f2h<<<Rr / 8, 256>>>(xbuf, ln1w + bo, ln1b + bo, hbuf);

        if (l < Ll - 1) {
            // full QKV
            gemm_mma<1, 0, 0, 128, Cc><<<dim3(3 * Cc / 128, Rr / 128), 128, SMEM_MT128>>>(
                hbuf, (__half*)p_wqkv + wq3, (float*)p_bqkv + (size_t)l * 3 * Cc,
                nullptr, p_qkv, 3 * Cc);

            attn_tc<<<BNn * Hh, 128, ATT_SMEM>>>(qkvb, ybuf);

            gemm_mma<0, 0, 1, 64, Cc><<<dim3(Cc / 128, Rr / 64), 128, SMEM_MT64>>>(
                ybuf, (__half*)p_wp + wo, bp + bo, xbuf, p_x, Cc);

            ln_f2h<<<Rr / 8, 256>>>(xbuf, ln2w + bo, ln2b + bo, hbuf);

            gemm_mma<1, 1, 0, 128, Cc><<<dim3(4 * Cc / 128, Rr / 128), 128, SMEM_MT128>>>(
                hbuf, (__half*)p_w1 + w1o, b1 + b1o, nullptr, p_mid, 4 * Cc);
            gemm_mma<0, 0, 1, 64, 4 * Cc><<<dim3(Cc / 128, Rr / 64), 128, SMEM_MT64>>>(
                midb, (__half*)p_w2 + w1o, b2 + bo, xbuf, p_x, Cc);
        } else {
            // last layer: only row S-2 of each bn feeds the output
            gather126<<<(2 * BNn * Cc) / 256, 256>>>(hbuf, xbuf);

            // k,v for all rows (columns [C, 3C) of qkv)
            gemm_mma<1, 0, 0, 128, Cc><<<dim3(2 * Cc / 128, Rr / 128), 128, SMEM_MT128>>>(
                hbuf, (__half*)p_wqkv + wq3 + (size_t)Cc * Cc,
                (float*)p_bqkv + (size_t)l * 3 * Cc + Cc,
                nullptr, (void*)((__half*)p_qkv + Cc), 3 * Cc);
            // q only for the 128 gathered rows
            gemm_mma<1, 0, 0, 128, Cc><<<dim3(Cc / 128, 1), 128, SMEM_MT128>>>(
                (__half*)p_hq126, (__half*)p_wqkv + wq3,
                (float*)p_bqkv + (size_t)l * 3 * Cc,
                nullptr, p_q126, Cc);

            attn_last<<<BNn * Hh, 128>>>(qkvb, (__half*)p_q126, (__half*)p_y126);

            // proj + residual (compact, in-place on x126)
            gemm_mma<0, 0, 1, 64, Cc><<<dim3(Cc / 128, BNn / 64), 128, SMEM_MT64>>>(
                (__half*)p_y126, (__half*)p_wp + wo, bp + bo,
                (float*)p_x126, p_x126, Cc);

            ln_f2h<<<BNn / 8, 256>>>((float*)p_x126, ln2w + bo, ln2b + bo, (__half*)p_h126);

            gemm_mma<1, 1, 0, 128, Cc><<<dim3(4 * Cc / 128, 1), 128, SMEM_MT128>>>(
                (__half*)p_h126, (__half*)p_w1 + w1o, b1 + b1o,
                nullptr, p_mid126, 4 * Cc);
            gemm_mma<0, 0, 1, 64, 4 * Cc><<<dim3(Cc / 128, BNn / 64), 128, SMEM_MT64>>>(
                (__half*)p_mid126, (__half*)p_w2 + w1o, b2 + bo,
                (float*)p_x126, p_x126, Cc);
        }
    }

    head_kernel<<<BNn, 256>>>((float*)p_x126, lnfw, lnfb, headW, (float*)d_out);
}

// round 14
// speedup vs baseline: 1.1942x; 1.0016x over previous
#include <cuda_runtime.h>
#include <cuda_fp16.h>
#include <mma.h>
#include <math.h>
#include <stdint.h>

using namespace nvcuda;

// ---------------- problem dims ----------------
#define Bb 8
#define Tt 64
#define Nn 16
#define DSs 128
#define Aa 32
#define Cc 1024
#define Hh 16
#define Ll 8
#define Ss 128            // 2*T
#define BNn 128           // B*N
#define Rr 16384          // BN*S
#define Dd 64             // head dim
#define QKVW (3 * Cc)     // fused qkv row width

// ---------------- scratch (device globals; no allocation allowed) ----------------
__device__ float   g_x[Rr * Cc];            // residual stream (fp32)
__device__ __half  g_h[Rr * Cc];            // LN output (fp16)
__device__ __half  g_qkv[Rr * 3 * Cc];      // fused q|k|v (fp16)
__device__ __half  g_y[Rr * Cc];
__device__ __half  g_mid[Rr * 4 * Cc];
__device__ __half  g_st[BNn * Tt * DSs];
__device__ __half  g_ac[BNn * Tt * Aa];
__device__ __half  g_wqkv[Ll * 3 * Cc * Cc];   // transposed [3C, C] per layer
__device__ float   g_bqkv[Ll * 3 * Cc];
__device__ __half  g_wp[Ll * Cc * Cc];         // transposed [N,K]
__device__ __half  g_w1[Ll * Cc * 4 * Cc];     // transposed [4C, C]
__device__ __half  g_w2[Ll * 4 * Cc * Cc];     // transposed [C, 4C]
__device__ __half  g_sew[DSs * Cc];            // K-major
__device__ __half  g_aew[Aa * Cc];
// last-layer compact buffers (row 126 of each bn)
__device__ __half  g_hq126[BNn * Cc];
__device__ float   g_x126[BNn * Cc];
__device__ __half  g_q126[BNn * Cc];
__device__ __half  g_y126[BNn * Cc];
__device__ __half  g_h126[BNn * Cc];
__device__ __half  g_mid126[BNn * 4 * Cc];

// ---------------- small helpers ----------------
__device__ __forceinline__ uint32_t smem_to_u32(const void* smem_ptr) {
    uint32_t addr;
    asm("{ .reg .u64 tmp; cvta.to.shared.u64 tmp, %1; cvt.u32.u64 %0, tmp; }"
        : "=r"(addr) : "l"(smem_ptr));
    return addr;
}
__device__ __forceinline__ void cp_async16(uint32_t saddr, const void* gptr) {
    asm volatile("cp.async.cg.shared.global [%0], [%1], 16;" :: "r"(saddr), "l"(gptr));
}
__device__ __forceinline__ void cp_commit() { asm volatile("cp.async.commit_group;" ::: "memory"); }
#define CP_WAIT_GROUP(n) asm volatile("cp.async.wait_group %0;" :: "n"(n) : "memory")

__device__ __forceinline__ uint32_t sw_off(uint32_t off) { return off ^ ((off >> 3) & 0x70u); }

__device__ __forceinline__ uint32_t h2_as_u32(__half2 h) {
    union { __half2 h2; uint32_t u; } cvt;
    cvt.h2 = h;
    return cvt.u;
}

__device__ __forceinline__ void ldmatrix_x4(uint32_t* d, uint32_t addr) {
    asm volatile("ldmatrix.sync.aligned.m8n8.x4.shared.b16 {%0,%1,%2,%3}, [%4];"
                 : "=r"(d[0]), "=r"(d[1]), "=r"(d[2]), "=r"(d[3]) : "r"(addr));
}
__device__ __forceinline__ void mma_16816(float* c, const uint32_t* a, const uint32_t* b) {
    asm volatile("mma.sync.aligned.m16n8k16.row.col.f32.f16.f16.f32 "
                 "{%0,%1,%2,%3}, {%4,%5,%6,%7}, {%8,%9}, {%0,%1,%2,%3};"
                 : "+f"(c[0]), "+f"(c[1]), "+f"(c[2]), "+f"(c[3])
                 : "r"(a[0]), "r"(a[1]), "r"(a[2]), "r"(a[3]), "r"(b[0]), "r"(b[1]));
}

// gelu(x) = 0.5x(1+tanh(z)) = x / (1 + exp(-2z)), exact identity
__device__ __forceinline__ float gelu_f(float x) {
    float x3 = x * x * x;
    float u = __expf(-1.5957691216057308f * (x + 0.044715f * x3));
    return __fdividef(x, 1.0f + u);
}

// ---------------- prep + all weight transposes (ONE kernel) ----------------
#define WCONV_BLOCKS 104160
__global__ void __launch_bounds__(256) wconv_all(const float* __restrict__ Wq,
                                                 const float* __restrict__ Wk,
                                                 const float* __restrict__ Wv,
                                                 const float* __restrict__ Wp,
                                                 const float* __restrict__ W1,
                                                 const float* __restrict__ W2,
                                                 const float* __restrict__ states,
                                                 const float* __restrict__ actions,
                                                 const float* __restrict__ seW,
                                                 const float* __restrict__ aeW,
                                                 const float* __restrict__ bq,
                                                 const float* __restrict__ bk,
                                                 const float* __restrict__ bv) {
    __shared__ float tile[32][33];
    int bid = blockIdx.x;
    if (bid >= 98304) {
        int i = (bid - 98304) * 256 + threadIdx.x;
        if (i < 1048576) {
            int ds = i % DSs;
            int row = i / DSs;
            int t = row % Tt;
            int bn = row / Tt;
            int b = bn / Nn, n = bn % Nn;
            g_st[i] = __float2half(states[(((size_t)b * Tt + t) * Nn + n) * DSs + ds]);
        } else if (i < 1310720) {
            int j = i - 1048576;
            int a = j % Aa;
            int row = j / Aa;
            int t = row % Tt;
            int bn = row / Tt;
            int b = bn / Nn, n = bn % Nn;
            g_ac[j] = __float2half(actions[(((size_t)b * Tt + t) * Nn + n) * Aa + a]);
        } else if (i < 1441792) {
            int j = i - 1310720;
            g_sew[j] = __float2half(seW[j]);
        } else if (i < 1474560) {
            int j = i - 1441792;
            g_aew[j] = __float2half(aeW[j]);
        } else {
            int j = i - 1474560;            // < Ll*3*Cc
            int l = j / (3 * Cc);
            int k = j - l * 3 * Cc;
            float v = (k < Cc) ? bq[l * Cc + k]
                    : (k < 2 * Cc) ? bk[l * Cc + k - Cc]
                                   : bv[l * Cc + k - 2 * Cc];
            g_bqkv[j] = v;
        }
        return;
    }
    const float* src;
    __half* dst;
    int K, N, bx, by;
    if (bid < 24576) {
        int which = bid >> 13;
        int r = bid & 8191;
        int layer = r >> 10;
        int rt = r & 1023;
        bx = rt & 31; by = rt >> 5; K = Cc; N = Cc;
        src = (which == 0 ? Wq : which == 1 ? Wk : Wv) + (size_t)layer * Cc * Cc;
        dst = g_wqkv + (size_t)layer * 3 * Cc * Cc + (size_t)which * Cc * Cc;
    } else if (bid < 32768) {
        int r = bid - 24576;
        int layer = r >> 10;
        int rt = r & 1023;
        bx = rt & 31; by = rt >> 5; K = Cc; N = Cc;
        src = Wp + (size_t)layer * Cc * Cc;
        dst = g_wp + (size_t)layer * Cc * Cc;
    } else if (bid < 65536) {
        int r = bid - 32768;
        int layer = r >> 12;
        int rt = r & 4095;
        bx = rt & 127; by = rt >> 7; K = Cc; N = 4 * Cc;
        src = W1 + (size_t)layer * Cc * 4 * Cc;
        dst = g_w1 + (size_t)layer * Cc * 4 * Cc;
    } else {
        int r = bid - 65536;
        int layer = r >> 12;
        int rt = r & 4095;
        bx = rt & 31; by = rt >> 5; K = 4 * Cc; N = Cc;
        src = W2 + (size_t)layer * 4 * Cc * Cc;
        dst = g_w2 + (size_t)layer * 4 * Cc * Cc;
    }
    int nb = bx * 32, kb = by * 32;
    int tx = threadIdx.x & 31, ty = threadIdx.x >> 5;  // 32 x 8
#pragma unroll
    for (int r = 0; r < 32; r += 8)
        tile[ty + r][tx] = src[(size_t)(kb + ty + r) * N + nb + tx];
    __syncthreads();
#pragma unroll
    for (int r = 0; r < 32; r += 8)
        dst[(size_t)(nb + ty + r) * K + kb + tx] = __float2half(tile[tx][ty + r]);
}

// ---------------- embed GEMM (wmma) with fused assemble epilogue; z=0 state, z=1 action ----------------
#define BM 128
#define BNt 128
#define BKt 32
#define APAD 8
#define BPAD 8
#define AS_BYTES (2 * BM * (BKt + APAD) * 2)
#define BS_BYTES (2 * BKt * (BNt + BPAD) * 2)

__global__ void __launch_bounds__(256) gemm_embed(const float* __restrict__ bias_s,
                                                  const float* __restrict__ bias_a,
                                                  const float* __restrict__ pe,
                                                  const float* __restrict__ gpe,
                                                  const int* __restrict__ ts,
                                                  float* __restrict__ xout) {
    __shared__ __align__(16) unsigned char sraw[AS_BYTES + BS_BYTES];
    typedef __half (*AsT)[BM][BKt + APAD];
    typedef __half (*BsT)[BKt][BNt + BPAD];
    AsT As = reinterpret_cast<AsT>(sraw);
    BsT Bs = reinterpret_cast<BsT>(sraw + AS_BYTES);

    int parity = blockIdx.z;
    const __half* A  = parity ? g_ac : g_st;
    const __half* Bm = parity ? g_aew : g_sew;
    const float* bias = parity ? bias_a : bias_s;
    int K = parity ? Aa : DSs;
    int N = Cc;

    int tid = threadIdx.x;
    int wid = tid >> 5;
    int wm = wid >> 2;
    int wn = wid & 3;
    int mBase = blockIdx.y * BM;
    int nBase = blockIdx.x * BNt;

    wmma::fragment<wmma::accumulator, 16, 16, 16, float> cf[4][2];
#pragma unroll
    for (int i = 0; i < 4; i++)
#pragma unroll
        for (int j = 0; j < 2; j++) wmma::fill_fragment(cf[i][j], 0.0f);

    int a_row[2], a_col[2], b_row[2], b_col[2];
#pragma unroll
    for (int u = 0; u < 2; u++) {
        int idx = tid + u * 256;
        a_row[u] = idx >> 2;
        a_col[u] = (idx & 3) * 8;
        b_row[u] = idx >> 4;
        b_col[u] = (idx & 15) * 8;
    }

    int ktiles = K / BKt;
    uint4 ra[2], rb[2];
#pragma unroll
    for (int u = 0; u < 2; u++) {
        ra[u] = (a_col[u] < K) ? *(const uint4*)(A + (size_t)(mBase + a_row[u]) * K + a_col[u])
                               : make_uint4(0, 0, 0, 0);
        rb[u] = *(const uint4*)(Bm + (size_t)b_row[u] * N + nBase + b_col[u]);
    }
#pragma unroll
    for (int u = 0; u < 2; u++) {
        if (a_col[u] < BKt) *(uint4*)&As[0][a_row[u]][a_col[u]] = ra[u];
        *(uint4*)&Bs[0][b_row[u]][b_col[u]] = rb[u];
    }
    __syncthreads();

    for (int kt = 0; kt < ktiles; kt++) {
        int cur = kt & 1, nxt = cur ^ 1;
        if (kt + 1 < ktiles) {
            int k0 = (kt + 1) * BKt;
#pragma unroll
            for (int u = 0; u < 2; u++) {
                ra[u] = *(const uint4*)(A + (size_t)(mBase + a_row[u]) * K + k0 + a_col[u]);
                rb[u] = *(const uint4*)(Bm + (size_t)(k0 + b_row[u]) * N + nBase + b_col[u]);
            }
        }
#pragma unroll
        for (int kk = 0; kk < BKt; kk += 16) {
            wmma::fragment<wmma::matrix_a, 16, 16, 16, __half, wmma::row_major> af[4];
            wmma::fragment<wmma::matrix_b, 16, 16, 16, __half, wmma::row_major> bf[2];
#pragma unroll
            for (int i = 0; i < 4; i++)
                wmma::load_matrix_sync(af[i], &As[cur][wm * 64 + i * 16][kk], BKt + APAD);
#pragma unroll
            for (int j = 0; j < 2; j++)
                wmma::load_matrix_sync(bf[j], &Bs[cur][kk][wn * 32 + j * 16], BNt + BPAD);
#pragma unroll
            for (int i = 0; i < 4; i++)
#pragma unroll
                for (int j = 0; j < 2; j++)
                    wmma::mma_sync(cf[i][j], af[i], bf[j], cf[i][j]);
        }
        if (kt + 1 < ktiles) {
            __syncthreads();
#pragma unroll
            for (int u = 0; u < 2; u++) {
                *(uint4*)&As[nxt][a_row[u]][a_col[u]] = ra[u];
                *(uint4*)&Bs[nxt][b_row[u]][b_col[u]] = rb[u];
            }
            __syncthreads();
        }
    }

    __syncthreads();
    float* Epi = reinterpret_cast<float*>(sraw);
#pragma unroll 1
    for (int p = 0; p < 2; p++) {
        if (wm == p) {
#pragma unroll
            for (int i = 0; i < 4; i++)
#pragma unroll
                for (int j = 0; j < 2; j++)
                    wmma::store_matrix_sync(&Epi[(i * 16) * 132 + wn * 32 + j * 16],
                                            cf[i][j], 132, wmma::mem_row_major);
        }
        __syncthreads();
#pragma unroll
        for (int it = 0; it < 8; it++) {
            int idx = tid + it * 256;
            int r = idx >> 5;
            int c4 = (idx & 31) * 4;
            int grow = mBase + p * 64 + r;
            int gcol = nBase + c4;
            float4 vv = *(float4*)&Epi[r * 132 + c4];
            int bn2 = grow >> 6, t = grow & 63, b = bn2 >> 4;
            int s2 = 2 * t + parity;
            int tsv = ts[b * Tt + t];
            const float4 pef = *(const float4*)(pe + (size_t)s2 * Cc + gcol);
            const float4 gf  = *(const float4*)(gpe + (size_t)tsv * Cc + gcol);
            float* Cp = xout + ((size_t)bn2 * Ss + s2) * Cc + gcol;
            *(float4*)Cp = make_float4(vv.x + bias[gcol + 0] + pef.x + gf.x,
                                       vv.y + bias[gcol + 1] + pef.y + gf.y,
                                       vv.z + bias[gcol + 2] + pef.z + gf.z,
                                       vv.w + bias[gcol + 3] + pef.w + gf.w);
        }
        __syncthreads();
    }
}

// ---------------- LayerNorm fp32 -> fp16, one warp per row; optional row-126 gather ----------------
template <int GATHER>
__global__ void __launch_bounds__(256) ln_f2h(const float* __restrict__ x,
                                              const float* __restrict__ w,
                                              const float* __restrict__ bb,
                                              __half* __restrict__ out) {
    int wid = threadIdx.x >> 5, lane = threadIdx.x & 31;
    size_t row = (size_t)blockIdx.x * 8 + wid;
    const float* xr = x + row * Cc;
    float v[32];
    float s = 0.f, ss = 0.f;
#pragma unroll
    for (int j = 0; j < 8; j++) {
        float4 f = *(const float4*)(xr + j * 128 + lane * 4);
        v[j * 4 + 0] = f.x; v[j * 4 + 1] = f.y; v[j * 4 + 2] = f.z; v[j * 4 + 3] = f.w;
        s  += f.x + f.y + f.z + f.w;
        ss += f.x * f.x + f.y * f.y + f.z * f.z + f.w * f.w;
    }
#pragma unroll
    for (int o = 16; o > 0; o >>= 1) {
        s  += __shfl_xor_sync(0xffffffffu, s, o);
        ss += __shfl_xor_sync(0xffffffffu, ss, o);
    }
    float mean = s * (1.0f / Cc);
    float var = ss * (1.0f / Cc) - mean * mean;
    float rstd = rsqrtf(var + 1e-5f);
    __half* orow = out + row * Cc;
    bool g126 = GATHER && ((row & (Ss - 1)) == Ss - 2);
    int bn = (int)(row >> 7);
#pragma unroll
    for (int j = 0; j < 8; j++) {
        int c = j * 128 + lane * 4;
        float4 wf = *(const float4*)(w + c);
        float4 bf = *(const float4*)(bb + c);
        float o0 = (v[j * 4 + 0] - mean) * rstd * wf.x + bf.x;
        float o1 = (v[j * 4 + 1] - mean) * rstd * wf.y + bf.y;
        float o2 = (v[j * 4 + 2] - mean) * rstd * wf.z + bf.z;
        float o3 = (v[j * 4 + 3] - mean) * rstd * wf.w + bf.w;
        __half2 h0 = __floats2half2_rn(o0, o1);
        __half2 h1 = __floats2half2_rn(o2, o3);
        *(__half2*)(orow + c)     = h0;
        *(__half2*)(orow + c + 2) = h1;
        if (g126) {
            *(__half2*)(g_hq126 + (size_t)bn * Cc + c)     = h0;
            *(__half2*)(g_hq126 + (size_t)bn * Cc + c + 2) = h1;
            *(float4*)(g_x126 + (size_t)bn * Cc + c) =
                make_float4(v[j * 4 + 0], v[j * 4 + 1], v[j * 4 + 2], v[j * 4 + 3]);
        }
    }
}

// ---------------- HMMA GEMM: MT x 128 CTA tile, 4 warps (MT/2 x 64 each), 3-stage cp.async ----------------
#define GBK 64
#define GSTG 3

template <int OUTHALF, int DOGELU, int DORES, int MT, int KDIM>
__global__ void __launch_bounds__(128, MT == 64 ? 3 : 2)
gemm_mma(const __half* __restrict__ A,
         const __half* __restrict__ Bt,
         const float* __restrict__ bias,
         const float* __restrict__ res,
         void* __restrict__ Cout,
         int N) {
    constexpr int MI = MT / 32;                    // 4 or 2
    constexpr int STAGE_B = (MT + 128) * 128;      // bytes per stage
    constexpr int ACH = MT * 8;                    // A chunks per stage
    constexpr int TOTCH = ACH + 1024;              // total 16B chunks
    constexpr int JN = TOTCH / 128;
    constexpr int KT = KDIM / GBK;

    extern __shared__ unsigned char gsm[];
    uint32_t sbase = smem_to_u32(gsm);
    const int tid = threadIdx.x;
    const int wid = tid >> 5;
    const int lane = tid & 31;
    const int wm = wid & 1;
    const int wn = wid >> 1;
    const int mBase = blockIdx.y * MT;
    const int nBase = blockIdx.x * 128;

    float acc[MI][8][4];
#pragma unroll
    for (int i = 0; i < MI; i++)
#pragma unroll
        for (int j = 0; j < 8; j++)
#pragma unroll
            for (int r = 0; r < 4; r++) acc[i][j][r] = 0.f;

    auto load_stage = [&](int kt) {
        int k0 = kt * GBK;
        uint32_t ab = sbase + (uint32_t)(kt % GSTG) * STAGE_B;
        uint32_t bb = ab + (uint32_t)(MT * 128);
#pragma unroll
        for (int j = 0; j < JN; j++) {
            int id = tid + j * 128;
            if (id < ACH) {
                int row = id >> 3;
                int c16 = id & 7;
                uint32_t sw = sw_off((uint32_t)(row * 128 + c16 * 16));
                cp_async16(ab + sw, A + (size_t)(mBase + row) * KDIM + k0 + c16 * 8);
            } else {
                int idx = id - ACH;
                int row = idx >> 3;
                int c16 = idx & 7;
                uint32_t sw = sw_off((uint32_t)(row * 128 + c16 * 16));
                cp_async16(bb + sw, Bt + (size_t)(nBase + row) * KDIM + k0 + c16 * 8);
            }
        }
    };

    load_stage(0); cp_commit();
    load_stage(1); cp_commit();

#pragma unroll 2
    for (int kt = 0; kt < KT; kt++) {
        CP_WAIT_GROUP(1);
        __syncthreads();
        if (kt + 2 < KT) load_stage(kt + 2);
        cp_commit();

        uint32_t ab = sbase + (uint32_t)(kt % GSTG) * STAGE_B;
        uint32_t bb = ab + (uint32_t)(MT * 128);
#pragma unroll
        for (int ks = 0; ks < 4; ks++) {
            uint32_t a_r[MI][4];
            uint32_t b_r[8][2];
#pragma unroll
            for (int mi = 0; mi < MI; mi++) {
                int row = wm * (MT / 2) + mi * 16 + (lane & 15);
                int kc = ks * 2 + (lane >> 4);
                ldmatrix_x4(a_r[mi], ab + sw_off((uint32_t)(row * 128 + kc * 16)));
            }
#pragma unroll
            for (int bj = 0; bj < 4; bj++) {
                int nrow = wn * 64 + bj * 16 + (lane & 7) + ((lane >> 4) & 1) * 8;
                int kc = ks * 2 + ((lane >> 3) & 1);
                uint32_t r[4];
                ldmatrix_x4(r, bb + sw_off((uint32_t)(nrow * 128 + kc * 16)));
                b_r[bj * 2 + 0][0] = r[0]; b_r[bj * 2 + 0][1] = r[1];
                b_r[bj * 2 + 1][0] = r[2]; b_r[bj * 2 + 1][1] = r[3];
            }
#pragma unroll
            for (int mi = 0; mi < MI; mi++)
#pragma unroll
                for (int ni = 0; ni < 8; ni++)
                    mma_16816(acc[mi][ni], a_r[mi], b_r[ni]);
        }
    }

#pragma unroll
    for (int mi = 0; mi < MI; mi++) {
#pragma unroll
        for (int ni = 0; ni < 8; ni++) {
            int r0 = mBase + wm * (MT / 2) + mi * 16 + (lane >> 2);
            int c0 = nBase + wn * 64 + ni * 8 + 2 * (lane & 3);
            float b0 = bias[c0], b1 = bias[c0 + 1];
#pragma unroll
            for (int half_ = 0; half_ < 2; half_++) {
                int row = r0 + half_ * 8;
                float o0 = acc[mi][ni][half_ * 2 + 0] + b0;
                float o1 = acc[mi][ni][half_ * 2 + 1] + b1;
                if (DOGELU) { o0 = gelu_f(o0); o1 = gelu_f(o1); }
                if (DORES) {
                    const float* rp = res + (size_t)row * N + c0;
                    o0 += rp[0]; o1 += rp[1];
                }
                if (OUTHALF) {
                    *(__half2*)((__half*)Cout + (size_t)row * N + c0) = __floats2half2_rn(o0, o1);
                } else {
                    *(float2*)((float*)Cout + (size_t)row * N + c0) = make_float2(o0, o1);
                }
            }
        }
    }
}

#define SMEM_MT128 (GSTG * (128 + 128) * 128)   // 98304
#define SMEM_MT64  (GSTG * (64 + 128) * 128)    // 73728

// ---------------- tensor-core attention, P kept in registers (FA-style) ----------------
// smem: K 16K | Q 16K | Vt0 8K | Vt1 8K = 48KB
#define ATT_SMEM 49152

__global__ void __launch_bounds__(128) attn_tc(const __half* __restrict__ qkv,
                                               __half* __restrict__ y) {
    extern __shared__ unsigned char asm_[];
    uint32_t sb = smem_to_u32(asm_);
    uint32_t sK = sb, sQ = sb + 16384, sV0 = sb + 32768, sV1 = sb + 40960;
    int tid = threadIdx.x, wid = tid >> 5, lane = tid & 31;
    int bh = blockIdx.x, bn = bh >> 4, h = bh & 15;
    size_t baseq = (size_t)bn * Ss * QKVW + h * Dd;
    size_t basey = (size_t)bn * Ss * Cc + h * Dd;

    for (int idx = tid; idx < 1024; idx += 128) {
        int row = idx >> 3, c = idx & 7;
        uint32_t sw = sw_off((uint32_t)(row * 128 + c * 16));
        cp_async16(sQ + sw, qkv + baseq + (size_t)row * QKVW + c * 8);
        cp_async16(sK + sw, qkv + baseq + Cc + (size_t)row * QKVW + c * 8);
    }
    cp_commit();
    for (int idx = tid; idx < 4096; idx += 128) {
        int kv = idx >> 5, d2 = idx & 31;
        __half2 v2 = *(const __half2*)(qkv + baseq + 2 * Cc + (size_t)kv * QKVW + d2 * 2);
        char* vbp = (char*)asm_ + ((kv < 64) ? 32768 : 40960);
        int kc = kv & 63;
        *(__half*)(vbp + sw_off((uint32_t)((d2 * 2) * 128 + kc * 2)))     = __low2half(v2);
        *(__half*)(vbp + sw_off((uint32_t)((d2 * 2 + 1) * 128 + kc * 2))) = __high2half(v2);
    }
    CP_WAIT_GROUP(0);
    __syncthreads();

    int qb = wid * 32;
    float accS[2][16][4];
#pragma unroll
    for (int mi = 0; mi < 2; mi++)
#pragma unroll
        for (int ni = 0; ni < 16; ni++)
#pragma unroll
            for (int r = 0; r < 4; r++) accS[mi][ni][r] = 0.f;

#pragma unroll
    for (int ks = 0; ks < 4; ks++) {
        uint32_t a[2][4], b[16][2];
#pragma unroll
        for (int mi = 0; mi < 2; mi++) {
            int row = qb + mi * 16 + (lane & 15);
            int kc = ks * 2 + (lane >> 4);
            ldmatrix_x4(a[mi], sQ + sw_off((uint32_t)(row * 128 + kc * 16)));
        }
#pragma unroll
        for (int bj = 0; bj < 8; bj++) {
            int nrow = bj * 16 + (lane & 7) + ((lane >> 4) & 1) * 8;
            int kc = ks * 2 + ((lane >> 3) & 1);
            uint32_t r[4];
            ldmatrix_x4(r, sK + sw_off((uint32_t)(nrow * 128 + kc * 16)));
            b[bj * 2 + 0][0] = r[0]; b[bj * 2 + 0][1] = r[1];
            b[bj * 2 + 1][0] = r[2]; b[bj * 2 + 1][1] = r[3];
        }
#pragma unroll
        for (int mi = 0; mi < 2; mi++)
#pragma unroll
            for (int ni = 0; ni < 16; ni++)
                mma_16816(accS[mi][ni], a[mi], b[ni]);
    }

    // mask + exp + row sums; pack P straight into A-fragments (C-layout == A-layout)
    uint32_t pf[2][16][2];
    float inv[2][2];
#pragma unroll
    for (int mi = 0; mi < 2; mi++) {
        float s0 = 0.f, s1 = 0.f;
        int rA = qb + mi * 16 + (lane >> 2);
        int rB = rA + 8;
#pragma unroll
        for (int ni = 0; ni < 16; ni++) {
            int c0 = ni * 8 + 2 * (lane & 3);
            float p00 = (c0     <= rA) ? __expf(accS[mi][ni][0] * 0.125f) : 0.f;
            float p01 = (c0 + 1 <= rA) ? __expf(accS[mi][ni][1] * 0.125f) : 0.f;
            float p10 = (c0     <= rB) ? __expf(accS[mi][ni][2] * 0.125f) : 0.f;
            float p11 = (c0 + 1 <= rB) ? __expf(accS[mi][ni][3] * 0.125f) : 0.f;
            s0 += p00 + p01; s1 += p10 + p11;
            pf[mi][ni][0] = h2_as_u32(__floats2half2_rn(p00, p01));
            pf[mi][ni][1] = h2_as_u32(__floats2half2_rn(p10, p11));
        }
        s0 += __shfl_xor_sync(0xffffffffu, s0, 1);
        s0 += __shfl_xor_sync(0xffffffffu, s0, 2);
        s1 += __shfl_xor_sync(0xffffffffu, s1, 1);
        s1 += __shfl_xor_sync(0xffffffffu, s1, 2);
        inv[mi][0] = 1.0f / s0;
        inv[mi][1] = 1.0f / s1;
    }

    // O = P V with P in registers
    float accO[2][8][4];
#pragma unroll
    for (int mi = 0; mi < 2; mi++)
#pragma unroll
        for (int ni = 0; ni < 8; ni++)
#pragma unroll
            for (int r = 0; r < 4; r++) accO[mi][ni][r] = 0.f;

#pragma unroll
    for (int ks = 0; ks < 8; ks++) {
        uint32_t vbase = (ks < 4) ? sV0 : sV1;
        int kss = ks & 3;
        uint32_t b[8][2];
#pragma unroll
        for (int bj = 0; bj < 4; bj++) {
            int nrow = bj * 16 + (lane & 7) + ((lane >> 4) & 1) * 8;
            int kc = kss * 2 + ((lane >> 3) & 1);
            uint32_t r[4];
            ldmatrix_x4(r, vbase + sw_off((uint32_t)(nrow * 128 + kc * 16)));
            b[bj * 2 + 0][0] = r[0]; b[bj * 2 + 0][1] = r[1];
            b[bj * 2 + 1][0] = r[2]; b[bj * 2 + 1][1] = r[3];
        }
#pragma unroll
        for (int mi = 0; mi < 2; mi++) {
            uint32_t a[4] = { pf[mi][2 * ks][0], pf[mi][2 * ks][1],
                              pf[mi][2 * ks + 1][0], pf[mi][2 * ks + 1][1] };
#pragma unroll
            for (int ni = 0; ni < 8; ni++)
                mma_16816(accO[mi][ni], a, b[ni]);
        }
    }

#pragma unroll
    for (int mi = 0; mi < 2; mi++) {
#pragma unroll
        for (int ni = 0; ni < 8; ni++) {
            int rA = qb + mi * 16 + (lane >> 2);
            int c0 = ni * 8 + 2 * (lane & 3);
            *(__half2*)(y + basey + (size_t)rA * Cc + c0) =
                __floats2half2_rn(accO[mi][ni][0] * inv[mi][0], accO[mi][ni][1] * inv[mi][0]);
            *(__half2*)(y + basey + (size_t)(rA + 8) * Cc + c0) =
                __floats2half2_rn(accO[mi][ni][2] * inv[mi][1], accO[mi][ni][3] * inv[mi][1]);
        }
    }
}

// ---------------- last-layer single-query attention: block per (bn,h) ----------------
__global__ void __launch_bounds__(128) attn_last(const __half* __restrict__ qkv,
                                                 const __half* __restrict__ q126,
                                                 __half* __restrict__ y126) {
    __shared__ float qs[Dd];
    __shared__ float e[Ss];
    __shared__ float ws[4];
    int tid = threadIdx.x, wid = tid >> 5, lane = tid & 31;
    int bh = blockIdx.x, bn = bh >> 4, h = bh & 15;
    size_t base = (size_t)bn * Ss * QKVW + h * Dd;

    if (tid < 32) {
        float2 f = __half22float2(*(const __half2*)(q126 + (size_t)bn * Cc + h * Dd + tid * 2));
        qs[tid * 2] = f.x; qs[tid * 2 + 1] = f.y;
    }
    __syncthreads();

    int j = tid;
    float ej = 0.f;
    if (j <= Ss - 2) {
        const __half* kr = qkv + base + Cc + (size_t)j * QKVW;
        float s = 0.f;
#pragma unroll
        for (int i = 0; i < Dd; i++) s += qs[i] * __half2float(kr[i]);
        ej = __expf(s * 0.125f);
    }
    e[j] = ej;
    float s = ej;
#pragma unroll
    for (int o = 16; o > 0; o >>= 1) s += __shfl_xor_sync(0xffffffffu, s, o);
    if (lane == 0) ws[wid] = s;
    __syncthreads();
    float sum = ws[0] + ws[1] + ws[2] + ws[3];

    if (tid < Dd) {
        float acc = 0.f;
        for (int k = 0; k <= Ss - 2; k++)
            acc += e[k] * __half2float(qkv[base + 2 * Cc + (size_t)k * QKVW + tid]);
        y126[(size_t)bn * Cc + h * Dd + tid] = __float2half(acc / sum);
    }
}

// ---------------- final LN + head (compact x126 input) ----------------
__global__ void __launch_bounds__(256) head_kernel(const float* __restrict__ x,
                                                   const float* __restrict__ lnw,
                                                   const float* __restrict__ lnb,
                                                   const float* __restrict__ headW,
                                                   float* __restrict__ out) {
    int bn = blockIdx.x;
    const float* xr = x + (size_t)bn * Cc;
    __shared__ float hsm[Cc];
    int c0 = threadIdx.x * 4;
    float4 f = *(const float4*)(xr + c0);
    float s = f.x + f.y + f.z + f.w;
    float ss = f.x * f.x + f.y * f.y + f.z * f.z + f.w * f.w;
#pragma unroll
    for (int o = 16; o > 0; o >>= 1) {
        s  += __shfl_xor_sync(0xffffffffu, s, o);
        ss += __shfl_xor_sync(0xffffffffu, ss, o);
    }
    __shared__ float rs[8], rss[8];
    int wrp = threadIdx.x >> 5, lane = threadIdx.x & 31;
    if (lane == 0) { rs[wrp] = s; rss[wrp] = ss; }
    __syncthreads();
    s = 0.f; ss = 0.f;
#pragma unroll
    for (int qq = 0; qq < 8; qq++) { s += rs[qq]; ss += rss[qq]; }
    float mean = s * (1.0f / Cc);
    float var = ss * (1.0f / Cc) - mean * mean;
    float rstd = rsqrtf(var + 1e-5f);
    float4 wf = *(const float4*)(lnw + c0);
    float4 bf = *(const float4*)(lnb + c0);
    hsm[c0 + 0] = (f.x - mean) * rstd * wf.x + bf.x;
    hsm[c0 + 1] = (f.y - mean) * rstd * wf.y + bf.y;
    hsm[c0 + 2] = (f.z - mean) * rstd * wf.z + bf.z;
    hsm[c0 + 3] = (f.w - mean) * rstd * wf.w + bf.w;
    __syncthreads();
    if (threadIdx.x < Aa) {
        int a = threadIdx.x;
        float acc = 0.f;
        for (int c = 0; c < Cc; c++) acc += hsm[c] * headW[c * Aa + a];
        out[bn * Aa + a] = acc;
    }
}

// ---------------- host launch ----------------
extern "C" void kernel_launch(void* const* d_in, const int* in_sizes, int n_in,
                              void* d_out, int out_size) {
    const float* states     = (const float*)d_in[0];
    const float* actions    = (const float*)d_in[1];
    const int*   timesteps  = (const int*)d_in[2];
    const float* pos_emb    = (const float*)d_in[3];
    const float* gpe        = (const float*)d_in[4];
    const float* seW        = (const float*)d_in[5];
    const float* seb        = (const float*)d_in[6];
    const float* aeW        = (const float*)d_in[7];
    const float* aeb        = (const float*)d_in[8];
    const float* ln1w       = (const float*)d_in[9];
    const float* ln1b       = (const float*)d_in[10];
    const float* Wq         = (const float*)d_in[11];
    const float* bq         = (const float*)d_in[12];
    const float* Wk         = (const float*)d_in[13];
    const float* bk         = (const float*)d_in[14];
    const float* Wv         = (const float*)d_in[15];
    const float* bv         = (const float*)d_in[16];
    const float* Wp         = (const float*)d_in[17];
    const float* bp         = (const float*)d_in[18];
    const float* ln2w       = (const float*)d_in[19];
    const float* ln2b       = (const float*)d_in[20];
    const float* W1         = (const float*)d_in[21];
    const float* b1         = (const float*)d_in[22];
    const float* W2         = (const float*)d_in[23];
    const float* b2         = (const float*)d_in[24];
    const float* lnfw       = (const float*)d_in[25];
    const float* lnfb       = (const float*)d_in[26];
    const float* headW      = (const float*)d_in[27];

    void *p_x, *p_h, *p_qkv, *p_y, *p_mid;
    void *p_wqkv, *p_bqkv, *p_wp, *p_w1, *p_w2;
    void *p_hq126, *p_x126, *p_q126, *p_y126, *p_h126, *p_mid126;
    cudaGetSymbolAddress(&p_x, g_x);       cudaGetSymbolAddress(&p_h, g_h);
    cudaGetSymbolAddress(&p_qkv, g_qkv);   cudaGetSymbolAddress(&p_y, g_y);
    cudaGetSymbolAddress(&p_mid, g_mid);   cudaGetSymbolAddress(&p_wqkv, g_wqkv);
    cudaGetSymbolAddress(&p_bqkv, g_bqkv); cudaGetSymbolAddress(&p_wp, g_wp);
    cudaGetSymbolAddress(&p_w1, g_w1);     cudaGetSymbolAddress(&p_w2, g_w2);
    cudaGetSymbolAddress(&p_hq126, g_hq126); cudaGetSymbolAddress(&p_x126, g_x126);
    cudaGetSymbolAddress(&p_q126, g_q126);   cudaGetSymbolAddress(&p_y126, g_y126);
    cudaGetSymbolAddress(&p_h126, g_h126);   cudaGetSymbolAddress(&p_mid126, g_mid126);

    float*  xbuf = (float*)p_x;
    __half* hbuf = (__half*)p_h;
    __half* qkvb = (__half*)p_qkv;
    __half* ybuf = (__half*)p_y;
    __half* midb = (__half*)p_mid;

    cudaFuncSetAttribute((gemm_mma<1, 0, 0, 128, Cc>), cudaFuncAttributeMaxDynamicSharedMemorySize, SMEM_MT128);
    cudaFuncSetAttribute((gemm_mma<1, 1, 0, 128, Cc>), cudaFuncAttributeMaxDynamicSharedMemorySize, SMEM_MT128);
    cudaFuncSetAttribute((gemm_mma<0, 0, 1, 64, Cc>),  cudaFuncAttributeMaxDynamicSharedMemorySize, SMEM_MT64);
    cudaFuncSetAttribute((gemm_mma<0, 0, 1, 64, 4 * Cc>), cudaFuncAttributeMaxDynamicSharedMemorySize, SMEM_MT64);
    cudaFuncSetAttribute(attn_tc, cudaFuncAttributeMaxDynamicSharedMemorySize, ATT_SMEM);

    // ours#1: all weight transposes + gathers + embed weights + bias concat
    wconv_all<<<WCONV_BLOCKS, 256>>>(Wq, Wk, Wv, Wp, W1, W2,
                                     states, actions, seW, aeW, bq, bk, bv);
    // ours#2: both embed GEMMs (z = parity) with fused assemble
    gemm_embed<<<dim3(Cc / BNt, 8192 / BM, 2), 256>>>(seb, aeb, pos_emb, gpe, timesteps, xbuf);

    for (int l = 0; l < Ll; l++) {
        size_t wo  = (size_t)l * Cc * Cc;
        size_t wq3 = (size_t)l * 3 * Cc * Cc;
        size_t w1o = (size_t)l * Cc * 4 * Cc;
        size_t bo  = (size_t)l * Cc;
        size_t b1o = (size_t)l * 4 * Cc;

        if (l < Ll - 1) {
            ln_f2h<0><<<Rr / 8, 256>>>(xbuf, ln1w + bo, ln1b + bo, hbuf);

            // full QKV
            gemm_mma<1, 0, 0, 128, Cc><<<dim3(3 * Cc / 128, Rr / 128), 128, SMEM_MT128>>>(
                hbuf, (__half*)p_wqkv + wq3, (float*)p_bqkv + (size_t)l * 3 * Cc,
                nullptr, p_qkv, 3 * Cc);

            attn_tc<<<BNn * Hh, 128, ATT_SMEM>>>(qkvb, ybuf);

            gemm_mma<0, 0, 1, 64, Cc><<<dim3(Cc / 128, Rr / 64), 128, SMEM_MT64>>>(
                ybuf, (__half*)p_wp + wo, bp + bo, xbuf, p_x, Cc);

            ln_f2h<0><<<Rr / 8, 256>>>(xbuf, ln2w + bo, ln2b + bo, hbuf);

            gemm_mma<1, 1, 0, 128, Cc><<<dim3(4 * Cc / 128, Rr / 128), 128, SMEM_MT128>>>(
                hbuf, (__half*)p_w1 + w1o, b1 + b1o, nullptr, p_mid, 4 * Cc);
            gemm_mma<0, 0, 1, 64, 4 * Cc><<<dim3(Cc / 128, Rr / 64), 128, SMEM_MT64>>>(
                midb, (__half*)p_w2 + w1o, b2 + bo, xbuf, p_x, Cc);
        } else {
            // last layer: only row S-2 of each bn feeds the output
            // LN1 with fused row-126 gather (writes g_hq126 + g_x126)
            ln_f2h<1><<<Rr / 8, 256>>>(xbuf, ln1w + bo, ln1b + bo, hbuf);

            // k,v for all rows (columns [C, 3C) of qkv)
            gemm_mma<1, 0, 0, 128, Cc><<<dim3(2 * Cc / 128, Rr / 128), 128, SMEM_MT128>>>(
                hbuf, (__half*)p_wqkv + wq3 + (size_t)Cc * Cc,
                (float*)p_bqkv + (size_t)l * 3 * Cc + Cc,
                nullptr, (void*)((__half*)p_qkv + Cc), 3 * Cc);
            // q only for the 128 gathered rows
            gemm_mma<1, 0, 0, 128, Cc><<<dim3(Cc / 128, 1), 128, SMEM_MT128>>>(
                (__half*)p_hq126, (__half*)p_wqkv + wq3,
                (float*)p_bqkv + (size_t)l * 3 * Cc,
                nullptr, p_q126, Cc);

            attn_last<<<BNn * Hh, 128>>>(qkvb, (__half*)p_q126, (__half*)p_y126);

            // proj + residual (compact, in-place on x126)
            gemm_mma<0, 0, 1, 64, Cc><<<dim3(Cc / 128, BNn / 64), 128, SMEM_MT64>>>(
                (__half*)p_y126, (__half*)p_wp + wo, bp + bo,
                (float*)p_x126, p_x126, Cc);

            ln_f2h<0><<<BNn / 8, 256>>>((float*)p_x126, ln2w + bo, ln2b + bo, (__half*)p_h126);

            gemm_mma<1, 1, 0, 128, Cc><<<dim3(4 * Cc / 128, 1), 128, SMEM_MT128>>>(
                (__half*)p_h126, (__half*)p_w1 + w1o, b1 + b1o,
                nullptr, p_mid126, 4 * Cc);
            gemm_mma<0, 0, 1, 64, 4 * Cc><<<dim3(Cc / 128, BNn / 64), 128, SMEM_MT64>>>(
                (__half*)p_mid126, (__half*)p_w2 + w1o, b2 + bo,
                (float*)p_x126, p_x126, Cc);
        }
    }

    head_kernel<<<BNn, 256>>>((float*)p_x126, lnfw, lnfb, headW, (float*)d_out);
}

// round 15
// speedup vs baseline: 1.1976x; 1.0029x over previous
#include <cuda_runtime.h>
#include <cuda_fp16.h>
#include <mma.h>
#include <math.h>
#include <stdint.h>

using namespace nvcuda;

// ---------------- problem dims ----------------
#define Bb 8
#define Tt 64
#define Nn 16
#define DSs 128
#define Aa 32
#define Cc 1024
#define Hh 16
#define Ll 8
#define Ss 128            // 2*T
#define BNn 128           // B*N
#define Rr 16384          // BN*S
#define Dd 64             // head dim
#define QKVW (3 * Cc)     // fused qkv row width

// ---------------- scratch (device globals; no allocation allowed) ----------------
__device__ float   g_x[Rr * Cc];            // residual stream (fp32)
__device__ __half  g_h[Rr * Cc];            // LN output (fp16)
__device__ __half  g_qkv[Rr * 3 * Cc];      // fused q|k|v (fp16)
__device__ __half  g_y[Rr * Cc];
__device__ __half  g_mid[Rr * 4 * Cc];
__device__ __half  g_st[BNn * Tt * DSs];
__device__ __half  g_ac[BNn * Tt * Aa];
__device__ __half  g_wqkv[Ll * 3 * Cc * Cc];   // transposed [3C, C] per layer
__device__ float   g_bqkv[Ll * 3 * Cc];
__device__ __half  g_wp[Ll * Cc * Cc];         // transposed [N,K]
__device__ __half  g_w1[Ll * Cc * 4 * Cc];     // transposed [4C, C]
__device__ __half  g_w2[Ll * 4 * Cc * Cc];     // transposed [C, 4C]
__device__ __half  g_sew[DSs * Cc];            // K-major
__device__ __half  g_aew[Aa * Cc];
// last-layer compact buffers (row 126 of each bn)
__device__ __half  g_hq126[BNn * Cc];
__device__ float   g_x126[BNn * Cc];
__device__ __half  g_q126[BNn * Cc];
__device__ __half  g_y126[BNn * Cc];
__device__ __half  g_h126[BNn * Cc];
__device__ __half  g_mid126[BNn * 4 * Cc];

// ---------------- small helpers ----------------
__device__ __forceinline__ uint32_t smem_to_u32(const void* smem_ptr) {
    uint32_t addr;
    asm("{ .reg .u64 tmp; cvta.to.shared.u64 tmp, %1; cvt.u32.u64 %0, tmp; }"
        : "=r"(addr) : "l"(smem_ptr));
    return addr;
}
__device__ __forceinline__ void cp_async16(uint32_t saddr, const void* gptr) {
    asm volatile("cp.async.cg.shared.global [%0], [%1], 16;" :: "r"(saddr), "l"(gptr));
}
__device__ __forceinline__ void cp_commit() { asm volatile("cp.async.commit_group;" ::: "memory"); }
#define CP_WAIT_GROUP(n) asm volatile("cp.async.wait_group %0;" :: "n"(n) : "memory")

__device__ __forceinline__ uint32_t sw_off(uint32_t off) { return off ^ ((off >> 3) & 0x70u); }

__device__ __forceinline__ uint32_t h2_as_u32(__half2 h) {
    union { __half2 h2; uint32_t u; } cvt;
    cvt.h2 = h;
    return cvt.u;
}

__device__ __forceinline__ void ldmatrix_x4(uint32_t* d, uint32_t addr) {
    asm volatile("ldmatrix.sync.aligned.m8n8.x4.shared.b16 {%0,%1,%2,%3}, [%4];"
                 : "=r"(d[0]), "=r"(d[1]), "=r"(d[2]), "=r"(d[3]) : "r"(addr));
}
__device__ __forceinline__ void mma_16816(float* c, const uint32_t* a, const uint32_t* b) {
    asm volatile("mma.sync.aligned.m16n8k16.row.col.f32.f16.f16.f32 "
                 "{%0,%1,%2,%3}, {%4,%5,%6,%7}, {%8,%9}, {%0,%1,%2,%3};"
                 : "+f"(c[0]), "+f"(c[1]), "+f"(c[2]), "+f"(c[3])
                 : "r"(a[0]), "r"(a[1]), "r"(a[2]), "r"(a[3]), "r"(b[0]), "r"(b[1]));
}

// gelu(x) = 0.5x(1+tanh(z)) = x / (1 + exp(-2z)), exact identity
__device__ __forceinline__ float gelu_f(float x) {
    float x3 = x * x * x;
    float u = __expf(-1.5957691216057308f * (x + 0.044715f * x3));
    return __fdividef(x, 1.0f + u);
}

// ---------------- prep + all weight transposes (ONE kernel), 64x64 tiles ----------------
// trans blocks: qkv 6144 | wp 2048 | w1 8192 | w2 8192 = 24576 ; prep 5856
#define WCONV_TRANS 24576
#define WCONV_BLOCKS (WCONV_TRANS + 5856)
__global__ void __launch_bounds__(256) wconv_all(const float* __restrict__ Wq,
                                                 const float* __restrict__ Wk,
                                                 const float* __restrict__ Wv,
                                                 const float* __restrict__ Wp,
                                                 const float* __restrict__ W1,
                                                 const float* __restrict__ W2,
                                                 const float* __restrict__ states,
                                                 const float* __restrict__ actions,
                                                 const float* __restrict__ seW,
                                                 const float* __restrict__ aeW,
                                                 const float* __restrict__ bq,
                                                 const float* __restrict__ bk,
                                                 const float* __restrict__ bv) {
    __shared__ float tile[64][65];
    int bid = blockIdx.x;
    if (bid >= WCONV_TRANS) {
        int i = (bid - WCONV_TRANS) * 256 + threadIdx.x;
        if (i < 1048576) {
            int ds = i % DSs;
            int row = i / DSs;
            int t = row % Tt;
            int bn = row / Tt;
            int b = bn / Nn, n = bn % Nn;
            g_st[i] = __float2half(states[(((size_t)b * Tt + t) * Nn + n) * DSs + ds]);
        } else if (i < 1310720) {
            int j = i - 1048576;
            int a = j % Aa;
            int row = j / Aa;
            int t = row % Tt;
            int bn = row / Tt;
            int b = bn / Nn, n = bn % Nn;
            g_ac[j] = __float2half(actions[(((size_t)b * Tt + t) * Nn + n) * Aa + a]);
        } else if (i < 1441792) {
            int j = i - 1310720;
            g_sew[j] = __float2half(seW[j]);
        } else if (i < 1474560) {
            int j = i - 1441792;
            g_aew[j] = __float2half(aeW[j]);
        } else {
            int j = i - 1474560;            // < Ll*3*Cc
            int l = j / (3 * Cc);
            int k = j - l * 3 * Cc;
            float v = (k < Cc) ? bq[l * Cc + k]
                    : (k < 2 * Cc) ? bk[l * Cc + k - Cc]
                                   : bv[l * Cc + k - 2 * Cc];
            g_bqkv[j] = v;
        }
        return;
    }
    const float* src;
    __half* dst;
    int K, N, bx, by;
    if (bid < 6144) {                   // qkv: 3 x 8 layers x (16 n-tiles x 16 k-tiles)
        int which = bid >> 11;          // /2048
        int r = bid & 2047;
        int layer = r >> 8;
        int rt = r & 255;
        bx = rt & 15; by = rt >> 4; K = Cc; N = Cc;
        src = (which == 0 ? Wq : which == 1 ? Wk : Wv) + (size_t)layer * Cc * Cc;
        dst = g_wqkv + (size_t)layer * 3 * Cc * Cc + (size_t)which * Cc * Cc;
    } else if (bid < 8192) {            // wp: 8 x 256
        int r = bid - 6144;
        int layer = r >> 8;
        int rt = r & 255;
        bx = rt & 15; by = rt >> 4; K = Cc; N = Cc;
        src = Wp + (size_t)layer * Cc * Cc;
        dst = g_wp + (size_t)layer * Cc * Cc;
    } else if (bid < 16384) {           // w1: 8 x (64 n-tiles x 16 k-tiles)
        int r = bid - 8192;
        int layer = r >> 10;
        int rt = r & 1023;
        bx = rt & 63; by = rt >> 6; K = Cc; N = 4 * Cc;
        src = W1 + (size_t)layer * Cc * 4 * Cc;
        dst = g_w1 + (size_t)layer * Cc * 4 * Cc;
    } else {                            // w2: 8 x (16 n-tiles x 64 k-tiles)
        int r = bid - 16384;
        int layer = r >> 10;
        int rt = r & 1023;
        bx = rt & 15; by = rt >> 4; K = 4 * Cc; N = Cc;
        src = W2 + (size_t)layer * 4 * Cc * Cc;
        dst = g_w2 + (size_t)layer * 4 * Cc * Cc;
    }
    int nb = bx * 64, kb = by * 64;
    int tx = threadIdx.x & 63, ty = threadIdx.x >> 6;   // 64 x 4
#pragma unroll
    for (int r = 0; r < 64; r += 4)
        tile[ty + r][tx] = src[(size_t)(kb + ty + r) * N + nb + tx];
    __syncthreads();
#pragma unroll
    for (int r = 0; r < 64; r += 4)
        dst[(size_t)(nb + ty + r) * K + kb + tx] = __float2half(tile[tx][ty + r]);
}

// ---------------- embed GEMM (wmma) with fused assemble epilogue; z=0 state, z=1 action ----------------
#define BM 128
#define BNt 128
#define BKt 32
#define APAD 8
#define BPAD 8
#define AS_BYTES (2 * BM * (BKt + APAD) * 2)
#define BS_BYTES (2 * BKt * (BNt + BPAD) * 2)

__global__ void __launch_bounds__(256) gemm_embed(const float* __restrict__ bias_s,
                                                  const float* __restrict__ bias_a,
                                                  const float* __restrict__ pe,
                                                  const float* __restrict__ gpe,
                                                  const int* __restrict__ ts,
                                                  float* __restrict__ xout) {
    __shared__ __align__(16) unsigned char sraw[AS_BYTES + BS_BYTES];
    typedef __half (*AsT)[BM][BKt + APAD];
    typedef __half (*BsT)[BKt][BNt + BPAD];
    AsT As = reinterpret_cast<AsT>(sraw);
    BsT Bs = reinterpret_cast<BsT>(sraw + AS_BYTES);

    int parity = blockIdx.z;
    const __half* A  = parity ? g_ac : g_st;
    const __half* Bm = parity ? g_aew : g_sew;
    const float* bias = parity ? bias_a : bias_s;
    int K = parity ? Aa : DSs;
    int N = Cc;

    int tid = threadIdx.x;
    int wid = tid >> 5;
    int wm = wid >> 2;
    int wn = wid & 3;
    int mBase = blockIdx.y * BM;
    int nBase = blockIdx.x * BNt;

    wmma::fragment<wmma::accumulator, 16, 16, 16, float> cf[4][2];
#pragma unroll
    for (int i = 0; i < 4; i++)
#pragma unroll
        for (int j = 0; j < 2; j++) wmma::fill_fragment(cf[i][j], 0.0f);

    int a_row[2], a_col[2], b_row[2], b_col[2];
#pragma unroll
    for (int u = 0; u < 2; u++) {
        int idx = tid + u * 256;
        a_row[u] = idx >> 2;
        a_col[u] = (idx & 3) * 8;
        b_row[u] = idx >> 4;
        b_col[u] = (idx & 15) * 8;
    }

    int ktiles = K / BKt;
    uint4 ra[2], rb[2];
#pragma unroll
    for (int u = 0; u < 2; u++) {
        ra[u] = (a_col[u] < K) ? *(const uint4*)(A + (size_t)(mBase + a_row[u]) * K + a_col[u])
                               : make_uint4(0, 0, 0, 0);
        rb[u] = *(const uint4*)(Bm + (size_t)b_row[u] * N + nBase + b_col[u]);
    }
#pragma unroll
    for (int u = 0; u < 2; u++) {
        if (a_col[u] < BKt) *(uint4*)&As[0][a_row[u]][a_col[u]] = ra[u];
        *(uint4*)&Bs[0][b_row[u]][b_col[u]] = rb[u];
    }
    __syncthreads();

    for (int kt = 0; kt < ktiles; kt++) {
        int cur = kt & 1, nxt = cur ^ 1;
        if (kt + 1 < ktiles) {
            int k0 = (kt + 1) * BKt;
#pragma unroll
            for (int u = 0; u < 2; u++) {
                ra[u] = *(const uint4*)(A + (size_t)(mBase + a_row[u]) * K + k0 + a_col[u]);
                rb[u] = *(const uint4*)(Bm + (size_t)(k0 + b_row[u]) * N + nBase + b_col[u]);
            }
        }
#pragma unroll
        for (int kk = 0; kk < BKt; kk += 16) {
            wmma::fragment<wmma::matrix_a, 16, 16, 16, __half, wmma::row_major> af[4];
            wmma::fragment<wmma::matrix_b, 16, 16, 16, __half, wmma::row_major> bf[2];
#pragma unroll
            for (int i = 0; i < 4; i++)
                wmma::load_matrix_sync(af[i], &As[cur][wm * 64 + i * 16][kk], BKt + APAD);
#pragma unroll
            for (int j = 0; j < 2; j++)
                wmma::load_matrix_sync(bf[j], &Bs[cur][kk][wn * 32 + j * 16], BNt + BPAD);
#pragma unroll
            for (int i = 0; i < 4; i++)
#pragma unroll
                for (int j = 0; j < 2; j++)
                    wmma::mma_sync(cf[i][j], af[i], bf[j], cf[i][j]);
        }
        if (kt + 1 < ktiles) {
            __syncthreads();
#pragma unroll
            for (int u = 0; u < 2; u++) {
                *(uint4*)&As[nxt][a_row[u]][a_col[u]] = ra[u];
                *(uint4*)&Bs[nxt][b_row[u]][b_col[u]] = rb[u];
            }
            __syncthreads();
        }
    }

    __syncthreads();
    float* Epi = reinterpret_cast<float*>(sraw);
#pragma unroll 1
    for (int p = 0; p < 2; p++) {
        if (wm == p) {
#pragma unroll
            for (int i = 0; i < 4; i++)
#pragma unroll
                for (int j = 0; j < 2; j++)
                    wmma::store_matrix_sync(&Epi[(i * 16) * 132 + wn * 32 + j * 16],
                                            cf[i][j], 132, wmma::mem_row_major);
        }
        __syncthreads();
#pragma unroll
        for (int it = 0; it < 8; it++) {
            int idx = tid + it * 256;
            int r = idx >> 5;
            int c4 = (idx & 31) * 4;
            int grow = mBase + p * 64 + r;
            int gcol = nBase + c4;
            float4 vv = *(float4*)&Epi[r * 132 + c4];
            int bn2 = grow >> 6, t = grow & 63, b = bn2 >> 4;
            int s2 = 2 * t + parity;
            int tsv = ts[b * Tt + t];
            const float4 pef = *(const float4*)(pe + (size_t)s2 * Cc + gcol);
            const float4 gf  = *(const float4*)(gpe + (size_t)tsv * Cc + gcol);
            float* Cp = xout + ((size_t)bn2 * Ss + s2) * Cc + gcol;
            *(float4*)Cp = make_float4(vv.x + bias[gcol + 0] + pef.x + gf.x,
                                       vv.y + bias[gcol + 1] + pef.y + gf.y,
                                       vv.z + bias[gcol + 2] + pef.z + gf.z,
                                       vv.w + bias[gcol + 3] + pef.w + gf.w);
        }
        __syncthreads();
    }
}

// ---------------- LayerNorm fp32 -> fp16, one warp per row; optional row-126 gather ----------------
template <int GATHER>
__global__ void __launch_bounds__(256) ln_f2h(const float* __restrict__ x,
                                              const float* __restrict__ w,
                                              const float* __restrict__ bb,
                                              __half* __restrict__ out) {
    int wid = threadIdx.x >> 5, lane = threadIdx.x & 31;
    size_t row = (size_t)blockIdx.x * 8 + wid;
    const float* xr = x + row * Cc;
    float v[32];
    float s = 0.f, ss = 0.f;
#pragma unroll
    for (int j = 0; j < 8; j++) {
        float4 f = *(const float4*)(xr + j * 128 + lane * 4);
        v[j * 4 + 0] = f.x; v[j * 4 + 1] = f.y; v[j * 4 + 2] = f.z; v[j * 4 + 3] = f.w;
        s  += f.x + f.y + f.z + f.w;
        ss += f.x * f.x + f.y * f.y + f.z * f.z + f.w * f.w;
    }
#pragma unroll
    for (int o = 16; o > 0; o >>= 1) {
        s  += __shfl_xor_sync(0xffffffffu, s, o);
        ss += __shfl_xor_sync(0xffffffffu, ss, o);
    }
    float mean = s * (1.0f / Cc);
    float var = ss * (1.0f / Cc) - mean * mean;
    float rstd = rsqrtf(var + 1e-5f);
    __half* orow = out + row * Cc;
    bool g126 = GATHER && ((row & (Ss - 1)) == Ss - 2);
    int bn = (int)(row >> 7);
#pragma unroll
    for (int j = 0; j < 8; j++) {
        int c = j * 128 + lane * 4;
        float4 wf = *(const float4*)(w + c);
        float4 bf = *(const float4*)(bb + c);
        float o0 = (v[j * 4 + 0] - mean) * rstd * wf.x + bf.x;
        float o1 = (v[j * 4 + 1] - mean) * rstd * wf.y + bf.y;
        float o2 = (v[j * 4 + 2] - mean) * rstd * wf.z + bf.z;
        float o3 = (v[j * 4 + 3] - mean) * rstd * wf.w + bf.w;
        __half2 h0 = __floats2half2_rn(o0, o1);
        __half2 h1 = __floats2half2_rn(o2, o3);
        *(__half2*)(orow + c)     = h0;
        *(__half2*)(orow + c + 2) = h1;
        if (g126) {
            *(__half2*)(g_hq126 + (size_t)bn * Cc + c)     = h0;
            *(__half2*)(g_hq126 + (size_t)bn * Cc + c + 2) = h1;
            *(float4*)(g_x126 + (size_t)bn * Cc + c) =
                make_float4(v[j * 4 + 0], v[j * 4 + 1], v[j * 4 + 2], v[j * 4 + 3]);
        }
    }
}

// ---------------- HMMA GEMM: MT x 128 CTA tile, 4 warps (MT/2 x 64 each), 3-stage cp.async ----------------
#define GBK 64
#define GSTG 3

template <int OUTHALF, int DOGELU, int DORES, int MT, int KDIM>
__global__ void __launch_bounds__(128, MT == 64 ? 3 : 2)
gemm_mma(const __half* __restrict__ A,
         const __half* __restrict__ Bt,
         const float* __restrict__ bias,
         const float* __restrict__ res,
         void* __restrict__ Cout,
         int N) {
    constexpr int MI = MT / 32;                    // 4 or 2
    constexpr int STAGE_B = (MT + 128) * 128;      // bytes per stage
    constexpr int ACH = MT * 8;                    // A chunks per stage
    constexpr int TOTCH = ACH + 1024;              // total 16B chunks
    constexpr int JN = TOTCH / 128;
    constexpr int KT = KDIM / GBK;

    extern __shared__ unsigned char gsm[];
    uint32_t sbase = smem_to_u32(gsm);
    const int tid = threadIdx.x;
    const int wid = tid >> 5;
    const int lane = tid & 31;
    const int wm = wid & 1;
    const int wn = wid >> 1;
    const int mBase = blockIdx.y * MT;
    const int nBase = blockIdx.x * 128;

    float acc[MI][8][4];
#pragma unroll
    for (int i = 0; i < MI; i++)
#pragma unroll
        for (int j = 0; j < 8; j++)
#pragma unroll
            for (int r = 0; r < 4; r++) acc[i][j][r] = 0.f;

    auto load_stage = [&](int kt) {
        int k0 = kt * GBK;
        uint32_t ab = sbase + (uint32_t)(kt % GSTG) * STAGE_B;
        uint32_t bb = ab + (uint32_t)(MT * 128);
#pragma unroll
        for (int j = 0; j < JN; j++) {
            int id = tid + j * 128;
            if (id < ACH) {
                int row = id >> 3;
                int c16 = id & 7;
                uint32_t sw = sw_off((uint32_t)(row * 128 + c16 * 16));
                cp_async16(ab + sw, A + (size_t)(mBase + row) * KDIM + k0 + c16 * 8);
            } else {
                int idx = id - ACH;
                int row = idx >> 3;
                int c16 = idx & 7;
                uint32_t sw = sw_off((uint32_t)(row * 128 + c16 * 16));
                cp_async16(bb + sw, Bt + (size_t)(nBase + row) * KDIM + k0 + c16 * 8);
            }
        }
    };

    load_stage(0); cp_commit();
    load_stage(1); cp_commit();

#pragma unroll 2
    for (int kt = 0; kt < KT; kt++) {
        CP_WAIT_GROUP(1);
        __syncthreads();
        if (kt + 2 < KT) load_stage(kt + 2);
        cp_commit();

        uint32_t ab = sbase + (uint32_t)(kt % GSTG) * STAGE_B;
        uint32_t bb = ab + (uint32_t)(MT * 128);
#pragma unroll
        for (int ks = 0; ks < 4; ks++) {
            uint32_t a_r[MI][4];
            uint32_t b_r[8][2];
#pragma unroll
            for (int mi = 0; mi < MI; mi++) {
                int row = wm * (MT / 2) + mi * 16 + (lane & 15);
                int kc = ks * 2 + (lane >> 4);
                ldmatrix_x4(a_r[mi], ab + sw_off((uint32_t)(row * 128 + kc * 16)));
            }
#pragma unroll
            for (int bj = 0; bj < 4; bj++) {
                int nrow = wn * 64 + bj * 16 + (lane & 7) + ((lane >> 4) & 1) * 8;
                int kc = ks * 2 + ((lane >> 3) & 1);
                uint32_t r[4];
                ldmatrix_x4(r, bb + sw_off((uint32_t)(nrow * 128 + kc * 16)));
                b_r[bj * 2 + 0][0] = r[0]; b_r[bj * 2 + 0][1] = r[1];
                b_r[bj * 2 + 1][0] = r[2]; b_r[bj * 2 + 1][1] = r[3];
            }
#pragma unroll
            for (int mi = 0; mi < MI; mi++)
#pragma unroll
                for (int ni = 0; ni < 8; ni++)
                    mma_16816(acc[mi][ni], a_r[mi], b_r[ni]);
        }
    }

#pragma unroll
    for (int mi = 0; mi < MI; mi++) {
#pragma unroll
        for (int ni = 0; ni < 8; ni++) {
            int r0 = mBase + wm * (MT / 2) + mi * 16 + (lane >> 2);
            int c0 = nBase + wn * 64 + ni * 8 + 2 * (lane & 3);
            float b0 = bias[c0], b1 = bias[c0 + 1];
#pragma unroll
            for (int half_ = 0; half_ < 2; half_++) {
                int row = r0 + half_ * 8;
                float o0 = acc[mi][ni][half_ * 2 + 0] + b0;
                float o1 = acc[mi][ni][half_ * 2 + 1] + b1;
                if (DOGELU) { o0 = gelu_f(o0); o1 = gelu_f(o1); }
                if (DORES) {
                    const float* rp = res + (size_t)row * N + c0;
                    o0 += rp[0]; o1 += rp[1];
                }
                if (OUTHALF) {
                    *(__half2*)((__half*)Cout + (size_t)row * N + c0) = __floats2half2_rn(o0, o1);
                } else {
                    *(float2*)((float*)Cout + (size_t)row * N + c0) = make_float2(o0, o1);
                }
            }
        }
    }
}

#define SMEM_MT128 (GSTG * (128 + 128) * 128)   // 98304
#define SMEM_MT64  (GSTG * (64 + 128) * 128)    // 73728

// ---------------- tensor-core attention, P kept in registers (FA-style) ----------------
// smem: K 16K | Q 16K | Vt0 8K | Vt1 8K = 48KB
#define ATT_SMEM 49152

__global__ void __launch_bounds__(128) attn_tc(const __half* __restrict__ qkv,
                                               __half* __restrict__ y) {
    extern __shared__ unsigned char asm_[];
    uint32_t sb = smem_to_u32(asm_);
    uint32_t sK = sb, sQ = sb + 16384, sV0 = sb + 32768, sV1 = sb + 40960;
    int tid = threadIdx.x, wid = tid >> 5, lane = tid & 31;
    int bh = blockIdx.x, bn = bh >> 4, h = bh & 15;
    size_t baseq = (size_t)bn * Ss * QKVW + h * Dd;
    size_t basey = (size_t)bn * Ss * Cc + h * Dd;

    for (int idx = tid; idx < 1024; idx += 128) {
        int row = idx >> 3, c = idx & 7;
        uint32_t sw = sw_off((uint32_t)(row * 128 + c * 16));
        cp_async16(sQ + sw, qkv + baseq + (size_t)row * QKVW + c * 8);
        cp_async16(sK + sw, qkv + baseq + Cc + (size_t)row * QKVW + c * 8);
    }
    cp_commit();
    // V transpose: each thread handles a 4-kv x 2-d block in registers
    for (int idx = tid; idx < 1024; idx += 128) {
        int q4 = idx >> 5;             // kv quad index 0..31 -> kv0 = 4*q4
        int d2 = idx & 31;             // d-pair index
        int kv0 = q4 * 4;
        const __half* vsrc = qkv + baseq + 2 * Cc + (size_t)kv0 * QKVW + d2 * 2;
        __half2 v0 = *(const __half2*)(vsrc);
        __half2 v1 = *(const __half2*)(vsrc + QKVW);
        __half2 v2 = *(const __half2*)(vsrc + 2 * QKVW);
        __half2 v3 = *(const __half2*)(vsrc + 3 * QKVW);
        char* vbp = (char*)asm_ + ((kv0 < 64) ? 32768 : 40960);
        int kc = kv0 & 63;
        int d0 = 2 * d2;
        uint32_t sw0 = sw_off((uint32_t)(d0 * 128 + kc * 2));
        uint32_t sw1 = sw_off((uint32_t)((d0 + 1) * 128 + kc * 2));
        *(__half2*)(vbp + sw0)     = __halves2half2(__low2half(v0),  __low2half(v1));
        *(__half2*)(vbp + sw0 + 4) = __halves2half2(__low2half(v2),  __low2half(v3));
        *(__half2*)(vbp + sw1)     = __halves2half2(__high2half(v0), __high2half(v1));
        *(__half2*)(vbp + sw1 + 4) = __halves2half2(__high2half(v2), __high2half(v3));
    }
    CP_WAIT_GROUP(0);
    __syncthreads();

    int qb = wid * 32;
    float accS[2][16][4];
#pragma unroll
    for (int mi = 0; mi < 2; mi++)
#pragma unroll
        for (int ni = 0; ni < 16; ni++)
#pragma unroll
            for (int r = 0; r < 4; r++) accS[mi][ni][r] = 0.f;

#pragma unroll
    for (int ks = 0; ks < 4; ks++) {
        uint32_t a[2][4], b[16][2];
#pragma unroll
        for (int mi = 0; mi < 2; mi++) {
            int row = qb + mi * 16 + (lane & 15);
            int kc = ks * 2 + (lane >> 4);
            ldmatrix_x4(a[mi], sQ + sw_off((uint32_t)(row * 128 + kc * 16)));
        }
#pragma unroll
        for (int bj = 0; bj < 8; bj++) {
            int nrow = bj * 16 + (lane & 7) + ((lane >> 4) & 1) * 8;
            int kc = ks * 2 + ((lane >> 3) & 1);
            uint32_t r[4];
            ldmatrix_x4(r, sK + sw_off((uint32_t)(nrow * 128 + kc * 16)));
            b[bj * 2 + 0][0] = r[0]; b[bj * 2 + 0][1] = r[1];
            b[bj * 2 + 1][0] = r[2]; b[bj * 2 + 1][1] = r[3];
        }
#pragma unroll
        for (int mi = 0; mi < 2; mi++)
#pragma unroll
            for (int ni = 0; ni < 16; ni++)
                mma_16816(accS[mi][ni], a[mi], b[ni]);
    }

    // mask + exp + row sums; pack P straight into A-fragments (C-layout == A-layout)
    uint32_t pf[2][16][2];
    float inv[2][2];
#pragma unroll
    for (int mi = 0; mi < 2; mi++) {
        float s0 = 0.f, s1 = 0.f;
        int rA = qb + mi * 16 + (lane >> 2);
        int rB = rA + 8;
#pragma unroll
        for (int ni = 0; ni < 16; ni++) {
            int c0 = ni * 8 + 2 * (lane & 3);
            float p00 = (c0     <= rA) ? __expf(accS[mi][ni][0] * 0.125f) : 0.f;
            float p01 = (c0 + 1 <= rA) ? __expf(accS[mi][ni][1] * 0.125f) : 0.f;
            float p10 = (c0     <= rB) ? __expf(accS[mi][ni][2] * 0.125f) : 0.f;
            float p11 = (c0 + 1 <= rB) ? __expf(accS[mi][ni][3] * 0.125f) : 0.f;
            s0 += p00 + p01; s1 += p10 + p11;
            pf[mi][ni][0] = h2_as_u32(__floats2half2_rn(p00, p01));
            pf[mi][ni][1] = h2_as_u32(__floats2half2_rn(p10, p11));
        }
        s0 += __shfl_xor_sync(0xffffffffu, s0, 1);
        s0 += __shfl_xor_sync(0xffffffffu, s0, 2);
        s1 += __shfl_xor_sync(0xffffffffu, s1, 1);
        s1 += __shfl_xor_sync(0xffffffffu, s1, 2);
        inv[mi][0] = 1.0f / s0;
        inv[mi][1] = 1.0f / s1;
    }

    // O = P V with P in registers
    float accO[2][8][4];
#pragma unroll
    for (int mi = 0; mi < 2; mi++)
#pragma unroll
        for (int ni = 0; ni < 8; ni++)
#pragma unroll
            for (int r = 0; r < 4; r++) accO[mi][ni][r] = 0.f;

#pragma unroll
    for (int ks = 0; ks < 8; ks++) {
        uint32_t vbase = (ks < 4) ? sV0 : sV1;
        int kss = ks & 3;
        uint32_t b[8][2];
#pragma unroll
        for (int bj = 0; bj < 4; bj++) {
            int nrow = bj * 16 + (lane & 7) + ((lane >> 4) & 1) * 8;
            int kc = kss * 2 + ((lane >> 3) & 1);
            uint32_t r[4];
            ldmatrix_x4(r, vbase + sw_off((uint32_t)(nrow * 128 + kc * 16)));
            b[bj * 2 + 0][0] = r[0]; b[bj * 2 + 0][1] = r[1];
            b[bj * 2 + 1][0] = r[2]; b[bj * 2 + 1][1] = r[3];
        }
#pragma unroll
        for (int mi = 0; mi < 2; mi++) {
            uint32_t a[4] = { pf[mi][2 * ks][0], pf[mi][2 * ks][1],
                              pf[mi][2 * ks + 1][0], pf[mi][2 * ks + 1][1] };
#pragma unroll
            for (int ni = 0; ni < 8; ni++)
                mma_16816(accO[mi][ni], a, b[ni]);
        }
    }

#pragma unroll
    for (int mi = 0; mi < 2; mi++) {
#pragma unroll
        for (int ni = 0; ni < 8; ni++) {
            int rA = qb + mi * 16 + (lane >> 2);
            int c0 = ni * 8 + 2 * (lane & 3);
            *(__half2*)(y + basey + (size_t)rA * Cc + c0) =
                __floats2half2_rn(accO[mi][ni][0] * inv[mi][0], accO[mi][ni][1] * inv[mi][0]);
            *(__half2*)(y + basey + (size_t)(rA + 8) * Cc + c0) =
                __floats2half2_rn(accO[mi][ni][2] * inv[mi][1], accO[mi][ni][3] * inv[mi][1]);
        }
    }
}

// ---------------- last-layer single-query attention: block per (bn,h) ----------------
__global__ void __launch_bounds__(128) attn_last(const __half* __restrict__ qkv,
                                                 const __half* __restrict__ q126,
                                                 __half* __restrict__ y126) {
    __shared__ float qs[Dd];
    __shared__ float e[Ss];
    __shared__ float ws[4];
    int tid = threadIdx.x, wid = tid >> 5, lane = tid & 31;
    int bh = blockIdx.x, bn = bh >> 4, h = bh & 15;
    size_t base = (size_t)bn * Ss * QKVW + h * Dd;

    if (tid < 32) {
        float2 f = __half22float2(*(const __half2*)(q126 + (size_t)bn * Cc + h * Dd + tid * 2));
        qs[tid * 2] = f.x; qs[tid * 2 + 1] = f.y;
    }
    __syncthreads();

    int j = tid;
    float ej = 0.f;
    if (j <= Ss - 2) {
        const __half* kr = qkv + base + Cc + (size_t)j * QKVW;
        float s = 0.f;
#pragma unroll
        for (int i = 0; i < Dd; i++) s += qs[i] * __half2float(kr[i]);
        ej = __expf(s * 0.125f);
    }
    e[j] = ej;
    float s = ej;
#pragma unroll
    for (int o = 16; o > 0; o >>= 1) s += __shfl_xor_sync(0xffffffffu, s, o);
    if (lane == 0) ws[wid] = s;
    __syncthreads();
    float sum = ws[0] + ws[1] + ws[2] + ws[3];

    if (tid < Dd) {
        float acc = 0.f;
        for (int k = 0; k <= Ss - 2; k++)
            acc += e[k] * __half2float(qkv[base + 2 * Cc + (size_t)k * QKVW + tid]);
        y126[(size_t)bn * Cc + h * Dd + tid] = __float2half(acc / sum);
    }
}

// ---------------- final LN + head (compact x126 input) ----------------
__global__ void __launch_bounds__(256) head_kernel(const float* __restrict__ x,
                                                   const float* __restrict__ lnw,
                                                   const float* __restrict__ lnb,
                                                   const float* __restrict__ headW,
                                                   float* __restrict__ out) {
    int bn = blockIdx.x;
    const float* xr = x + (size_t)bn * Cc;
    __shared__ float hsm[Cc];
    int c0 = threadIdx.x * 4;
    float4 f = *(const float4*)(xr + c0);
    float s = f.x + f.y + f.z + f.w;
    float ss = f.x * f.x + f.y * f.y + f.z * f.z + f.w * f.w;
#pragma unroll
    for (int o = 16; o > 0; o >>= 1) {
        s  += __shfl_xor_sync(0xffffffffu, s, o);
        ss += __shfl_xor_sync(0xffffffffu, ss, o);
    }
    __shared__ float rs[8], rss[8];
    int wrp = threadIdx.x >> 5, lane = threadIdx.x & 31;
    if (lane == 0) { rs[wrp] = s; rss[wrp] = ss; }
    __syncthreads();
    s = 0.f; ss = 0.f;
#pragma unroll
    for (int qq = 0; qq < 8; qq++) { s += rs[qq]; ss += rss[qq]; }
    float mean = s * (1.0f / Cc);
    float var = ss * (1.0f / Cc) - mean * mean;
    float rstd = rsqrtf(var + 1e-5f);
    float4 wf = *(const float4*)(lnw + c0);
    float4 bf = *(const float4*)(lnb + c0);
    hsm[c0 + 0] = (f.x - mean) * rstd * wf.x + bf.x;
    hsm[c0 + 1] = (f.y - mean) * rstd * wf.y + bf.y;
    hsm[c0 + 2] = (f.z - mean) * rstd * wf.z + bf.z;
    hsm[c0 + 3] = (f.w - mean) * rstd * wf.w + bf.w;
    __syncthreads();
    if (threadIdx.x < Aa) {
        int a = threadIdx.x;
        float acc = 0.f;
        for (int c = 0; c < Cc; c++) acc += hsm[c] * headW[c * Aa + a];
        out[bn * Aa + a] = acc;
    }
}

// ---------------- host launch ----------------
extern "C" void kernel_launch(void* const* d_in, const int* in_sizes, int n_in,
                              void* d_out, int out_size) {
    const float* states     = (const float*)d_in[0];
    const float* actions    = (const float*)d_in[1];
    const int*   timesteps  = (const int*)d_in[2];
    const float* pos_emb    = (const float*)d_in[3];
    const float* gpe        = (const float*)d_in[4];
    const float* seW        = (const float*)d_in[5];
    const float* seb        = (const float*)d_in[6];
    const float* aeW        = (const float*)d_in[7];
    const float* aeb        = (const float*)d_in[8];
    const float* ln1w       = (const float*)d_in[9];
    const float* ln1b       = (const float*)d_in[10];
    const float* Wq         = (const float*)d_in[11];
    const float* bq         = (const float*)d_in[12];
    const float* Wk         = (const float*)d_in[13];
    const float* bk         = (const float*)d_in[14];
    const float* Wv         = (const float*)d_in[15];
    const float* bv         = (const float*)d_in[16];
    const float* Wp         = (const float*)d_in[17];
    const float* bp         = (const float*)d_in[18];
    const float* ln2w       = (const float*)d_in[19];
    const float* ln2b       = (const float*)d_in[20];
    const float* W1         = (const float*)d_in[21];
    const float* b1         = (const float*)d_in[22];
    const float* W2         = (const float*)d_in[23];
    const float* b2         = (const float*)d_in[24];
    const float* lnfw       = (const float*)d_in[25];
    const float* lnfb       = (const float*)d_in[26];
    const float* headW      = (const float*)d_in[27];

    void *p_x, *p_h, *p_qkv, *p_y, *p_mid;
    void *p_wqkv, *p_bqkv, *p_wp, *p_w1, *p_w2;
    void *p_hq126, *p_x126, *p_q126, *p_y126, *p_h126, *p_mid126;
    cudaGetSymbolAddress(&p_x, g_x);       cudaGetSymbolAddress(&p_h, g_h);
    cudaGetSymbolAddress(&p_qkv, g_qkv);   cudaGetSymbolAddress(&p_y, g_y);
    cudaGetSymbolAddress(&p_mid, g_mid);   cudaGetSymbolAddress(&p_wqkv, g_wqkv);
    cudaGetSymbolAddress(&p_bqkv, g_bqkv); cudaGetSymbolAddress(&p_wp, g_wp);
    cudaGetSymbolAddress(&p_w1, g_w1);     cudaGetSymbolAddress(&p_w2, g_w2);
    cudaGetSymbolAddress(&p_hq126, g_hq126); cudaGetSymbolAddress(&p_x126, g_x126);
    cudaGetSymbolAddress(&p_q126, g_q126);   cudaGetSymbolAddress(&p_y126, g_y126);
    cudaGetSymbolAddress(&p_h126, g_h126);   cudaGetSymbolAddress(&p_mid126, g_mid126);

    float*  xbuf = (float*)p_x;
    __half* hbuf = (__half*)p_h;
    __half* qkvb = (__half*)p_qkv;
    __half* ybuf = (__half*)p_y;
    __half* midb = (__half*)p_mid;

    cudaFuncSetAttribute((gemm_mma<1, 0, 0, 128, Cc>), cudaFuncAttributeMaxDynamicSharedMemorySize, SMEM_MT128);
    cudaFuncSetAttribute((gemm_mma<1, 1, 0, 128, Cc>), cudaFuncAttributeMaxDynamicSharedMemorySize, SMEM_MT128);
    cudaFuncSetAttribute((gemm_mma<0, 0, 1, 64, Cc>),  cudaFuncAttributeMaxDynamicSharedMemorySize, SMEM_MT64);
    cudaFuncSetAttribute((gemm_mma<0, 0, 1, 64, 4 * Cc>), cudaFuncAttributeMaxDynamicSharedMemorySize, SMEM_MT64);
    cudaFuncSetAttribute(attn_tc, cudaFuncAttributeMaxDynamicSharedMemorySize, ATT_SMEM);

    // ours#1: all weight transposes + gathers + embed weights + bias concat
    wconv_all<<<WCONV_BLOCKS, 256>>>(Wq, Wk, Wv, Wp, W1, W2,
                                     states, actions, seW, aeW, bq, bk, bv);
    // ours#2: both embed GEMMs (z = parity) with fused assemble
    gemm_embed<<<dim3(Cc / BNt, 8192 / BM, 2), 256>>>(seb, aeb, pos_emb, gpe, timesteps, xbuf);

    for (int l = 0; l < Ll; l++) {
        size_t wo  = (size_t)l * Cc * Cc;
        size_t wq3 = (size_t)l * 3 * Cc * Cc;
        size_t w1o = (size_t)l * Cc * 4 * Cc;
        size_t bo  = (size_t)l * Cc;
        size_t b1o = (size_t)l * 4 * Cc;

        if (l < Ll - 1) {
            ln_f2h<0><<<Rr / 8, 256>>>(xbuf, ln1w + bo, ln1b + bo, hbuf);

            // full QKV
            gemm_mma<1, 0, 0, 128, Cc><<<dim3(3 * Cc / 128, Rr / 128), 128, SMEM_MT128>>>(
                hbuf, (__half*)p_wqkv + wq3, (float*)p_bqkv + (size_t)l * 3 * Cc,
                nullptr, p_qkv, 3 * Cc);

            attn_tc<<<BNn * Hh, 128, ATT_SMEM>>>(qkvb, ybuf);

            gemm_mma<0, 0, 1, 64, Cc><<<dim3(Cc / 128, Rr / 64), 128, SMEM_MT64>>>(
                ybuf, (__half*)p_wp + wo, bp + bo, xbuf, p_x, Cc);

            ln_f2h<0><<<Rr / 8, 256>>>(xbuf, ln2w + bo, ln2b + bo, hbuf);

            gemm_mma<1, 1, 0, 128, Cc><<<dim3(4 * Cc / 128, Rr / 128), 128, SMEM_MT128>>>(
                hbuf, (__half*)p_w1 + w1o, b1 + b1o, nullptr, p_mid, 4 * Cc);
            gemm_mma<0, 0, 1, 64, 4 * Cc><<<dim3(Cc / 128, Rr / 64), 128, SMEM_MT64>>>(
                midb, (__half*)p_w2 + w1o, b2 + bo, xbuf, p_x, Cc);
        } else {
            // last layer: only row S-2 of each bn feeds the output
            // LN1 with fused row-126 gather (writes g_hq126 + g_x126)
            ln_f2h<1><<<Rr / 8, 256>>>(xbuf, ln1w + bo, ln1b + bo, hbuf);

            // k,v for all rows (columns [C, 3C) of qkv)
            gemm_mma<1, 0, 0, 128, Cc><<<dim3(2 * Cc / 128, Rr / 128), 128, SMEM_MT128>>>(
                hbuf, (__half*)p_wqkv + wq3 + (size_t)Cc * Cc,
                (float*)p_bqkv + (size_t)l * 3 * Cc + Cc,
                nullptr, (void*)((__half*)p_qkv + Cc), 3 * Cc);
            // q only for the 128 gathered rows
            gemm_mma<1, 0, 0, 128, Cc><<<dim3(Cc / 128, 1), 128, SMEM_MT128>>>(
                (__half*)p_hq126, (__half*)p_wqkv + wq3,
                (float*)p_bqkv + (size_t)l * 3 * Cc,
                nullptr, p_q126, Cc);

            attn_last<<<BNn * Hh, 128>>>(qkvb, (__half*)p_q126, (__half*)p_y126);

            // proj + residual (compact, in-place on x126)
            gemm_mma<0, 0, 1, 64, Cc><<<dim3(Cc / 128, BNn / 64), 128, SMEM_MT64>>>(
                (__half*)p_y126, (__half*)p_wp + wo, bp + bo,
                (float*)p_x126, p_x126, Cc);

            ln_f2h<0><<<BNn / 8, 256>>>((float*)p_x126, ln2w + bo, ln2b + bo, (__half*)p_h126);

            gemm_mma<1, 1, 0, 128, Cc><<<dim3(4 * Cc / 128, 1), 128, SMEM_MT128>>>(
                (__half*)p_h126, (__half*)p_w1 + w1o, b1 + b1o,
                nullptr, p_mid126, 4 * Cc);
            gemm_mma<0, 0, 1, 64, 4 * Cc><<<dim3(Cc / 128, BNn / 64), 128, SMEM_MT64>>>(
                (__half*)p_mid126, (__half*)p_w2 + w1o, b2 + bo,
                (float*)p_x126, p_x126, Cc);
        }
    }

    head_kernel<<<BNn, 256>>>((float*)p_x126, lnfw, lnfb, headW, (float*)d_out);
}